// round 1
// baseline (speedup 1.0000x reference)
#include <cuda_runtime.h>

// ---------------- problem constants ----------------
#define BB  4
#define SS  2048
#define DD  512
#define HH  8
#define DHH 64
#define FF  2048
#define NLL 4
#define MM  (BB*SS)      // 8192 rows
#define CC  64           // attention chunk length
#define NCC (SS/CC)      // 32 chunks
#define BHH (BB*HH)      // 32 (b,h) pairs

// ---------------- scratch (device globals; no allocs allowed) ----------------
__device__ float g_h[MM*DD];          // residual stream
__device__ float g_q[MM*DD];          // q proj / generic tmp
__device__ float g_k[MM*DD];
__device__ float g_v[MM*DD];
__device__ float g_a[MM*DD];          // attention output
__device__ float g_t[MM*FF];          // FFN hidden
__device__ float g_S[(size_t)BHH*NCC*DHH*DHH]; // chunk states (then exclusive prefix)
__device__ float g_ks[BHH*NCC*DHH];   // chunk key-sums (then exclusive prefix)
__device__ int   g_len[BB];

__device__ __forceinline__ float phi_f(float u) {
    // elu(u)+1 : u>0 ? u+1 : exp(u)
    return u > 0.f ? u + 1.f : __expf(u);
}

// ---------------- lengths: count nonzero tokens per batch row ----------------
__global__ void len_kernel(const int* __restrict__ x) {
    __shared__ int red[256];
    int b = blockIdx.x, tid = threadIdx.x;
    int cnt = 0;
    for (int s = tid; s < SS; s += 256) cnt += (x[b*SS + s] != 0);
    red[tid] = cnt; __syncthreads();
    for (int off = 128; off; off >>= 1) {
        if (tid < off) red[tid] += red[tid + off];
        __syncthreads();
    }
    if (tid == 0) g_len[b] = red[0];
}

// ---------------- embedding + positional ----------------
__global__ void embed_kernel(const int* __restrict__ x,
                             const float* __restrict__ emb,
                             const float* __restrict__ pe) {
    int idx = blockIdx.x * 256 + threadIdx.x;        // over MM * DD/4
    if (idx >= MM * (DD/4)) return;
    int i  = idx >> 7;          // DD/4 = 128
    int d4 = idx & 127;
    int s  = i & (SS - 1);
    int tok = x[i];
    float4 e = ((const float4*)emb)[(size_t)tok * (DD/4) + d4];
    float4 p = ((const float4*)pe)[(size_t)s * (DD/4) + d4];
    float4 o;
    o.x = e.x + p.x; o.y = e.y + p.y; o.z = e.z + p.z; o.w = e.w + p.w;
    ((float4*)g_h)[idx] = o;
}

// ---------------- generic SGEMM: C = A[M,K] @ W[K,N] + bias, optional ReLU ----
// 128x128 tile, BK=8, 256 threads, 8x8 micro-tile, smem double buffered.
// All dims guaranteed multiples of tile sizes here.
struct GemmArgs {
    const float* A;
    const float* W[3];
    const float* bias[3];
    float*       out[3];
    int N, K;
};

template<int RELU>
__global__ void __launch_bounds__(256) gemm_kernel(GemmArgs p) {
    __shared__ float As[2][8][132];
    __shared__ float Bs[2][8][132];
    const int z = blockIdx.z;
    const float* A    = p.A;
    const float* Bw   = p.W[z];
    const float* bias = p.bias[z];
    float*       Cc   = p.out[z];
    const int N = p.N, K = p.K;
    const int tid  = threadIdx.x;
    const int arow = tid >> 1,  acol = (tid & 1) << 2;
    const int brow = tid >> 5,  bcol = (tid & 31) << 2;
    const float* Ap = A  + (size_t)(blockIdx.y * 128 + arow) * K + acol;
    const float* Bp = Bw + (size_t)brow * N + blockIdx.x * 128 + bcol;

    float4 av = *(const float4*)Ap;
    float4 bv = *(const float4*)Bp;
    As[0][acol+0][arow] = av.x;
    As[0][acol+1][arow] = av.y;
    As[0][acol+2][arow] = av.z;
    As[0][acol+3][arow] = av.w;
    *(float4*)&Bs[0][brow][bcol] = bv;
    __syncthreads();

    const int tcol = tid & 15, trow = tid >> 4;
    float acc[8][8];
    #pragma unroll
    for (int i = 0; i < 8; i++)
        #pragma unroll
        for (int j = 0; j < 8; j++) acc[i][j] = 0.f;

    const int nt = K >> 3;
    int buf = 0;
    for (int t = 0; t < nt; t++) {
        if (t + 1 < nt) {
            av = *(const float4*)(Ap + (t + 1) * 8);
            bv = *(const float4*)(Bp + (size_t)(t + 1) * 8 * N);
        }
        #pragma unroll
        for (int k = 0; k < 8; k++) {
            float4 a0 = *(const float4*)&As[buf][k][trow*4];
            float4 a1 = *(const float4*)&As[buf][k][trow*4 + 64];
            float4 b0 = *(const float4*)&Bs[buf][k][tcol*4];
            float4 b1 = *(const float4*)&Bs[buf][k][tcol*4 + 64];
            float ar[8] = {a0.x,a0.y,a0.z,a0.w,a1.x,a1.y,a1.z,a1.w};
            float br[8] = {b0.x,b0.y,b0.z,b0.w,b1.x,b1.y,b1.z,b1.w};
            #pragma unroll
            for (int i = 0; i < 8; i++)
                #pragma unroll
                for (int j = 0; j < 8; j++)
                    acc[i][j] = fmaf(ar[i], br[j], acc[i][j]);
        }
        if (t + 1 < nt) {
            buf ^= 1;
            As[buf][acol+0][arow] = av.x;
            As[buf][acol+1][arow] = av.y;
            As[buf][acol+2][arow] = av.z;
            As[buf][acol+3][arow] = av.w;
            *(float4*)&Bs[buf][brow][bcol] = bv;
            __syncthreads();
        }
    }

    const int n0 = blockIdx.x * 128 + tcol * 4;
    float4 bz0 = *(const float4*)&bias[n0];
    float4 bz1 = *(const float4*)&bias[n0 + 64];
    float bb[8] = {bz0.x,bz0.y,bz0.z,bz0.w,bz1.x,bz1.y,bz1.z,bz1.w};
    #pragma unroll
    for (int i = 0; i < 8; i++) {
        int m = blockIdx.y * 128 + trow * 4 + (i & 3) + ((i & 4) << 4);
        float4 o0, o1;
        o0.x = acc[i][0] + bb[0]; o0.y = acc[i][1] + bb[1];
        o0.z = acc[i][2] + bb[2]; o0.w = acc[i][3] + bb[3];
        o1.x = acc[i][4] + bb[4]; o1.y = acc[i][5] + bb[5];
        o1.z = acc[i][6] + bb[6]; o1.w = acc[i][7] + bb[7];
        if (RELU) {
            o0.x = fmaxf(o0.x, 0.f); o0.y = fmaxf(o0.y, 0.f);
            o0.z = fmaxf(o0.z, 0.f); o0.w = fmaxf(o0.w, 0.f);
            o1.x = fmaxf(o1.x, 0.f); o1.y = fmaxf(o1.y, 0.f);
            o1.z = fmaxf(o1.z, 0.f); o1.w = fmaxf(o1.w, 0.f);
        }
        *(float4*)&Cc[(size_t)m * N + n0]      = o0;
        *(float4*)&Cc[(size_t)m * N + n0 + 64] = o1;
    }
}

// ---------------- attention pass 1: per-chunk  S_c = phiK^T V,  ks_c = sum phiK
__global__ void __launch_bounds__(256) att_sums_kernel() {
    __shared__ float sK[CC][68];
    __shared__ float sV[CC][68];
    int c = blockIdx.x, bh = blockIdx.y;
    int b = bh >> 3, h = bh & 7;
    int tid = threadIdx.x;
    int len = g_len[b];
    for (int idx = tid; idx < CC * DHH; idx += 256) {
        int j = idx >> 6, d = idx & 63;
        int srow = c * CC + j;
        size_t g = ((size_t)(b * SS + srow)) * DD + h * DHH + d;
        float kv = g_k[g];
        sK[j][d] = (srow < len) ? phi_f(kv) : 0.f;
        sV[j][d] = g_v[g];
    }
    __syncthreads();
    int ti = tid & 15, tj = tid >> 4;
    float acc[4][4];
    #pragma unroll
    for (int r = 0; r < 4; r++)
        #pragma unroll
        for (int e = 0; e < 4; e++) acc[r][e] = 0.f;
    #pragma unroll 8
    for (int j = 0; j < CC; j++) {
        float4 kf = *(const float4*)&sK[j][ti*4];
        float4 vf = *(const float4*)&sV[j][tj*4];
        float ka[4] = {kf.x,kf.y,kf.z,kf.w};
        float va[4] = {vf.x,vf.y,vf.z,vf.w};
        #pragma unroll
        for (int r = 0; r < 4; r++)
            #pragma unroll
            for (int e = 0; e < 4; e++)
                acc[r][e] = fmaf(ka[r], va[e], acc[r][e]);
    }
    float* So = &g_S[((size_t)(bh * NCC + c)) * (DHH * DHH)];
    #pragma unroll
    for (int r = 0; r < 4; r++) {
        int d = ti * 4 + r;
        float4 o; o.x = acc[r][0]; o.y = acc[r][1]; o.z = acc[r][2]; o.w = acc[r][3];
        *(float4*)&So[d * DHH + tj * 4] = o;
    }
    if (tid < DHH) {
        float s = 0.f;
        #pragma unroll 8
        for (int j = 0; j < CC; j++) s += sK[j][tid];
        g_ks[(bh * NCC + c) * DHH + tid] = s;
    }
}

// ---------------- attention pass 2: exclusive prefix over chunks (in place) ---
__global__ void __launch_bounds__(256) att_scan_kernel() {
    int bh = blockIdx.x, tid = threadIdx.x;
    float run[16];
    #pragma unroll
    for (int r = 0; r < 16; r++) run[r] = 0.f;
    for (int c = 0; c < NCC; c++) {
        float* p = &g_S[((size_t)(bh * NCC + c)) * (DHH*DHH) + tid * 16];
        #pragma unroll
        for (int r4 = 0; r4 < 4; r4++) {
            float4 tv = ((const float4*)p)[r4];
            float4 rv;
            rv.x = run[r4*4+0]; rv.y = run[r4*4+1];
            rv.z = run[r4*4+2]; rv.w = run[r4*4+3];
            ((float4*)p)[r4] = rv;
            run[r4*4+0] += tv.x; run[r4*4+1] += tv.y;
            run[r4*4+2] += tv.z; run[r4*4+3] += tv.w;
        }
    }
    if (tid < DHH) {
        float rk = 0.f;
        for (int c = 0; c < NCC; c++) {
            float* kp = &g_ks[(bh * NCC + c) * DHH + tid];
            float t = *kp; *kp = rk; rk += t;
        }
    }
}

// ---------------- attention pass 3: per-chunk output ---------------------------
// out_i = [ sum_{j<=i} (phiQ_i . phiK_j) V_j + phiQ_i @ S_prev ] / (phiQ_i.(k_prev + cum phiK) + eps)
#define SM3_FLOATS (3*CC*68 + DHH)
#define SM3_BYTES  (SM3_FLOATS * 4)
__global__ void __launch_bounds__(256) att_out_kernel() {
    extern __shared__ float sm[];
    float* sQ  = sm;               // [64][68] d-major: sQ[d*68 + i]
    float* sKV = sm + CC*68;       // phase A: phiK d-major ; phase 3: V j-major
    float* sSA = sm + 2*CC*68;     // phase A: S_prev d-major ; phase 3: masked A^T j-major
    float* skp = sm + 3*CC*68;     // [64] k_prev, reused as 1/Z

    int c = blockIdx.x, bh = blockIdx.y;
    int b = bh >> 3, h = bh & 7;
    int tid = threadIdx.x;
    int len = g_len[b];

    for (int idx = tid; idx < CC * DHH; idx += 256) {
        int r = idx >> 6, d = idx & 63;
        int srow = c * CC + r;
        size_t g = ((size_t)(b * SS + srow)) * DD + h * DHH + d;
        sQ[d*68 + r]  = phi_f(g_q[g]);
        float kv = g_k[g];
        sKV[d*68 + r] = (srow < len) ? phi_f(kv) : 0.f;
        sSA[r*68 + d] = g_S[((size_t)(bh * NCC + c)) * (DHH*DHH) + idx]; // [d][e]
    }
    if (tid < DHH) skp[tid] = g_ks[(bh * NCC + c) * DHH + tid];
    __syncthreads();

    int ti = tid & 15, tj = tid >> 4;

    // z init : phiQ_i . k_prev   (threads 0..63, row i = tid)
    float zi = 0.f;
    if (tid < DHH) {
        #pragma unroll 8
        for (int d = 0; d < DHH; d++) zi += sQ[d*68 + tid] * skp[d];
    }

    // fused: out init (Q @ S_prev) and A = Q K^T
    float oacc[4][4], aacc[4][4];
    #pragma unroll
    for (int r = 0; r < 4; r++)
        #pragma unroll
        for (int e = 0; e < 4; e++) { oacc[r][e] = 0.f; aacc[r][e] = 0.f; }
    #pragma unroll 4
    for (int d = 0; d < DHH; d++) {
        float4 aq = *(const float4*)&sQ [d*68 + ti*4];
        float4 bs = *(const float4*)&sSA[d*68 + tj*4];
        float4 bk = *(const float4*)&sKV[d*68 + tj*4];
        float qa[4] = {aq.x,aq.y,aq.z,aq.w};
        float sa[4] = {bs.x,bs.y,bs.z,bs.w};
        float ka[4] = {bk.x,bk.y,bk.z,bk.w};
        #pragma unroll
        for (int r = 0; r < 4; r++)
            #pragma unroll
            for (int e = 0; e < 4; e++) {
                oacc[r][e] = fmaf(qa[r], sa[e], oacc[r][e]);
                aacc[r][e] = fmaf(qa[r], ka[e], aacc[r][e]);
            }
    }
    __syncthreads();

    // store masked A transposed over sSA ; reload V over sKV (j-major)
    #pragma unroll
    for (int r = 0; r < 4; r++)
        #pragma unroll
        for (int e = 0; e < 4; e++) {
            int i = ti * 4 + r, j = tj * 4 + e;
            sSA[j*68 + i] = (j <= i) ? aacc[r][e] : 0.f;
        }
    for (int idx = tid; idx < CC * DHH; idx += 256) {
        int r = idx >> 6, e = idx & 63;
        sKV[r*68 + e] = g_v[((size_t)(b * SS + c * CC + r)) * DD + h * DHH + e];
    }
    __syncthreads();

    // finalize Z (row sums of masked A), store reciprocal in skp
    if (tid < DHH) {
        float z = zi;
        #pragma unroll 8
        for (int j = 0; j < CC; j++) z += sSA[j*68 + tid];
        skp[tid] = 1.f / (z + 1e-6f);
    }

    // out += A @ V
    #pragma unroll 4
    for (int j = 0; j < CC; j++) {
        float4 aj = *(const float4*)&sSA[j*68 + ti*4];
        float4 ve = *(const float4*)&sKV[j*68 + tj*4];
        float aa[4] = {aj.x,aj.y,aj.z,aj.w};
        float va[4] = {ve.x,ve.y,ve.z,ve.w};
        #pragma unroll
        for (int r = 0; r < 4; r++)
            #pragma unroll
            for (int e = 0; e < 4; e++)
                oacc[r][e] = fmaf(aa[r], va[e], oacc[r][e]);
    }
    __syncthreads();

    #pragma unroll
    for (int r = 0; r < 4; r++) {
        int i = ti * 4 + r;
        float zr = skp[i];
        float4 o;
        o.x = oacc[r][0] * zr; o.y = oacc[r][1] * zr;
        o.z = oacc[r][2] * zr; o.w = oacc[r][3] * zr;
        *(float4*)&g_a[((size_t)(b * SS + c * CC + i)) * DD + h * DHH + tj * 4] = o;
    }
}

// ---------------- LayerNorm (optionally + residual add) -----------------------
__global__ void ln_kernel(const float* __restrict__ x, const float* __restrict__ add,
                          const float* __restrict__ gamma, const float* __restrict__ beta,
                          float* __restrict__ out) {
    __shared__ float rs[4], rq[4];
    int row = blockIdx.x, tid = threadIdx.x;     // 128 threads, 4 elems each
    float4 v = ((const float4*)(x + (size_t)row * DD))[tid];
    if (add) {
        float4 a = ((const float4*)(add + (size_t)row * DD))[tid];
        v.x += a.x; v.y += a.y; v.z += a.z; v.w += a.w;
    }
    float s = v.x + v.y + v.z + v.w;
    float q = v.x*v.x + v.y*v.y + v.z*v.z + v.w*v.w;
    #pragma unroll
    for (int off = 16; off; off >>= 1) {
        s += __shfl_xor_sync(0xffffffffu, s, off);
        q += __shfl_xor_sync(0xffffffffu, q, off);
    }
    if ((tid & 31) == 0) { rs[tid >> 5] = s; rq[tid >> 5] = q; }
    __syncthreads();
    s = rs[0] + rs[1] + rs[2] + rs[3];
    q = rq[0] + rq[1] + rq[2] + rq[3];
    float mu   = s * (1.f / DD);
    float var  = q * (1.f / DD) - mu * mu;
    float rstd = rsqrtf(var + 1e-5f);
    float4 g  = ((const float4*)gamma)[tid];
    float4 bt = ((const float4*)beta)[tid];
    float4 o;
    o.x = (v.x - mu) * rstd * g.x + bt.x;
    o.y = (v.y - mu) * rstd * g.y + bt.y;
    o.z = (v.z - mu) * rstd * g.z + bt.z;
    o.w = (v.w - mu) * rstd * g.w + bt.w;
    ((float4*)(out + (size_t)row * DD))[tid] = o;
}

// ---------------- launch --------------------------------------------------------
extern "C" void kernel_launch(void* const* d_in, const int* in_sizes, int n_in,
                              void* d_out, int out_size) {
    (void)in_sizes; (void)n_in; (void)out_size;
    const int*   x   = (const int*)  d_in[0];
    const float* emb = (const float*)d_in[1];
    const float* pe  = (const float*)d_in[2];
    const float* Wq  = (const float*)d_in[3];
    const float* bq  = (const float*)d_in[4];
    const float* Wk  = (const float*)d_in[5];
    const float* bk  = (const float*)d_in[6];
    const float* Wv  = (const float*)d_in[7];
    const float* bv  = (const float*)d_in[8];
    const float* Wo  = (const float*)d_in[9];
    const float* bo  = (const float*)d_in[10];
    const float* W1  = (const float*)d_in[11];
    const float* b1  = (const float*)d_in[12];
    const float* W2  = (const float*)d_in[13];
    const float* b2  = (const float*)d_in[14];
    const float* g1  = (const float*)d_in[15];
    const float* be1 = (const float*)d_in[16];
    const float* g2  = (const float*)d_in[17];
    const float* be2 = (const float*)d_in[18];
    const float* gf  = (const float*)d_in[19];
    const float* bf  = (const float*)d_in[20];

    float *h, *q, *k, *v, *a, *t;
    cudaGetSymbolAddress((void**)&h, g_h);
    cudaGetSymbolAddress((void**)&q, g_q);
    cudaGetSymbolAddress((void**)&k, g_k);
    cudaGetSymbolAddress((void**)&v, g_v);
    cudaGetSymbolAddress((void**)&a, g_a);
    cudaGetSymbolAddress((void**)&t, g_t);

    cudaFuncSetAttribute(att_out_kernel,
                         cudaFuncAttributeMaxDynamicSharedMemorySize, SM3_BYTES);

    len_kernel<<<BB, 256>>>(x);
    embed_kernel<<<(MM * (DD/4) + 255) / 256, 256>>>(x, emb, pe);

    for (int l = 0; l < NLL; l++) {
        size_t wo  = (size_t)l * DD * DD;
        size_t boff = (size_t)l * DD;

        GemmArgs ga = {};
        ga.A = h; ga.N = DD; ga.K = DD;
        ga.W[0] = Wq + wo;  ga.W[1] = Wk + wo;  ga.W[2] = Wv + wo;
        ga.bias[0] = bq + boff; ga.bias[1] = bk + boff; ga.bias[2] = bv + boff;
        ga.out[0] = q; ga.out[1] = k; ga.out[2] = v;
        gemm_kernel<0><<<dim3(DD/128, MM/128, 3), 256>>>(ga);

        att_sums_kernel<<<dim3(NCC, BHH), 256>>>();
        att_scan_kernel<<<BHH, 256>>>();
        att_out_kernel<<<dim3(NCC, BHH), 256, SM3_BYTES>>>();

        GemmArgs go = {};
        go.A = a; go.N = DD; go.K = DD;
        go.W[0] = Wo + wo; go.bias[0] = bo + boff; go.out[0] = q;
        gemm_kernel<0><<<dim3(DD/128, MM/128, 1), 256>>>(go);

        ln_kernel<<<MM, 128>>>(h, q, g1 + boff, be1 + boff, h);

        GemmArgs gm1 = {};
        gm1.A = h; gm1.N = FF; gm1.K = DD;
        gm1.W[0] = W1 + (size_t)l * DD * FF; gm1.bias[0] = b1 + (size_t)l * FF; gm1.out[0] = t;
        gemm_kernel<1><<<dim3(FF/128, MM/128, 1), 256>>>(gm1);

        GemmArgs gm2 = {};
        gm2.A = t; gm2.N = DD; gm2.K = FF;
        gm2.W[0] = W2 + (size_t)l * FF * DD; gm2.bias[0] = b2 + boff; gm2.out[0] = q;
        gemm_kernel<0><<<dim3(DD/128, MM/128, 1), 256>>>(gm2);

        ln_kernel<<<MM, 128>>>(h, q, g2 + boff, be2 + boff, h);
    }

    ln_kernel<<<MM, 128>>>(h, nullptr, gf, bf, (float*)d_out);
}

// round 3
// speedup vs baseline: 1.6415x; 1.6415x over previous
#include <cuda_runtime.h>
#include <cuda_bf16.h>
#include <cstdint>

// ---------------- problem constants ----------------
#define BB  4
#define SS  2048
#define DD  512
#define HH  8
#define DHH 64
#define FF  2048
#define NLL 4
#define MM  (BB*SS)      // 8192 rows
#define CC  64           // attention chunk length
#define NCC (SS/CC)      // 32 chunks
#define BHH (BB*HH)      // 32 (b,h) pairs

__device__ __forceinline__ uint32_t smem_u32(const void* p) {
    uint32_t a;
    asm("{ .reg .u64 t; cvta.to.shared.u64 t, %1; cvt.u32.u64 %0, t; }" : "=r"(a) : "l"(p));
    return a;
}

// ---------------- scratch (device globals; no allocs allowed) ----------------
__device__ float g_h[MM*DD];          // residual stream fp32
__device__ float g_q[MM*DD];          // q proj fp32 / generic tmp
__device__ float g_k[MM*DD];
__device__ float g_v[MM*DD];
__device__ float g_S[(size_t)BHH*NCC*DHH*DHH];
__device__ float g_ks[BHH*NCC*DHH];
__device__ int   g_len[BB];

// bf16 hi/lo activation pairs
__device__ __align__(16) __nv_bfloat16 g_hb_h[MM*DD], g_hb_l[MM*DD];
__device__ __align__(16) __nv_bfloat16 g_ab_h[MM*DD], g_ab_l[MM*DD];
__device__ __align__(16) __nv_bfloat16 g_tb_h[(size_t)MM*FF], g_tb_l[(size_t)MM*FF];

// transposed + split weights: layout [N][K]
__device__ __align__(16) __nv_bfloat16 g_wq_h[NLL*DD*DD], g_wq_l[NLL*DD*DD];
__device__ __align__(16) __nv_bfloat16 g_wk_h[NLL*DD*DD], g_wk_l[NLL*DD*DD];
__device__ __align__(16) __nv_bfloat16 g_wv_h[NLL*DD*DD], g_wv_l[NLL*DD*DD];
__device__ __align__(16) __nv_bfloat16 g_wo_h[NLL*DD*DD], g_wo_l[NLL*DD*DD];
__device__ __align__(16) __nv_bfloat16 g_w1_h[NLL*FF*DD], g_w1_l[NLL*FF*DD];
__device__ __align__(16) __nv_bfloat16 g_w2_h[NLL*DD*FF], g_w2_l[NLL*DD*FF];

__device__ __forceinline__ float phi_f(float u) { return u > 0.f ? u + 1.f : __expf(u); }

__device__ __forceinline__ void split_bf(float x, __nv_bfloat16& h, __nv_bfloat16& l) {
    h = __float2bfloat16(x);
    l = __float2bfloat16(x - __bfloat162float(h));
}

// ---------------- lengths ----------------
__global__ void len_kernel(const int* __restrict__ x) {
    __shared__ int red[256];
    int b = blockIdx.x, tid = threadIdx.x;
    int cnt = 0;
    for (int s = tid; s < SS; s += 256) cnt += (x[b*SS + s] != 0);
    red[tid] = cnt; __syncthreads();
    for (int off = 128; off; off >>= 1) {
        if (tid < off) red[tid] += red[tid + off];
        __syncthreads();
    }
    if (tid == 0) g_len[b] = red[0];
}

// ---------------- embedding + positional (+ bf16 split) ----------------
__global__ void embed_kernel(const int* __restrict__ x,
                             const float* __restrict__ emb,
                             const float* __restrict__ pe) {
    int idx = blockIdx.x * 256 + threadIdx.x;
    if (idx >= MM * (DD/4)) return;
    int i  = idx >> 7;
    int d4 = idx & 127;
    int s  = i & (SS - 1);
    int tok = x[i];
    float4 e = ((const float4*)emb)[(size_t)tok * (DD/4) + d4];
    float4 p = ((const float4*)pe)[(size_t)s * (DD/4) + d4];
    float4 o;
    o.x = e.x + p.x; o.y = e.y + p.y; o.z = e.z + p.z; o.w = e.w + p.w;
    ((float4*)g_h)[idx] = o;
    size_t e0 = (size_t)idx * 4;
    float vv[4] = {o.x, o.y, o.z, o.w};
    #pragma unroll
    for (int j = 0; j < 4; j++) split_bf(vv[j], g_hb_h[e0+j], g_hb_l[e0+j]);
}

// ---------------- weight transpose + split ----------------
__global__ void wtc_kernel(const float* __restrict__ W, __nv_bfloat16* __restrict__ oh,
                           __nv_bfloat16* __restrict__ ol, int K, int N) {
    __shared__ float t[32][33];
    int n0 = blockIdx.x * 32, k0 = blockIdx.y * 32;
    int tx = threadIdx.x, ty = threadIdx.y;   // 32x8
    #pragma unroll
    for (int i = 0; i < 32; i += 8)
        t[ty + i][tx] = W[(size_t)(k0 + ty + i) * N + n0 + tx];
    __syncthreads();
    #pragma unroll
    for (int i = 0; i < 32; i += 8) {
        float v = t[tx][ty + i];
        size_t o = (size_t)(n0 + ty + i) * K + k0 + tx;
        split_bf(v, oh[o], ol[o]);
    }
}

// ---------------- split-bf16 GEMM via warp mma.sync ----------------
// C[M,N] = A[M,K] * B[N,K]^T + bias ; A,B as bf16 (hi,lo) pairs, K-major rows.
// Block 128x128, BK=32, 256 thr, warp tile 64x32, cp.async 2-stage.
struct GTArgs {
    const __nv_bfloat16 *Ah, *Al;
    const __nv_bfloat16 *Bh[3], *Bl[3];
    const float* bias[3];
    float* outf[3];
    __nv_bfloat16 *outh[3], *outl[3];
    int N, K;
};

#define AST 40                         // smem row stride (bf16): 80B, ldmatrix conflict-free
#define TILE_ELEMS (128*AST)           // 5120
#define STAGE_ELEMS (4*TILE_ELEMS)     // Ah,Al,Bh,Bl
#define GM_SMEM_BYTES (2*STAGE_ELEMS*2)   // 81920

#define MMA_BF16(d, a, b) \
    asm volatile("mma.sync.aligned.m16n8k16.row.col.f32.bf16.bf16.f32 " \
        "{%0,%1,%2,%3}, {%4,%5,%6,%7}, {%8,%9}, {%0,%1,%2,%3};" \
        : "+f"((d)[0]), "+f"((d)[1]), "+f"((d)[2]), "+f"((d)[3]) \
        : "r"((a)[0]), "r"((a)[1]), "r"((a)[2]), "r"((a)[3]), "r"((b)[0]), "r"((b)[1]))

#define LDMX4(r, addr) \
    asm volatile("ldmatrix.sync.aligned.m8n8.x4.shared.b16 {%0,%1,%2,%3}, [%4];" \
        : "=r"((r)[0]), "=r"((r)[1]), "=r"((r)[2]), "=r"((r)[3]) : "r"(addr))

template<int RELU, int OUTBF>
__global__ void __launch_bounds__(256) gemm_mma(GTArgs p) {
    extern __shared__ __nv_bfloat16 sm[];
    const int z = blockIdx.z;
    const __nv_bfloat16* gA[2] = { p.Ah, p.Al };
    const __nv_bfloat16* gB[2] = { p.Bh[z], p.Bl[z] };
    const int N = p.N, K = p.K;
    const int tid = threadIdx.x;
    const int m0 = blockIdx.y * 128, n0 = blockIdx.x * 128;

    // ---- async loader: one stage = 2048 x 16B chunks ----
    auto load_stage = [&](int st, int k0) {
        #pragma unroll
        for (int i = 0; i < 8; i++) {
            int c  = i * 256 + tid;          // 0..2047
            int op = c >> 9;                 // 0=Ah 1=Al 2=Bh 3=Bl
            int cc = c & 511;
            int row = cc >> 2, ch = cc & 3;
            const __nv_bfloat16* src = (op < 2 ? gA[op] : gB[op - 2])
                + (size_t)((op < 2 ? m0 : n0) + row) * K + k0 + ch * 8;
            uint32_t da = smem_u32(sm + st * STAGE_ELEMS + op * TILE_ELEMS + row * AST + ch * 8);
            asm volatile("cp.async.cg.shared.global [%0], [%1], 16;" :: "r"(da), "l"(src));
        }
        asm volatile("cp.async.commit_group;" ::: "memory");
    };

    const int wid = tid >> 5, lane = tid & 31;
    const int wm = (wid & 1) * 64;
    const int wn = (wid >> 1) * 32;

    float acc[4][4][4];
    #pragma unroll
    for (int a = 0; a < 4; a++)
        #pragma unroll
        for (int b = 0; b < 4; b++)
            #pragma unroll
            for (int c = 0; c < 4; c++) acc[a][b][c] = 0.f;

    const int nt = K >> 5;
    load_stage(0, 0);
    load_stage(1, 32);

    for (int t = 0; t < nt; t++) {
        asm volatile("cp.async.wait_group 1;" ::: "memory");
        __syncthreads();
        const __nv_bfloat16* base = sm + (t & 1) * STAGE_ELEMS;
        #pragma unroll
        for (int kh = 0; kh < 2; kh++) {
            const int k0 = kh * 16;
            uint32_t afr[2][4][4];
            #pragma unroll
            for (int sp = 0; sp < 2; sp++) {
                const __nv_bfloat16* At = base + sp * TILE_ELEMS;
                #pragma unroll
                for (int mt = 0; mt < 4; mt++) {
                    int row = wm + mt * 16 + (lane & 15);
                    int col = k0 + ((lane >> 4) << 3);
                    uint32_t ad = smem_u32(At + row * AST + col);
                    LDMX4(afr[sp][mt], ad);
                }
            }
            uint32_t bfr[2][2][4];
            #pragma unroll
            for (int sp = 0; sp < 2; sp++) {
                const __nv_bfloat16* Bt = base + (2 + sp) * TILE_ELEMS;
                #pragma unroll
                for (int ng = 0; ng < 2; ng++) {
                    int n  = wn + ng * 16 + (lane & 7) + ((lane >> 4) << 3);
                    int kc = k0 + (((lane >> 3) & 1) << 3);
                    uint32_t ad = smem_u32(Bt + n * AST + kc);
                    LDMX4(bfr[sp][ng], ad);
                }
            }
            #pragma unroll
            for (int mt = 0; mt < 4; mt++)
                #pragma unroll
                for (int nn = 0; nn < 4; nn++) {
                    int ng = nn >> 1, hb = (nn & 1) * 2;
                    uint32_t b0h[2] = { bfr[0][ng][hb], bfr[0][ng][hb+1] };
                    uint32_t b0l[2] = { bfr[1][ng][hb], bfr[1][ng][hb+1] };
                    MMA_BF16(acc[mt][nn], afr[0][mt], b0h);  // Ah*Bh
                    MMA_BF16(acc[mt][nn], afr[0][mt], b0l);  // Ah*Bl
                    MMA_BF16(acc[mt][nn], afr[1][mt], b0h);  // Al*Bh
                }
        }
        __syncthreads();
        if (t + 2 < nt) load_stage(t & 1, (t + 2) * 32);
        else asm volatile("cp.async.commit_group;" ::: "memory");
    }

    // ---- epilogue ----
    const float* bias = p.bias[z];
    #pragma unroll
    for (int nn = 0; nn < 4; nn++) {
        int cn = n0 + wn + nn * 8 + (lane & 3) * 2;
        float b0v = bias[cn], b1v = bias[cn + 1];
        #pragma unroll
        for (int mt = 0; mt < 4; mt++) {
            int r0 = m0 + wm + mt * 16 + (lane >> 2);
            #pragma unroll
            for (int half = 0; half < 2; half++) {
                int r = r0 + half * 8;
                float v0 = acc[mt][nn][half*2 + 0] + b0v;
                float v1 = acc[mt][nn][half*2 + 1] + b1v;
                if (RELU) { v0 = fmaxf(v0, 0.f); v1 = fmaxf(v1, 0.f); }
                if (OUTBF) {
                    __nv_bfloat16 h0, l0, h1, l1;
                    split_bf(v0, h0, l0);
                    split_bf(v1, h1, l1);
                    __nv_bfloat162 hp; hp.x = h0; hp.y = h1;
                    __nv_bfloat162 lp; lp.x = l0; lp.y = l1;
                    *(__nv_bfloat162*)(p.outh[z] + (size_t)r * N + cn) = hp;
                    *(__nv_bfloat162*)(p.outl[z] + (size_t)r * N + cn) = lp;
                } else {
                    float2 o; o.x = v0; o.y = v1;
                    *(float2*)(p.outf[z] + (size_t)r * N + cn) = o;
                }
            }
        }
    }
}

// ---------------- attention pass 1: per-chunk  S_c = phiK^T V,  ks_c = sum phiK
__global__ void __launch_bounds__(256) att_sums_kernel() {
    __shared__ float sK[CC][68];
    __shared__ float sV[CC][68];
    int c = blockIdx.x, bh = blockIdx.y;
    int b = bh >> 3, h = bh & 7;
    int tid = threadIdx.x;
    int len = g_len[b];
    for (int idx = tid; idx < CC * DHH; idx += 256) {
        int j = idx >> 6, d = idx & 63;
        int srow = c * CC + j;
        size_t g = ((size_t)(b * SS + srow)) * DD + h * DHH + d;
        float kv = g_k[g];
        sK[j][d] = (srow < len) ? phi_f(kv) : 0.f;
        sV[j][d] = g_v[g];
    }
    __syncthreads();
    int ti = tid & 15, tj = tid >> 4;
    float acc[4][4];
    #pragma unroll
    for (int r = 0; r < 4; r++)
        #pragma unroll
        for (int e = 0; e < 4; e++) acc[r][e] = 0.f;
    #pragma unroll 8
    for (int j = 0; j < CC; j++) {
        float4 kf = *(const float4*)&sK[j][ti*4];
        float4 vf = *(const float4*)&sV[j][tj*4];
        float ka[4] = {kf.x,kf.y,kf.z,kf.w};
        float va[4] = {vf.x,vf.y,vf.z,vf.w};
        #pragma unroll
        for (int r = 0; r < 4; r++)
            #pragma unroll
            for (int e = 0; e < 4; e++)
                acc[r][e] = fmaf(ka[r], va[e], acc[r][e]);
    }
    float* So = &g_S[((size_t)(bh * NCC + c)) * (DHH * DHH)];
    #pragma unroll
    for (int r = 0; r < 4; r++) {
        int d = ti * 4 + r;
        float4 o; o.x = acc[r][0]; o.y = acc[r][1]; o.z = acc[r][2]; o.w = acc[r][3];
        *(float4*)&So[d * DHH + tj * 4] = o;
    }
    if (tid < DHH) {
        float s = 0.f;
        #pragma unroll 8
        for (int j = 0; j < CC; j++) s += sK[j][tid];
        g_ks[(bh * NCC + c) * DHH + tid] = s;
    }
}

// ---------------- attention pass 2: exclusive prefix over chunks ----------------
__global__ void __launch_bounds__(256) att_scan_kernel() {
    int bh = blockIdx.x, tid = threadIdx.x;
    float run[16];
    #pragma unroll
    for (int r = 0; r < 16; r++) run[r] = 0.f;
    for (int c = 0; c < NCC; c++) {
        float* p = &g_S[((size_t)(bh * NCC + c)) * (DHH*DHH) + tid * 16];
        #pragma unroll
        for (int r4 = 0; r4 < 4; r4++) {
            float4 tv = ((const float4*)p)[r4];
            float4 rv;
            rv.x = run[r4*4+0]; rv.y = run[r4*4+1];
            rv.z = run[r4*4+2]; rv.w = run[r4*4+3];
            ((float4*)p)[r4] = rv;
            run[r4*4+0] += tv.x; run[r4*4+1] += tv.y;
            run[r4*4+2] += tv.z; run[r4*4+3] += tv.w;
        }
    }
    if (tid < DHH) {
        float rk = 0.f;
        for (int c = 0; c < NCC; c++) {
            float* kp = &g_ks[(bh * NCC + c) * DHH + tid];
            float t = *kp; *kp = rk; rk += t;
        }
    }
}

// ---------------- attention pass 3 ----------------
#define SM3_FLOATS (3*CC*68 + DHH)
#define SM3_BYTES  (SM3_FLOATS * 4)
__global__ void __launch_bounds__(256) att_out_kernel() {
    extern __shared__ float smf[];
    float* sQ  = smf;
    float* sKV = smf + CC*68;
    float* sSA = smf + 2*CC*68;
    float* skp = smf + 3*CC*68;

    int c = blockIdx.x, bh = blockIdx.y;
    int b = bh >> 3, h = bh & 7;
    int tid = threadIdx.x;
    int len = g_len[b];

    for (int idx = tid; idx < CC * DHH; idx += 256) {
        int r = idx >> 6, d = idx & 63;
        int srow = c * CC + r;
        size_t g = ((size_t)(b * SS + srow)) * DD + h * DHH + d;
        sQ[d*68 + r]  = phi_f(g_q[g]);
        float kv = g_k[g];
        sKV[d*68 + r] = (srow < len) ? phi_f(kv) : 0.f;
        sSA[r*68 + d] = g_S[((size_t)(bh * NCC + c)) * (DHH*DHH) + idx];
    }
    if (tid < DHH) skp[tid] = g_ks[(bh * NCC + c) * DHH + tid];
    __syncthreads();

    int ti = tid & 15, tj = tid >> 4;

    float zi = 0.f;
    if (tid < DHH) {
        #pragma unroll 8
        for (int d = 0; d < DHH; d++) zi += sQ[d*68 + tid] * skp[d];
    }

    float oacc[4][4], aacc[4][4];
    #pragma unroll
    for (int r = 0; r < 4; r++)
        #pragma unroll
        for (int e = 0; e < 4; e++) { oacc[r][e] = 0.f; aacc[r][e] = 0.f; }
    #pragma unroll 4
    for (int d = 0; d < DHH; d++) {
        float4 aq = *(const float4*)&sQ [d*68 + ti*4];
        float4 bs = *(const float4*)&sSA[d*68 + tj*4];
        float4 bk = *(const float4*)&sKV[d*68 + tj*4];
        float qa[4] = {aq.x,aq.y,aq.z,aq.w};
        float sa[4] = {bs.x,bs.y,bs.z,bs.w};
        float ka[4] = {bk.x,bk.y,bk.z,bk.w};
        #pragma unroll
        for (int r = 0; r < 4; r++)
            #pragma unroll
            for (int e = 0; e < 4; e++) {
                oacc[r][e] = fmaf(qa[r], sa[e], oacc[r][e]);
                aacc[r][e] = fmaf(qa[r], ka[e], aacc[r][e]);
            }
    }
    __syncthreads();

    #pragma unroll
    for (int r = 0; r < 4; r++)
        #pragma unroll
        for (int e = 0; e < 4; e++) {
            int i = ti * 4 + r, j = tj * 4 + e;
            sSA[j*68 + i] = (j <= i) ? aacc[r][e] : 0.f;
        }
    for (int idx = tid; idx < CC * DHH; idx += 256) {
        int r = idx >> 6, e = idx & 63;
        sKV[r*68 + e] = g_v[((size_t)(b * SS + c * CC + r)) * DD + h * DHH + e];
    }
    __syncthreads();

    if (tid < DHH) {
        float z = zi;
        #pragma unroll 8
        for (int j = 0; j < CC; j++) z += sSA[j*68 + tid];
        skp[tid] = 1.f / (z + 1e-6f);
    }

    #pragma unroll 4
    for (int j = 0; j < CC; j++) {
        float4 aj = *(const float4*)&sSA[j*68 + ti*4];
        float4 ve = *(const float4*)&sKV[j*68 + tj*4];
        float aa[4] = {aj.x,aj.y,aj.z,aj.w};
        float va[4] = {ve.x,ve.y,ve.z,ve.w};
        #pragma unroll
        for (int r = 0; r < 4; r++)
            #pragma unroll
            for (int e = 0; e < 4; e++)
                oacc[r][e] = fmaf(aa[r], va[e], oacc[r][e]);
    }
    __syncthreads();

    #pragma unroll
    for (int r = 0; r < 4; r++) {
        int i = ti * 4 + r;
        float zr = skp[i];
        size_t base = ((size_t)(b * SS + c * CC + i)) * DD + h * DHH + tj * 4;
        #pragma unroll
        for (int e = 0; e < 4; e++) {
            float o = oacc[r][e] * zr;
            __nv_bfloat16 hh, ll;
            split_bf(o, hh, ll);
            g_ab_h[base + e] = hh;
            g_ab_l[base + e] = ll;
        }
    }
}

// ---------------- LayerNorm (+ residual, + optional bf16 split out) ----------------
__global__ void ln_kernel(const float* __restrict__ x, const float* __restrict__ add,
                          const float* __restrict__ gamma, const float* __restrict__ beta,
                          float* __restrict__ out,
                          __nv_bfloat16* __restrict__ oh, __nv_bfloat16* __restrict__ ol) {
    __shared__ float rs[4], rq[4];
    int row = blockIdx.x, tid = threadIdx.x;
    float4 v = ((const float4*)(x + (size_t)row * DD))[tid];
    if (add) {
        float4 a = ((const float4*)(add + (size_t)row * DD))[tid];
        v.x += a.x; v.y += a.y; v.z += a.z; v.w += a.w;
    }
    float s = v.x + v.y + v.z + v.w;
    float q = v.x*v.x + v.y*v.y + v.z*v.z + v.w*v.w;
    #pragma unroll
    for (int off = 16; off; off >>= 1) {
        s += __shfl_xor_sync(0xffffffffu, s, off);
        q += __shfl_xor_sync(0xffffffffu, q, off);
    }
    if ((tid & 31) == 0) { rs[tid >> 5] = s; rq[tid >> 5] = q; }
    __syncthreads();
    s = rs[0] + rs[1] + rs[2] + rs[3];
    q = rq[0] + rq[1] + rq[2] + rq[3];
    float mu   = s * (1.f / DD);
    float var  = q * (1.f / DD) - mu * mu;
    float rstd = rsqrtf(var + 1e-5f);
    float4 g  = ((const float4*)gamma)[tid];
    float4 bt = ((const float4*)beta)[tid];
    float4 o;
    o.x = (v.x - mu) * rstd * g.x + bt.x;
    o.y = (v.y - mu) * rstd * g.y + bt.y;
    o.z = (v.z - mu) * rstd * g.z + bt.z;
    o.w = (v.w - mu) * rstd * g.w + bt.w;
    ((float4*)(out + (size_t)row * DD))[tid] = o;
    if (oh) {
        size_t e0 = (size_t)row * DD + tid * 4;
        float vv[4] = {o.x, o.y, o.z, o.w};
        #pragma unroll
        for (int j = 0; j < 4; j++) split_bf(vv[j], oh[e0+j], ol[e0+j]);
    }
}

// ---------------- launch --------------------------------------------------------
extern "C" void kernel_launch(void* const* d_in, const int* in_sizes, int n_in,
                              void* d_out, int out_size) {
    (void)in_sizes; (void)n_in; (void)out_size;
    const int*   x   = (const int*)  d_in[0];
    const float* emb = (const float*)d_in[1];
    const float* pe  = (const float*)d_in[2];
    const float* Wq  = (const float*)d_in[3];
    const float* bq  = (const float*)d_in[4];
    const float* Wk  = (const float*)d_in[5];
    const float* bk  = (const float*)d_in[6];
    const float* Wv  = (const float*)d_in[7];
    const float* bv  = (const float*)d_in[8];
    const float* Wo  = (const float*)d_in[9];
    const float* bo  = (const float*)d_in[10];
    const float* W1  = (const float*)d_in[11];
    const float* b1  = (const float*)d_in[12];
    const float* W2  = (const float*)d_in[13];
    const float* b2  = (const float*)d_in[14];
    const float* g1  = (const float*)d_in[15];
    const float* be1 = (const float*)d_in[16];
    const float* g2  = (const float*)d_in[17];
    const float* be2 = (const float*)d_in[18];
    const float* gf  = (const float*)d_in[19];
    const float* bf  = (const float*)d_in[20];

    float *h, *q, *kk, *vv;
    cudaGetSymbolAddress((void**)&h, g_h);
    cudaGetSymbolAddress((void**)&q, g_q);
    cudaGetSymbolAddress((void**)&kk, g_k);
    cudaGetSymbolAddress((void**)&vv, g_v);
    __nv_bfloat16 *hb_h, *hb_l, *ab_h, *ab_l, *tb_h, *tb_l;
    cudaGetSymbolAddress((void**)&hb_h, g_hb_h);
    cudaGetSymbolAddress((void**)&hb_l, g_hb_l);
    cudaGetSymbolAddress((void**)&ab_h, g_ab_h);
    cudaGetSymbolAddress((void**)&ab_l, g_ab_l);
    cudaGetSymbolAddress((void**)&tb_h, g_tb_h);
    cudaGetSymbolAddress((void**)&tb_l, g_tb_l);
    __nv_bfloat16 *wqh, *wql, *wkh, *wkl, *wvh, *wvl, *woh, *wol, *w1h, *w1l, *w2h, *w2l;
    cudaGetSymbolAddress((void**)&wqh, g_wq_h); cudaGetSymbolAddress((void**)&wql, g_wq_l);
    cudaGetSymbolAddress((void**)&wkh, g_wk_h); cudaGetSymbolAddress((void**)&wkl, g_wk_l);
    cudaGetSymbolAddress((void**)&wvh, g_wv_h); cudaGetSymbolAddress((void**)&wvl, g_wv_l);
    cudaGetSymbolAddress((void**)&woh, g_wo_h); cudaGetSymbolAddress((void**)&wol, g_wo_l);
    cudaGetSymbolAddress((void**)&w1h, g_w1_h); cudaGetSymbolAddress((void**)&w1l, g_w1_l);
    cudaGetSymbolAddress((void**)&w2h, g_w2_h); cudaGetSymbolAddress((void**)&w2l, g_w2_l);

    cudaFuncSetAttribute(att_out_kernel,
                         cudaFuncAttributeMaxDynamicSharedMemorySize, SM3_BYTES);
    cudaFuncSetAttribute(gemm_mma<0,0>,
                         cudaFuncAttributeMaxDynamicSharedMemorySize, GM_SMEM_BYTES);
    cudaFuncSetAttribute(gemm_mma<1,1>,
                         cudaFuncAttributeMaxDynamicSharedMemorySize, GM_SMEM_BYTES);

    len_kernel<<<BB, 256>>>(x);
    embed_kernel<<<(MM * (DD/4) + 255) / 256, 256>>>(x, emb, pe);

    dim3 wb(32, 8);
    for (int l = 0; l < NLL; l++) {
        size_t wo = (size_t)l * DD * DD;
        size_t wf = (size_t)l * DD * FF;
        wtc_kernel<<<dim3(DD/32, DD/32), wb>>>(Wq + wo, wqh + wo, wql + wo, DD, DD);
        wtc_kernel<<<dim3(DD/32, DD/32), wb>>>(Wk + wo, wkh + wo, wkl + wo, DD, DD);
        wtc_kernel<<<dim3(DD/32, DD/32), wb>>>(Wv + wo, wvh + wo, wvl + wo, DD, DD);
        wtc_kernel<<<dim3(DD/32, DD/32), wb>>>(Wo + wo, woh + wo, wol + wo, DD, DD);
        wtc_kernel<<<dim3(FF/32, DD/32), wb>>>(W1 + wf, w1h + wf, w1l + wf, DD, FF);
        wtc_kernel<<<dim3(DD/32, FF/32), wb>>>(W2 + wf, w2h + wf, w2l + wf, FF, DD);
    }

    for (int l = 0; l < NLL; l++) {
        size_t wo   = (size_t)l * DD * DD;
        size_t wf   = (size_t)l * DD * FF;
        size_t boff = (size_t)l * DD;

        // QKV fused
        GTArgs ga = {};
        ga.Ah = hb_h; ga.Al = hb_l; ga.N = DD; ga.K = DD;
        ga.Bh[0] = wqh + wo; ga.Bl[0] = wql + wo;
        ga.Bh[1] = wkh + wo; ga.Bl[1] = wkl + wo;
        ga.Bh[2] = wvh + wo; ga.Bl[2] = wvl + wo;
        ga.bias[0] = bq + boff; ga.bias[1] = bk + boff; ga.bias[2] = bv + boff;
        ga.outf[0] = q; ga.outf[1] = kk; ga.outf[2] = vv;
        gemm_mma<0,0><<<dim3(DD/128, MM/128, 3), 256, GM_SMEM_BYTES>>>(ga);

        att_sums_kernel<<<dim3(NCC, BHH), 256>>>();
        att_scan_kernel<<<BHH, 256>>>();
        att_out_kernel<<<dim3(NCC, BHH), 256, SM3_BYTES>>>();

        // O proj
        GTArgs go = {};
        go.Ah = ab_h; go.Al = ab_l; go.N = DD; go.K = DD;
        go.Bh[0] = woh + wo; go.Bl[0] = wol + wo;
        go.bias[0] = bo + boff; go.outf[0] = q;
        gemm_mma<0,0><<<dim3(DD/128, MM/128, 1), 256, GM_SMEM_BYTES>>>(go);

        ln_kernel<<<MM, 128>>>(h, q, g1 + boff, be1 + boff, h, hb_h, hb_l);

        // FFN1 (relu, bf16-split output)
        GTArgs g1a = {};
        g1a.Ah = hb_h; g1a.Al = hb_l; g1a.N = FF; g1a.K = DD;
        g1a.Bh[0] = w1h + wf; g1a.Bl[0] = w1l + wf;
        g1a.bias[0] = b1 + (size_t)l * FF;
        g1a.outh[0] = tb_h; g1a.outl[0] = tb_l;
        gemm_mma<1,1><<<dim3(FF/128, MM/128, 1), 256, GM_SMEM_BYTES>>>(g1a);

        // FFN2
        GTArgs g2a = {};
        g2a.Ah = tb_h; g2a.Al = tb_l; g2a.N = DD; g2a.K = FF;
        g2a.Bh[0] = w2h + wf; g2a.Bl[0] = w2l + wf;
        g2a.bias[0] = b2 + boff; g2a.outf[0] = q;
        gemm_mma<0,0><<<dim3(DD/128, MM/128, 1), 256, GM_SMEM_BYTES>>>(g2a);

        ln_kernel<<<MM, 128>>>(h, q, g2 + boff, be2 + boff, h, hb_h, hb_l);
    }

    ln_kernel<<<MM, 128>>>(h, nullptr, gf, bf, (float*)d_out, nullptr, nullptr);
}

// round 4
// speedup vs baseline: 1.7650x; 1.0752x over previous
#include <cuda_runtime.h>
#include <cuda_bf16.h>
#include <cstdint>

// ---------------- problem constants ----------------
#define BB  4
#define SS  2048
#define DD  512
#define HH  8
#define DHH 64
#define FF  2048
#define NLL 4
#define MM  (BB*SS)      // 8192 rows
#define CC  64           // attention chunk length
#define NCC (SS/CC)      // 32 chunks
#define BHH (BB*HH)      // 32 (b,h) pairs

__device__ __forceinline__ uint32_t smem_u32(const void* p) {
    uint32_t a;
    asm("{ .reg .u64 t; cvta.to.shared.u64 t, %1; cvt.u32.u64 %0, t; }" : "=r"(a) : "l"(p));
    return a;
}

// ---------------- scratch (device globals; no allocs allowed) ----------------
__device__ float g_h[MM*DD];
__device__ float g_q[MM*DD];
__device__ float g_k[MM*DD];
__device__ float g_v[MM*DD];
__device__ float g_S[(size_t)BHH*NCC*DHH*DHH];
__device__ float g_ks[BHH*NCC*DHH];
__device__ int   g_len[BB];

__device__ __align__(16) __nv_bfloat16 g_hb_h[MM*DD], g_hb_l[MM*DD];
__device__ __align__(16) __nv_bfloat16 g_ab_h[MM*DD], g_ab_l[MM*DD];
__device__ __align__(16) __nv_bfloat16 g_tb_h[(size_t)MM*FF], g_tb_l[(size_t)MM*FF];

__device__ __align__(16) __nv_bfloat16 g_wq_h[NLL*DD*DD], g_wq_l[NLL*DD*DD];
__device__ __align__(16) __nv_bfloat16 g_wk_h[NLL*DD*DD], g_wk_l[NLL*DD*DD];
__device__ __align__(16) __nv_bfloat16 g_wv_h[NLL*DD*DD], g_wv_l[NLL*DD*DD];
__device__ __align__(16) __nv_bfloat16 g_wo_h[NLL*DD*DD], g_wo_l[NLL*DD*DD];
__device__ __align__(16) __nv_bfloat16 g_w1_h[NLL*FF*DD], g_w1_l[NLL*FF*DD];
__device__ __align__(16) __nv_bfloat16 g_w2_h[NLL*DD*FF], g_w2_l[NLL*DD*FF];

__device__ __forceinline__ float phi_f(float u) { return u > 0.f ? u + 1.f : __expf(u); }

__device__ __forceinline__ void split_bf(float x, __nv_bfloat16& h, __nv_bfloat16& l) {
    h = __float2bfloat16(x);
    l = __float2bfloat16(x - __bfloat162float(h));
}

// ---------------- lengths ----------------
__global__ void len_kernel(const int* __restrict__ x) {
    __shared__ int red[256];
    int b = blockIdx.x, tid = threadIdx.x;
    int cnt = 0;
    for (int s = tid; s < SS; s += 256) cnt += (x[b*SS + s] != 0);
    red[tid] = cnt; __syncthreads();
    for (int off = 128; off; off >>= 1) {
        if (tid < off) red[tid] += red[tid + off];
        __syncthreads();
    }
    if (tid == 0) g_len[b] = red[0];
}

// ---------------- embedding + positional (+ bf16 split) ----------------
__global__ void embed_kernel(const int* __restrict__ x,
                             const float* __restrict__ emb,
                             const float* __restrict__ pe) {
    int idx = blockIdx.x * 256 + threadIdx.x;
    if (idx >= MM * (DD/4)) return;
    int i  = idx >> 7;
    int d4 = idx & 127;
    int s  = i & (SS - 1);
    int tok = x[i];
    float4 e = ((const float4*)emb)[(size_t)tok * (DD/4) + d4];
    float4 p = ((const float4*)pe)[(size_t)s * (DD/4) + d4];
    float4 o;
    o.x = e.x + p.x; o.y = e.y + p.y; o.z = e.z + p.z; o.w = e.w + p.w;
    ((float4*)g_h)[idx] = o;
    size_t e0 = (size_t)idx * 4;
    float vv[4] = {o.x, o.y, o.z, o.w};
    #pragma unroll
    for (int j = 0; j < 4; j++) split_bf(vv[j], g_hb_h[e0+j], g_hb_l[e0+j]);
}

// ---------------- batched weight transpose + split (24 matrices, one launch) ----
struct WtcArgs {
    const float* src[24];
    __nv_bfloat16* oh[24];
    __nv_bfloat16* ol[24];
    int K[24], N[24];
};
__global__ void wtc_all_kernel(WtcArgs p) {
    __shared__ float t[32][33];
    int m = blockIdx.z;
    int K = p.K[m], N = p.N[m];
    int n0 = blockIdx.x * 32, k0 = blockIdx.y * 32;
    if (n0 >= N || k0 >= K) return;
    const float* W = p.src[m];
    __nv_bfloat16 *oh = p.oh[m], *ol = p.ol[m];
    int tx = threadIdx.x, ty = threadIdx.y;   // 32x8
    #pragma unroll
    for (int i = 0; i < 32; i += 8)
        t[ty + i][tx] = W[(size_t)(k0 + ty + i) * N + n0 + tx];
    __syncthreads();
    #pragma unroll
    for (int i = 0; i < 32; i += 8) {
        float v = t[tx][ty + i];
        size_t o = (size_t)(n0 + ty + i) * K + k0 + tx;
        split_bf(v, oh[o], ol[o]);
    }
}

// ---------------- split-bf16 GEMM via warp mma.sync, 4-stage cp.async ----------
// C[M,N] = A[M,K] * B[N,K]^T + bias ; A,B as bf16 (hi,lo) pairs, K-major rows.
// Block 128x128, BK=32, 256 thr, warp tile 64x32.
struct GTArgs {
    const __nv_bfloat16 *Ah, *Al;
    const __nv_bfloat16 *Bh[3], *Bl[3];
    const float* bias[3];
    float* outf[3];
    __nv_bfloat16 *outh[3], *outl[3];
    int N, K;
};

#define STAGES 4
#define AST 40                            // smem row stride (bf16): 80B
#define TILE_ELEMS (128*AST)              // 5120
#define STAGE_ELEMS (4*TILE_ELEMS)        // Ah,Al,Bh,Bl = 20480 elems
#define STAGE_BYTES (STAGE_ELEMS*2)       // 40960
#define GM_SMEM_BYTES (STAGES*STAGE_BYTES)   // 163840

#define MMA_BF16(d, a, b) \
    asm volatile("mma.sync.aligned.m16n8k16.row.col.f32.bf16.bf16.f32 " \
        "{%0,%1,%2,%3}, {%4,%5,%6,%7}, {%8,%9}, {%0,%1,%2,%3};" \
        : "+f"((d)[0]), "+f"((d)[1]), "+f"((d)[2]), "+f"((d)[3]) \
        : "r"((a)[0]), "r"((a)[1]), "r"((a)[2]), "r"((a)[3]), "r"((b)[0]), "r"((b)[1]))

#define LDMX4(r, addr) \
    asm volatile("ldmatrix.sync.aligned.m8n8.x4.shared.b16 {%0,%1,%2,%3}, [%4];" \
        : "=r"((r)[0]), "=r"((r)[1]), "=r"((r)[2]), "=r"((r)[3]) : "r"(addr))

template<int RELU, int OUTBF>
__global__ void __launch_bounds__(256) gemm_mma(GTArgs p) {
    extern __shared__ __nv_bfloat16 sm[];
    const uint32_t sbase = smem_u32(sm);
    const int z = blockIdx.z;
    const __nv_bfloat16* gA[2] = { p.Ah, p.Al };
    const __nv_bfloat16* gB[2] = { p.Bh[z], p.Bl[z] };
    const int N = p.N, K = p.K;
    const int tid = threadIdx.x;
    const int m0 = blockIdx.y * 128, n0 = blockIdx.x * 128;

    // ---- hoisted loader addressing: 8 chunks of 16B per thread per stage ----
    const int rA  = tid >> 2;          // 0..63
    const int ch8 = (tid & 3) * 8;     // 0,8,16,24 (elements)
    const __nv_bfloat16* gsrc[8];
    uint32_t soff[8];
    #pragma unroll
    for (int op = 0; op < 4; op++) {
        const __nv_bfloat16* bsp = (op < 2) ? gA[op] : gB[op - 2];
        const int row0 = (op < 2) ? m0 : n0;
        #pragma unroll
        for (int j = 0; j < 2; j++) {
            int row = rA + j * 64;
            gsrc[op*2 + j] = bsp + (size_t)(row0 + row) * K + ch8;
            soff[op*2 + j] = (uint32_t)(op * TILE_ELEMS + row * AST + ch8) * 2u;
        }
    }

    const int wid = tid >> 5, lane = tid & 31;
    const int wm = (wid & 1) * 64;
    const int wn = (wid >> 1) * 32;

    // ---- hoisted fragment addresses (byte offsets within a stage) ----
    uint32_t aoff[2][4], boff2[2][2];
    #pragma unroll
    for (int sp = 0; sp < 2; sp++) {
        #pragma unroll
        for (int mt = 0; mt < 4; mt++) {
            int row = wm + mt * 16 + (lane & 15);
            int col = (lane >> 4) << 3;
            aoff[sp][mt] = (uint32_t)(sp * TILE_ELEMS + row * AST + col) * 2u;
        }
        #pragma unroll
        for (int ng = 0; ng < 2; ng++) {
            int n  = wn + ng * 16 + (lane & 7) + ((lane >> 4) << 3);
            int kc = ((lane >> 3) & 1) << 3;
            boff2[sp][ng] = (uint32_t)((2 + sp) * TILE_ELEMS + n * AST + kc) * 2u;
        }
    }

    float acc[4][4][4];
    #pragma unroll
    for (int a = 0; a < 4; a++)
        #pragma unroll
        for (int b = 0; b < 4; b++)
            #pragma unroll
            for (int c = 0; c < 4; c++) acc[a][b][c] = 0.f;

    const int nt = K >> 5;

    auto load_stage = [&](int slot, int k0) {
        uint32_t sb = sbase + (uint32_t)slot * STAGE_BYTES;
        #pragma unroll
        for (int i = 0; i < 8; i++) {
            asm volatile("cp.async.cg.shared.global [%0], [%1], 16;"
                         :: "r"(sb + soff[i]), "l"(gsrc[i] + k0));
        }
        asm volatile("cp.async.commit_group;" ::: "memory");
    };

    // prologue: fill 3 stages
    load_stage(0, 0);
    load_stage(1, 32);
    load_stage(2, 64);

    for (int t = 0; t < nt; t++) {
        asm volatile("cp.async.wait_group 2;" ::: "memory");
        __syncthreads();
        if (t + 3 < nt) load_stage((t + 3) & (STAGES - 1), (t + 3) * 32);
        else asm volatile("cp.async.commit_group;" ::: "memory");

        const uint32_t stg = sbase + (uint32_t)(t & (STAGES - 1)) * STAGE_BYTES;
        #pragma unroll
        for (int kh = 0; kh < 2; kh++) {
            const uint32_t kofs = (uint32_t)(kh * 16 * 2);
            uint32_t afr[2][4][4];
            #pragma unroll
            for (int sp = 0; sp < 2; sp++)
                #pragma unroll
                for (int mt = 0; mt < 4; mt++)
                    LDMX4(afr[sp][mt], stg + aoff[sp][mt] + kofs);
            uint32_t bfr[2][2][4];
            #pragma unroll
            for (int sp = 0; sp < 2; sp++)
                #pragma unroll
                for (int ng = 0; ng < 2; ng++)
                    LDMX4(bfr[sp][ng], stg + boff2[sp][ng] + kofs);
            #pragma unroll
            for (int mt = 0; mt < 4; mt++)
                #pragma unroll
                for (int nn = 0; nn < 4; nn++) {
                    int ng = nn >> 1, hb = (nn & 1) * 2;
                    uint32_t b0h[2] = { bfr[0][ng][hb], bfr[0][ng][hb+1] };
                    uint32_t b0l[2] = { bfr[1][ng][hb], bfr[1][ng][hb+1] };
                    MMA_BF16(acc[mt][nn], afr[0][mt], b0h);  // Ah*Bh
                    MMA_BF16(acc[mt][nn], afr[0][mt], b0l);  // Ah*Bl
                    MMA_BF16(acc[mt][nn], afr[1][mt], b0h);  // Al*Bh
                }
        }
    }

    // ---- epilogue ----
    const float* bias = p.bias[z];
    #pragma unroll
    for (int nn = 0; nn < 4; nn++) {
        int cn = n0 + wn + nn * 8 + (lane & 3) * 2;
        float b0v = bias[cn], b1v = bias[cn + 1];
        #pragma unroll
        for (int mt = 0; mt < 4; mt++) {
            int r0 = m0 + wm + mt * 16 + (lane >> 2);
            #pragma unroll
            for (int half = 0; half < 2; half++) {
                int r = r0 + half * 8;
                float v0 = acc[mt][nn][half*2 + 0] + b0v;
                float v1 = acc[mt][nn][half*2 + 1] + b1v;
                if (RELU) { v0 = fmaxf(v0, 0.f); v1 = fmaxf(v1, 0.f); }
                if (OUTBF) {
                    __nv_bfloat16 h0, l0, h1, l1;
                    split_bf(v0, h0, l0);
                    split_bf(v1, h1, l1);
                    __nv_bfloat162 hp; hp.x = h0; hp.y = h1;
                    __nv_bfloat162 lp; lp.x = l0; lp.y = l1;
                    *(__nv_bfloat162*)(p.outh[z] + (size_t)r * N + cn) = hp;
                    *(__nv_bfloat162*)(p.outl[z] + (size_t)r * N + cn) = lp;
                } else {
                    float2 o; o.x = v0; o.y = v1;
                    *(float2*)(p.outf[z] + (size_t)r * N + cn) = o;
                }
            }
        }
    }
}

// ---------------- attention pass 1: per-chunk  S_c = phiK^T V,  ks_c = sum phiK
__global__ void __launch_bounds__(256) att_sums_kernel() {
    __shared__ float sK[CC][68];
    __shared__ float sV[CC][68];
    int c = blockIdx.x, bh = blockIdx.y;
    int b = bh >> 3, h = bh & 7;
    int tid = threadIdx.x;
    int len = g_len[b];
    for (int idx = tid; idx < CC * DHH; idx += 256) {
        int j = idx >> 6, d = idx & 63;
        int srow = c * CC + j;
        size_t g = ((size_t)(b * SS + srow)) * DD + h * DHH + d;
        float kv = g_k[g];
        sK[j][d] = (srow < len) ? phi_f(kv) : 0.f;
        sV[j][d] = g_v[g];
    }
    __syncthreads();
    int ti = tid & 15, tj = tid >> 4;
    float acc[4][4];
    #pragma unroll
    for (int r = 0; r < 4; r++)
        #pragma unroll
        for (int e = 0; e < 4; e++) acc[r][e] = 0.f;
    #pragma unroll 8
    for (int j = 0; j < CC; j++) {
        float4 kf = *(const float4*)&sK[j][ti*4];
        float4 vf = *(const float4*)&sV[j][tj*4];
        float ka[4] = {kf.x,kf.y,kf.z,kf.w};
        float va[4] = {vf.x,vf.y,vf.z,vf.w};
        #pragma unroll
        for (int r = 0; r < 4; r++)
            #pragma unroll
            for (int e = 0; e < 4; e++)
                acc[r][e] = fmaf(ka[r], va[e], acc[r][e]);
    }
    float* So = &g_S[((size_t)(bh * NCC + c)) * (DHH * DHH)];
    #pragma unroll
    for (int r = 0; r < 4; r++) {
        int d = ti * 4 + r;
        float4 o; o.x = acc[r][0]; o.y = acc[r][1]; o.z = acc[r][2]; o.w = acc[r][3];
        *(float4*)&So[d * DHH + tj * 4] = o;
    }
    if (tid < DHH) {
        float s = 0.f;
        #pragma unroll 8
        for (int j = 0; j < CC; j++) s += sK[j][tid];
        g_ks[(bh * NCC + c) * DHH + tid] = s;
    }
}

// ---------------- attention pass 2: exclusive prefix over chunks ----------------
__global__ void __launch_bounds__(256) att_scan_kernel() {
    int bh = blockIdx.x, tid = threadIdx.x;
    float run[16];
    #pragma unroll
    for (int r = 0; r < 16; r++) run[r] = 0.f;
    for (int c = 0; c < NCC; c++) {
        float* p = &g_S[((size_t)(bh * NCC + c)) * (DHH*DHH) + tid * 16];
        #pragma unroll
        for (int r4 = 0; r4 < 4; r4++) {
            float4 tv = ((const float4*)p)[r4];
            float4 rv;
            rv.x = run[r4*4+0]; rv.y = run[r4*4+1];
            rv.z = run[r4*4+2]; rv.w = run[r4*4+3];
            ((float4*)p)[r4] = rv;
            run[r4*4+0] += tv.x; run[r4*4+1] += tv.y;
            run[r4*4+2] += tv.z; run[r4*4+3] += tv.w;
        }
    }
    if (tid < DHH) {
        float rk = 0.f;
        for (int c = 0; c < NCC; c++) {
            float* kp = &g_ks[(bh * NCC + c) * DHH + tid];
            float t = *kp; *kp = rk; rk += t;
        }
    }
}

// ---------------- attention pass 3 ----------------
#define SM3_FLOATS (3*CC*68 + DHH)
#define SM3_BYTES  (SM3_FLOATS * 4)
__global__ void __launch_bounds__(256) att_out_kernel() {
    extern __shared__ float smf[];
    float* sQ  = smf;
    float* sKV = smf + CC*68;
    float* sSA = smf + 2*CC*68;
    float* skp = smf + 3*CC*68;

    int c = blockIdx.x, bh = blockIdx.y;
    int b = bh >> 3, h = bh & 7;
    int tid = threadIdx.x;
    int len = g_len[b];

    for (int idx = tid; idx < CC * DHH; idx += 256) {
        int r = idx >> 6, d = idx & 63;
        int srow = c * CC + r;
        size_t g = ((size_t)(b * SS + srow)) * DD + h * DHH + d;
        sQ[d*68 + r]  = phi_f(g_q[g]);
        float kv = g_k[g];
        sKV[d*68 + r] = (srow < len) ? phi_f(kv) : 0.f;
        sSA[r*68 + d] = g_S[((size_t)(bh * NCC + c)) * (DHH*DHH) + idx];
    }
    if (tid < DHH) skp[tid] = g_ks[(bh * NCC + c) * DHH + tid];
    __syncthreads();

    int ti = tid & 15, tj = tid >> 4;

    float zi = 0.f;
    if (tid < DHH) {
        #pragma unroll 8
        for (int d = 0; d < DHH; d++) zi += sQ[d*68 + tid] * skp[d];
    }

    float oacc[4][4], aacc[4][4];
    #pragma unroll
    for (int r = 0; r < 4; r++)
        #pragma unroll
        for (int e = 0; e < 4; e++) { oacc[r][e] = 0.f; aacc[r][e] = 0.f; }
    #pragma unroll 4
    for (int d = 0; d < DHH; d++) {
        float4 aq = *(const float4*)&sQ [d*68 + ti*4];
        float4 bs = *(const float4*)&sSA[d*68 + tj*4];
        float4 bk = *(const float4*)&sKV[d*68 + tj*4];
        float qa[4] = {aq.x,aq.y,aq.z,aq.w};
        float sa[4] = {bs.x,bs.y,bs.z,bs.w};
        float ka[4] = {bk.x,bk.y,bk.z,bk.w};
        #pragma unroll
        for (int r = 0; r < 4; r++)
            #pragma unroll
            for (int e = 0; e < 4; e++) {
                oacc[r][e] = fmaf(qa[r], sa[e], oacc[r][e]);
                aacc[r][e] = fmaf(qa[r], ka[e], aacc[r][e]);
            }
    }
    __syncthreads();

    #pragma unroll
    for (int r = 0; r < 4; r++)
        #pragma unroll
        for (int e = 0; e < 4; e++) {
            int i = ti * 4 + r, j = tj * 4 + e;
            sSA[j*68 + i] = (j <= i) ? aacc[r][e] : 0.f;
        }
    for (int idx = tid; idx < CC * DHH; idx += 256) {
        int r = idx >> 6, e = idx & 63;
        sKV[r*68 + e] = g_v[((size_t)(b * SS + c * CC + r)) * DD + h * DHH + e];
    }
    __syncthreads();

    if (tid < DHH) {
        float z = zi;
        #pragma unroll 8
        for (int j = 0; j < CC; j++) z += sSA[j*68 + tid];
        skp[tid] = 1.f / (z + 1e-6f);
    }

    #pragma unroll 4
    for (int j = 0; j < CC; j++) {
        float4 aj = *(const float4*)&sSA[j*68 + ti*4];
        float4 ve = *(const float4*)&sKV[j*68 + tj*4];
        float aa[4] = {aj.x,aj.y,aj.z,aj.w};
        float va[4] = {ve.x,ve.y,ve.z,ve.w};
        #pragma unroll
        for (int r = 0; r < 4; r++)
            #pragma unroll
            for (int e = 0; e < 4; e++)
                oacc[r][e] = fmaf(aa[r], va[e], oacc[r][e]);
    }
    __syncthreads();

    #pragma unroll
    for (int r = 0; r < 4; r++) {
        int i = ti * 4 + r;
        float zr = skp[i];
        size_t base = ((size_t)(b * SS + c * CC + i)) * DD + h * DHH + tj * 4;
        #pragma unroll
        for (int e = 0; e < 4; e++) {
            float o = oacc[r][e] * zr;
            __nv_bfloat16 hh, ll;
            split_bf(o, hh, ll);
            g_ab_h[base + e] = hh;
            g_ab_l[base + e] = ll;
        }
    }
}

// ---------------- LayerNorm (+ residual, + optional bf16 split out) ----------------
__global__ void ln_kernel(const float* __restrict__ x, const float* __restrict__ add,
                          const float* __restrict__ gamma, const float* __restrict__ beta,
                          float* __restrict__ out,
                          __nv_bfloat16* __restrict__ oh, __nv_bfloat16* __restrict__ ol) {
    __shared__ float rs[4], rq[4];
    int row = blockIdx.x, tid = threadIdx.x;
    float4 v = ((const float4*)(x + (size_t)row * DD))[tid];
    if (add) {
        float4 a = ((const float4*)(add + (size_t)row * DD))[tid];
        v.x += a.x; v.y += a.y; v.z += a.z; v.w += a.w;
    }
    float s = v.x + v.y + v.z + v.w;
    float q = v.x*v.x + v.y*v.y + v.z*v.z + v.w*v.w;
    #pragma unroll
    for (int off = 16; off; off >>= 1) {
        s += __shfl_xor_sync(0xffffffffu, s, off);
        q += __shfl_xor_sync(0xffffffffu, q, off);
    }
    if ((tid & 31) == 0) { rs[tid >> 5] = s; rq[tid >> 5] = q; }
    __syncthreads();
    s = rs[0] + rs[1] + rs[2] + rs[3];
    q = rq[0] + rq[1] + rq[2] + rq[3];
    float mu   = s * (1.f / DD);
    float var  = q * (1.f / DD) - mu * mu;
    float rstd = rsqrtf(var + 1e-5f);
    float4 g  = ((const float4*)gamma)[tid];
    float4 bt = ((const float4*)beta)[tid];
    float4 o;
    o.x = (v.x - mu) * rstd * g.x + bt.x;
    o.y = (v.y - mu) * rstd * g.y + bt.y;
    o.z = (v.z - mu) * rstd * g.z + bt.z;
    o.w = (v.w - mu) * rstd * g.w + bt.w;
    ((float4*)(out + (size_t)row * DD))[tid] = o;
    if (oh) {
        size_t e0 = (size_t)row * DD + tid * 4;
        float vv[4] = {o.x, o.y, o.z, o.w};
        #pragma unroll
        for (int j = 0; j < 4; j++) split_bf(vv[j], oh[e0+j], ol[e0+j]);
    }
}

// ---------------- launch --------------------------------------------------------
extern "C" void kernel_launch(void* const* d_in, const int* in_sizes, int n_in,
                              void* d_out, int out_size) {
    (void)in_sizes; (void)n_in; (void)out_size;
    const int*   x   = (const int*)  d_in[0];
    const float* emb = (const float*)d_in[1];
    const float* pe  = (const float*)d_in[2];
    const float* Wq  = (const float*)d_in[3];
    const float* bq  = (const float*)d_in[4];
    const float* Wk  = (const float*)d_in[5];
    const float* bk  = (const float*)d_in[6];
    const float* Wv  = (const float*)d_in[7];
    const float* bv  = (const float*)d_in[8];
    const float* Wo  = (const float*)d_in[9];
    const float* bo  = (const float*)d_in[10];
    const float* W1  = (const float*)d_in[11];
    const float* b1  = (const float*)d_in[12];
    const float* W2  = (const float*)d_in[13];
    const float* b2  = (const float*)d_in[14];
    const float* g1  = (const float*)d_in[15];
    const float* be1 = (const float*)d_in[16];
    const float* g2  = (const float*)d_in[17];
    const float* be2 = (const float*)d_in[18];
    const float* gf  = (const float*)d_in[19];
    const float* bf  = (const float*)d_in[20];

    float *h, *q, *kk, *vv;
    cudaGetSymbolAddress((void**)&h, g_h);
    cudaGetSymbolAddress((void**)&q, g_q);
    cudaGetSymbolAddress((void**)&kk, g_k);
    cudaGetSymbolAddress((void**)&vv, g_v);
    __nv_bfloat16 *hb_h, *hb_l, *ab_h, *ab_l, *tb_h, *tb_l;
    cudaGetSymbolAddress((void**)&hb_h, g_hb_h);
    cudaGetSymbolAddress((void**)&hb_l, g_hb_l);
    cudaGetSymbolAddress((void**)&ab_h, g_ab_h);
    cudaGetSymbolAddress((void**)&ab_l, g_ab_l);
    cudaGetSymbolAddress((void**)&tb_h, g_tb_h);
    cudaGetSymbolAddress((void**)&tb_l, g_tb_l);
    __nv_bfloat16 *wqh, *wql, *wkh, *wkl, *wvh, *wvl, *woh, *wol, *w1h, *w1l, *w2h, *w2l;
    cudaGetSymbolAddress((void**)&wqh, g_wq_h); cudaGetSymbolAddress((void**)&wql, g_wq_l);
    cudaGetSymbolAddress((void**)&wkh, g_wk_h); cudaGetSymbolAddress((void**)&wkl, g_wk_l);
    cudaGetSymbolAddress((void**)&wvh, g_wv_h); cudaGetSymbolAddress((void**)&wvl, g_wv_l);
    cudaGetSymbolAddress((void**)&woh, g_wo_h); cudaGetSymbolAddress((void**)&wol, g_wo_l);
    cudaGetSymbolAddress((void**)&w1h, g_w1_h); cudaGetSymbolAddress((void**)&w1l, g_w1_l);
    cudaGetSymbolAddress((void**)&w2h, g_w2_h); cudaGetSymbolAddress((void**)&w2l, g_w2_l);

    cudaFuncSetAttribute(att_out_kernel,
                         cudaFuncAttributeMaxDynamicSharedMemorySize, SM3_BYTES);
    cudaFuncSetAttribute(gemm_mma<0,0>,
                         cudaFuncAttributeMaxDynamicSharedMemorySize, GM_SMEM_BYTES);
    cudaFuncSetAttribute(gemm_mma<1,1>,
                         cudaFuncAttributeMaxDynamicSharedMemorySize, GM_SMEM_BYTES);

    len_kernel<<<BB, 256>>>(x);
    embed_kernel<<<(MM * (DD/4) + 255) / 256, 256>>>(x, emb, pe);

    // batched weight transpose+split: 24 matrices, one launch
    {
        WtcArgs wa = {};
        int idx = 0;
        for (int l = 0; l < NLL; l++) {
            size_t wo = (size_t)l * DD * DD;
            size_t wf = (size_t)l * DD * FF;
            wa.src[idx] = Wq + wo; wa.oh[idx] = wqh + wo; wa.ol[idx] = wql + wo; wa.K[idx] = DD; wa.N[idx] = DD; idx++;
            wa.src[idx] = Wk + wo; wa.oh[idx] = wkh + wo; wa.ol[idx] = wkl + wo; wa.K[idx] = DD; wa.N[idx] = DD; idx++;
            wa.src[idx] = Wv + wo; wa.oh[idx] = wvh + wo; wa.ol[idx] = wvl + wo; wa.K[idx] = DD; wa.N[idx] = DD; idx++;
            wa.src[idx] = Wo + wo; wa.oh[idx] = woh + wo; wa.ol[idx] = wol + wo; wa.K[idx] = DD; wa.N[idx] = DD; idx++;
            wa.src[idx] = W1 + wf; wa.oh[idx] = w1h + wf; wa.ol[idx] = w1l + wf; wa.K[idx] = DD; wa.N[idx] = FF; idx++;
            wa.src[idx] = W2 + wf; wa.oh[idx] = w2h + wf; wa.ol[idx] = w2l + wf; wa.K[idx] = FF; wa.N[idx] = DD; idx++;
        }
        wtc_all_kernel<<<dim3(FF/32, FF/32, 24), dim3(32, 8)>>>(wa);
    }

    for (int l = 0; l < NLL; l++) {
        size_t wo   = (size_t)l * DD * DD;
        size_t wf   = (size_t)l * DD * FF;
        size_t boff = (size_t)l * DD;

        // QKV fused
        GTArgs ga = {};
        ga.Ah = hb_h; ga.Al = hb_l; ga.N = DD; ga.K = DD;
        ga.Bh[0] = wqh + wo; ga.Bl[0] = wql + wo;
        ga.Bh[1] = wkh + wo; ga.Bl[1] = wkl + wo;
        ga.Bh[2] = wvh + wo; ga.Bl[2] = wvl + wo;
        ga.bias[0] = bq + boff; ga.bias[1] = bk + boff; ga.bias[2] = bv + boff;
        ga.outf[0] = q; ga.outf[1] = kk; ga.outf[2] = vv;
        gemm_mma<0,0><<<dim3(DD/128, MM/128, 3), 256, GM_SMEM_BYTES>>>(ga);

        att_sums_kernel<<<dim3(NCC, BHH), 256>>>();
        att_scan_kernel<<<BHH, 256>>>();
        att_out_kernel<<<dim3(NCC, BHH), 256, SM3_BYTES>>>();

        // O proj
        GTArgs go = {};
        go.Ah = ab_h; go.Al = ab_l; go.N = DD; go.K = DD;
        go.Bh[0] = woh + wo; go.Bl[0] = wol + wo;
        go.bias[0] = bo + boff; go.outf[0] = q;
        gemm_mma<0,0><<<dim3(DD/128, MM/128, 1), 256, GM_SMEM_BYTES>>>(go);

        ln_kernel<<<MM, 128>>>(h, q, g1 + boff, be1 + boff, h, hb_h, hb_l);

        // FFN1 (relu, bf16-split output)
        GTArgs g1a = {};
        g1a.Ah = hb_h; g1a.Al = hb_l; g1a.N = FF; g1a.K = DD;
        g1a.Bh[0] = w1h + wf; g1a.Bl[0] = w1l + wf;
        g1a.bias[0] = b1 + (size_t)l * FF;
        g1a.outh[0] = tb_h; g1a.outl[0] = tb_l;
        gemm_mma<1,1><<<dim3(FF/128, MM/128, 1), 256, GM_SMEM_BYTES>>>(g1a);

        // FFN2
        GTArgs g2a = {};
        g2a.Ah = tb_h; g2a.Al = tb_l; g2a.N = DD; g2a.K = FF;
        g2a.Bh[0] = w2h + wf; g2a.Bl[0] = w2l + wf;
        g2a.bias[0] = b2 + boff; g2a.outf[0] = q;
        gemm_mma<0,0><<<dim3(DD/128, MM/128, 1), 256, GM_SMEM_BYTES>>>(g2a);

        ln_kernel<<<MM, 128>>>(h, q, g2 + boff, be2 + boff, h, hb_h, hb_l);
    }

    ln_kernel<<<MM, 128>>>(h, nullptr, gf, bf, (float*)d_out, nullptr, nullptr);
}

// round 5
// speedup vs baseline: 1.9489x; 1.1042x over previous
#include <cuda_runtime.h>
#include <cuda_bf16.h>
#include <cstdint>

// ---------------- problem constants ----------------
#define BB  4
#define SS  2048
#define DD  512
#define HH  8
#define DHH 64
#define FF  2048
#define NLL 4
#define MM  (BB*SS)      // 8192 rows
#define CC  64           // attention chunk length
#define NCC (SS/CC)      // 32 chunks
#define BHH (BB*HH)      // 32 (b,h) pairs

__device__ __forceinline__ uint32_t smem_u32(const void* p) {
    uint32_t a;
    asm("{ .reg .u64 t; cvta.to.shared.u64 t, %1; cvt.u32.u64 %0, t; }" : "=r"(a) : "l"(p));
    return a;
}

// ---------------- scratch (device globals; no allocs allowed) ----------------
__device__ float g_h[MM*DD];
__device__ float g_q[MM*DD];
__device__ float g_k[MM*DD];
__device__ float g_v[MM*DD];
__device__ float g_S[(size_t)BHH*NCC*DHH*DHH];
__device__ float g_ks[BHH*NCC*DHH];
__device__ int   g_len[BB];

__device__ __align__(16) __nv_bfloat16 g_hb_h[MM*DD], g_hb_l[MM*DD];
__device__ __align__(16) __nv_bfloat16 g_ab_h[MM*DD], g_ab_l[MM*DD];
__device__ __align__(16) __nv_bfloat16 g_tb_h[(size_t)MM*FF], g_tb_l[(size_t)MM*FF];

__device__ __align__(16) __nv_bfloat16 g_wq_h[NLL*DD*DD], g_wq_l[NLL*DD*DD];
__device__ __align__(16) __nv_bfloat16 g_wk_h[NLL*DD*DD], g_wk_l[NLL*DD*DD];
__device__ __align__(16) __nv_bfloat16 g_wv_h[NLL*DD*DD], g_wv_l[NLL*DD*DD];
__device__ __align__(16) __nv_bfloat16 g_wo_h[NLL*DD*DD], g_wo_l[NLL*DD*DD];
__device__ __align__(16) __nv_bfloat16 g_w1_h[NLL*FF*DD], g_w1_l[NLL*FF*DD];
__device__ __align__(16) __nv_bfloat16 g_w2_h[NLL*DD*FF], g_w2_l[NLL*DD*FF];

__device__ __forceinline__ float phi_f(float u) { return u > 0.f ? u + 1.f : __expf(u); }

__device__ __forceinline__ void split_bf(float x, __nv_bfloat16& h, __nv_bfloat16& l) {
    h = __float2bfloat16(x);
    l = __float2bfloat16(x - __bfloat162float(h));
}

// ---------------- lengths ----------------
__global__ void len_kernel(const int* __restrict__ x) {
    __shared__ int red[256];
    int b = blockIdx.x, tid = threadIdx.x;
    int cnt = 0;
    for (int s = tid; s < SS; s += 256) cnt += (x[b*SS + s] != 0);
    red[tid] = cnt; __syncthreads();
    for (int off = 128; off; off >>= 1) {
        if (tid < off) red[tid] += red[tid + off];
        __syncthreads();
    }
    if (tid == 0) g_len[b] = red[0];
}

// ---------------- embedding + positional (+ bf16 split) ----------------
__global__ void embed_kernel(const int* __restrict__ x,
                             const float* __restrict__ emb,
                             const float* __restrict__ pe) {
    int idx = blockIdx.x * 256 + threadIdx.x;
    if (idx >= MM * (DD/4)) return;
    int i  = idx >> 7;
    int d4 = idx & 127;
    int s  = i & (SS - 1);
    int tok = x[i];
    float4 e = ((const float4*)emb)[(size_t)tok * (DD/4) + d4];
    float4 p = ((const float4*)pe)[(size_t)s * (DD/4) + d4];
    float4 o;
    o.x = e.x + p.x; o.y = e.y + p.y; o.z = e.z + p.z; o.w = e.w + p.w;
    ((float4*)g_h)[idx] = o;
    size_t e0 = (size_t)idx * 4;
    float vv[4] = {o.x, o.y, o.z, o.w};
    #pragma unroll
    for (int j = 0; j < 4; j++) split_bf(vv[j], g_hb_h[e0+j], g_hb_l[e0+j]);
}

// ---------------- batched weight transpose + split (24 matrices, one launch) ----
struct WtcArgs {
    const float* src[24];
    __nv_bfloat16* oh[24];
    __nv_bfloat16* ol[24];
    int K[24], N[24];
};
__global__ void wtc_all_kernel(WtcArgs p) {
    __shared__ float t[32][33];
    int m = blockIdx.z;
    int K = p.K[m], N = p.N[m];
    int n0 = blockIdx.x * 32, k0 = blockIdx.y * 32;
    if (n0 >= N || k0 >= K) return;
    const float* W = p.src[m];
    __nv_bfloat16 *oh = p.oh[m], *ol = p.ol[m];
    int tx = threadIdx.x, ty = threadIdx.y;   // 32x8
    #pragma unroll
    for (int i = 0; i < 32; i += 8)
        t[ty + i][tx] = W[(size_t)(k0 + ty + i) * N + n0 + tx];
    __syncthreads();
    #pragma unroll
    for (int i = 0; i < 32; i += 8) {
        float v = t[tx][ty + i];
        size_t o = (size_t)(n0 + ty + i) * K + k0 + tx;
        split_bf(v, oh[o], ol[o]);
    }
}

// ---------------- split-bf16 GEMM via warp mma.sync ----------------
// C[M,N] = A[M,K] * B[N,K]^T + bias ; A,B as bf16 (hi,lo) pairs, K-major rows.
// Block 128x128, BK=32, 256 thr, warp tile 64x32, 2-stage cp.async,
// 2 CTAs/SM (80KB smem, <=128 regs) for latency hiding.
struct GTArgs {
    const __nv_bfloat16 *Ah, *Al;
    const __nv_bfloat16 *Bh[3], *Bl[3];
    const float* bias[3];
    float* outf[3];
    __nv_bfloat16 *outh[3], *outl[3];
    int N, K;
};

#define STAGES 2
#define AST 40                            // smem row stride (bf16): 80B
#define TILE_ELEMS (128*AST)              // 5120
#define STAGE_ELEMS (4*TILE_ELEMS)        // Ah,Al,Bh,Bl = 20480 elems
#define STAGE_BYTES (STAGE_ELEMS*2)       // 40960
#define GM_SMEM_BYTES (STAGES*STAGE_BYTES)   // 81920

#define MMA_BF16(d, a, b) \
    asm volatile("mma.sync.aligned.m16n8k16.row.col.f32.bf16.bf16.f32 " \
        "{%0,%1,%2,%3}, {%4,%5,%6,%7}, {%8,%9}, {%0,%1,%2,%3};" \
        : "+f"((d)[0]), "+f"((d)[1]), "+f"((d)[2]), "+f"((d)[3]) \
        : "r"((a)[0]), "r"((a)[1]), "r"((a)[2]), "r"((a)[3]), "r"((b)[0]), "r"((b)[1]))

#define LDMX4(r, addr) \
    asm volatile("ldmatrix.sync.aligned.m8n8.x4.shared.b16 {%0,%1,%2,%3}, [%4];" \
        : "=r"((r)[0]), "=r"((r)[1]), "=r"((r)[2]), "=r"((r)[3]) : "r"(addr))

template<int RELU, int OUTBF>
__global__ void __launch_bounds__(256, 2) gemm_mma(GTArgs p) {
    extern __shared__ __nv_bfloat16 sm[];
    const uint32_t sbase = smem_u32(sm);
    const int z = blockIdx.z;
    const int N = p.N, K = p.K;
    const int tid = threadIdx.x;
    const int m0 = blockIdx.y * 128, n0 = blockIdx.x * 128;

    // ---- slim loader state: 4 base pointers + 1 smem offset ----
    const int rA  = tid >> 2;          // 0..63
    const int ch8 = (tid & 3) * 8;     // 0,8,16,24 (elements)
    const __nv_bfloat16* gp[4];
    gp[0] = p.Ah + (size_t)(m0 + rA) * K + ch8;
    gp[1] = p.Al + (size_t)(m0 + rA) * K + ch8;
    gp[2] = p.Bh[z] + (size_t)(n0 + rA) * K + ch8;
    gp[3] = p.Bl[z] + (size_t)(n0 + rA) * K + ch8;
    const uint32_t s0 = (uint32_t)(rA * AST + ch8) * 2u;
    const size_t K64 = (size_t)K << 6;   // 64 rows stride

    const int wid = tid >> 5, lane = tid & 31;
    const int wm = (wid & 1) * 64;
    const int wn = (wid >> 1) * 32;

    // ---- fragment base offsets (bytes within a stage); rest are constants ----
    const uint32_t aBase = (uint32_t)((wm + (lane & 15)) * AST + ((lane >> 4) << 3)) * 2u;
    const uint32_t bBase = (uint32_t)(2 * TILE_ELEMS * 2)
        + (uint32_t)((wn + (lane & 7) + ((lane >> 4) << 3)) * AST + (((lane >> 3) & 1) << 3)) * 2u;

    float acc[4][4][4];
    #pragma unroll
    for (int a = 0; a < 4; a++)
        #pragma unroll
        for (int b = 0; b < 4; b++)
            #pragma unroll
            for (int c = 0; c < 4; c++) acc[a][b][c] = 0.f;

    const int nt = K >> 5;

    auto load_stage = [&](int slot, int k0) {
        uint32_t sb = sbase + (uint32_t)slot * STAGE_BYTES + s0;
        #pragma unroll
        for (int op = 0; op < 4; op++)
            #pragma unroll
            for (int j = 0; j < 2; j++) {
                asm volatile("cp.async.cg.shared.global [%0], [%1], 16;"
                    :: "r"(sb + (uint32_t)(op * TILE_ELEMS + j * 64 * AST) * 2u),
                       "l"(gp[op] + (j ? K64 : 0) + k0));
            }
        asm volatile("cp.async.commit_group;" ::: "memory");
    };

    load_stage(0, 0);
    load_stage(1, 32);

    for (int t = 0; t < nt; t++) {
        asm volatile("cp.async.wait_group 1;" ::: "memory");
        __syncthreads();

        const uint32_t stg = sbase + (uint32_t)(t & 1) * STAGE_BYTES;
        #pragma unroll
        for (int kh = 0; kh < 2; kh++) {
            const uint32_t kofs = (uint32_t)(kh * 32);   // 16 elems * 2B
            uint32_t afr[2][4][4];
            #pragma unroll
            for (int sp = 0; sp < 2; sp++)
                #pragma unroll
                for (int mt = 0; mt < 4; mt++)
                    LDMX4(afr[sp][mt],
                          stg + aBase + (uint32_t)(sp * TILE_ELEMS * 2 + mt * 16 * AST * 2) + kofs);
            uint32_t bfr[2][2][4];
            #pragma unroll
            for (int sp = 0; sp < 2; sp++)
                #pragma unroll
                for (int ng = 0; ng < 2; ng++)
                    LDMX4(bfr[sp][ng],
                          stg + bBase + (uint32_t)(sp * TILE_ELEMS * 2 + ng * 16 * AST * 2) + kofs);
            #pragma unroll
            for (int mt = 0; mt < 4; mt++)
                #pragma unroll
                for (int nn = 0; nn < 4; nn++) {
                    int ng = nn >> 1, hb = (nn & 1) * 2;
                    uint32_t b0h[2] = { bfr[0][ng][hb], bfr[0][ng][hb+1] };
                    uint32_t b0l[2] = { bfr[1][ng][hb], bfr[1][ng][hb+1] };
                    MMA_BF16(acc[mt][nn], afr[0][mt], b0h);  // Ah*Bh
                    MMA_BF16(acc[mt][nn], afr[0][mt], b0l);  // Ah*Bl
                    MMA_BF16(acc[mt][nn], afr[1][mt], b0h);  // Al*Bh
                }
        }
        __syncthreads();
        if (t + 2 < nt) load_stage(t & 1, (t + 2) * 32);
        else asm volatile("cp.async.commit_group;" ::: "memory");
    }

    // ---- epilogue ----
    const float* bias = p.bias[z];
    #pragma unroll
    for (int nn = 0; nn < 4; nn++) {
        int cn = n0 + wn + nn * 8 + (lane & 3) * 2;
        float b0v = bias[cn], b1v = bias[cn + 1];
        #pragma unroll
        for (int mt = 0; mt < 4; mt++) {
            int r0 = m0 + wm + mt * 16 + (lane >> 2);
            #pragma unroll
            for (int half = 0; half < 2; half++) {
                int r = r0 + half * 8;
                float v0 = acc[mt][nn][half*2 + 0] + b0v;
                float v1 = acc[mt][nn][half*2 + 1] + b1v;
                if (RELU) { v0 = fmaxf(v0, 0.f); v1 = fmaxf(v1, 0.f); }
                if (OUTBF) {
                    __nv_bfloat16 h0, l0, h1, l1;
                    split_bf(v0, h0, l0);
                    split_bf(v1, h1, l1);
                    __nv_bfloat162 hp; hp.x = h0; hp.y = h1;
                    __nv_bfloat162 lp; lp.x = l0; lp.y = l1;
                    *(__nv_bfloat162*)(p.outh[z] + (size_t)r * N + cn) = hp;
                    *(__nv_bfloat162*)(p.outl[z] + (size_t)r * N + cn) = lp;
                } else {
                    float2 o; o.x = v0; o.y = v1;
                    *(float2*)(p.outf[z] + (size_t)r * N + cn) = o;
                }
            }
        }
    }
}

// ---------------- attention pass 1: per-chunk  S_c = phiK^T V,  ks_c = sum phiK
__global__ void __launch_bounds__(256) att_sums_kernel() {
    __shared__ float sK[CC][68];
    __shared__ float sV[CC][68];
    int c = blockIdx.x, bh = blockIdx.y;
    int b = bh >> 3, h = bh & 7;
    int tid = threadIdx.x;
    int len = g_len[b];
    for (int idx = tid; idx < CC * DHH; idx += 256) {
        int j = idx >> 6, d = idx & 63;
        int srow = c * CC + j;
        size_t g = ((size_t)(b * SS + srow)) * DD + h * DHH + d;
        float kv = g_k[g];
        sK[j][d] = (srow < len) ? phi_f(kv) : 0.f;
        sV[j][d] = g_v[g];
    }
    __syncthreads();
    int ti = tid & 15, tj = tid >> 4;
    float acc[4][4];
    #pragma unroll
    for (int r = 0; r < 4; r++)
        #pragma unroll
        for (int e = 0; e < 4; e++) acc[r][e] = 0.f;
    #pragma unroll 8
    for (int j = 0; j < CC; j++) {
        float4 kf = *(const float4*)&sK[j][ti*4];
        float4 vf = *(const float4*)&sV[j][tj*4];
        float ka[4] = {kf.x,kf.y,kf.z,kf.w};
        float va[4] = {vf.x,vf.y,vf.z,vf.w};
        #pragma unroll
        for (int r = 0; r < 4; r++)
            #pragma unroll
            for (int e = 0; e < 4; e++)
                acc[r][e] = fmaf(ka[r], va[e], acc[r][e]);
    }
    float* So = &g_S[((size_t)(bh * NCC + c)) * (DHH * DHH)];
    #pragma unroll
    for (int r = 0; r < 4; r++) {
        int d = ti * 4 + r;
        float4 o; o.x = acc[r][0]; o.y = acc[r][1]; o.z = acc[r][2]; o.w = acc[r][3];
        *(float4*)&So[d * DHH + tj * 4] = o;
    }
    if (tid < DHH) {
        float s = 0.f;
        #pragma unroll 8
        for (int j = 0; j < CC; j++) s += sK[j][tid];
        g_ks[(bh * NCC + c) * DHH + tid] = s;
    }
}

// ---------------- attention pass 2: exclusive prefix over chunks ----------------
__global__ void __launch_bounds__(256) att_scan_kernel() {
    int bh = blockIdx.x, tid = threadIdx.x;
    float run[16];
    #pragma unroll
    for (int r = 0; r < 16; r++) run[r] = 0.f;
    for (int c = 0; c < NCC; c++) {
        float* p = &g_S[((size_t)(bh * NCC + c)) * (DHH*DHH) + tid * 16];
        #pragma unroll
        for (int r4 = 0; r4 < 4; r4++) {
            float4 tv = ((const float4*)p)[r4];
            float4 rv;
            rv.x = run[r4*4+0]; rv.y = run[r4*4+1];
            rv.z = run[r4*4+2]; rv.w = run[r4*4+3];
            ((float4*)p)[r4] = rv;
            run[r4*4+0] += tv.x; run[r4*4+1] += tv.y;
            run[r4*4+2] += tv.z; run[r4*4+3] += tv.w;
        }
    }
    if (tid < DHH) {
        float rk = 0.f;
        for (int c = 0; c < NCC; c++) {
            float* kp = &g_ks[(bh * NCC + c) * DHH + tid];
            float t = *kp; *kp = rk; rk += t;
        }
    }
}

// ---------------- attention pass 3 ----------------
#define SM3_FLOATS (3*CC*68 + DHH)
#define SM3_BYTES  (SM3_FLOATS * 4)
__global__ void __launch_bounds__(256) att_out_kernel() {
    extern __shared__ float smf[];
    float* sQ  = smf;
    float* sKV = smf + CC*68;
    float* sSA = smf + 2*CC*68;
    float* skp = smf + 3*CC*68;

    int c = blockIdx.x, bh = blockIdx.y;
    int b = bh >> 3, h = bh & 7;
    int tid = threadIdx.x;
    int len = g_len[b];

    for (int idx = tid; idx < CC * DHH; idx += 256) {
        int r = idx >> 6, d = idx & 63;
        int srow = c * CC + r;
        size_t g = ((size_t)(b * SS + srow)) * DD + h * DHH + d;
        sQ[d*68 + r]  = phi_f(g_q[g]);
        float kv = g_k[g];
        sKV[d*68 + r] = (srow < len) ? phi_f(kv) : 0.f;
        sSA[r*68 + d] = g_S[((size_t)(bh * NCC + c)) * (DHH*DHH) + idx];
    }
    if (tid < DHH) skp[tid] = g_ks[(bh * NCC + c) * DHH + tid];
    __syncthreads();

    int ti = tid & 15, tj = tid >> 4;

    float zi = 0.f;
    if (tid < DHH) {
        #pragma unroll 8
        for (int d = 0; d < DHH; d++) zi += sQ[d*68 + tid] * skp[d];
    }

    float oacc[4][4], aacc[4][4];
    #pragma unroll
    for (int r = 0; r < 4; r++)
        #pragma unroll
        for (int e = 0; e < 4; e++) { oacc[r][e] = 0.f; aacc[r][e] = 0.f; }
    #pragma unroll 4
    for (int d = 0; d < DHH; d++) {
        float4 aq = *(const float4*)&sQ [d*68 + ti*4];
        float4 bs = *(const float4*)&sSA[d*68 + tj*4];
        float4 bk = *(const float4*)&sKV[d*68 + tj*4];
        float qa[4] = {aq.x,aq.y,aq.z,aq.w};
        float sa[4] = {bs.x,bs.y,bs.z,bs.w};
        float ka[4] = {bk.x,bk.y,bk.z,bk.w};
        #pragma unroll
        for (int r = 0; r < 4; r++)
            #pragma unroll
            for (int e = 0; e < 4; e++) {
                oacc[r][e] = fmaf(qa[r], sa[e], oacc[r][e]);
                aacc[r][e] = fmaf(qa[r], ka[e], aacc[r][e]);
            }
    }
    __syncthreads();

    #pragma unroll
    for (int r = 0; r < 4; r++)
        #pragma unroll
        for (int e = 0; e < 4; e++) {
            int i = ti * 4 + r, j = tj * 4 + e;
            sSA[j*68 + i] = (j <= i) ? aacc[r][e] : 0.f;
        }
    for (int idx = tid; idx < CC * DHH; idx += 256) {
        int r = idx >> 6, e = idx & 63;
        sKV[r*68 + e] = g_v[((size_t)(b * SS + c * CC + r)) * DD + h * DHH + e];
    }
    __syncthreads();

    if (tid < DHH) {
        float z = zi;
        #pragma unroll 8
        for (int j = 0; j < CC; j++) z += sSA[j*68 + tid];
        skp[tid] = 1.f / (z + 1e-6f);
    }

    #pragma unroll 4
    for (int j = 0; j < CC; j++) {
        float4 aj = *(const float4*)&sSA[j*68 + ti*4];
        float4 ve = *(const float4*)&sKV[j*68 + tj*4];
        float aa[4] = {aj.x,aj.y,aj.z,aj.w};
        float va[4] = {ve.x,ve.y,ve.z,ve.w};
        #pragma unroll
        for (int r = 0; r < 4; r++)
            #pragma unroll
            for (int e = 0; e < 4; e++)
                oacc[r][e] = fmaf(aa[r], va[e], oacc[r][e]);
    }
    __syncthreads();

    #pragma unroll
    for (int r = 0; r < 4; r++) {
        int i = ti * 4 + r;
        float zr = skp[i];
        size_t base = ((size_t)(b * SS + c * CC + i)) * DD + h * DHH + tj * 4;
        #pragma unroll
        for (int e = 0; e < 4; e++) {
            float o = oacc[r][e] * zr;
            __nv_bfloat16 hh, ll;
            split_bf(o, hh, ll);
            g_ab_h[base + e] = hh;
            g_ab_l[base + e] = ll;
        }
    }
}

// ---------------- LayerNorm (+ residual, + optional bf16 split out) ----------------
__global__ void ln_kernel(const float* __restrict__ x, const float* __restrict__ add,
                          const float* __restrict__ gamma, const float* __restrict__ beta,
                          float* __restrict__ out,
                          __nv_bfloat16* __restrict__ oh, __nv_bfloat16* __restrict__ ol) {
    __shared__ float rs[4], rq[4];
    int row = blockIdx.x, tid = threadIdx.x;
    float4 v = ((const float4*)(x + (size_t)row * DD))[tid];
    if (add) {
        float4 a = ((const float4*)(add + (size_t)row * DD))[tid];
        v.x += a.x; v.y += a.y; v.z += a.z; v.w += a.w;
    }
    float s = v.x + v.y + v.z + v.w;
    float q = v.x*v.x + v.y*v.y + v.z*v.z + v.w*v.w;
    #pragma unroll
    for (int off = 16; off; off >>= 1) {
        s += __shfl_xor_sync(0xffffffffu, s, off);
        q += __shfl_xor_sync(0xffffffffu, q, off);
    }
    if ((tid & 31) == 0) { rs[tid >> 5] = s; rq[tid >> 5] = q; }
    __syncthreads();
    s = rs[0] + rs[1] + rs[2] + rs[3];
    q = rq[0] + rq[1] + rq[2] + rq[3];
    float mu   = s * (1.f / DD);
    float var  = q * (1.f / DD) - mu * mu;
    float rstd = rsqrtf(var + 1e-5f);
    float4 g  = ((const float4*)gamma)[tid];
    float4 bt = ((const float4*)beta)[tid];
    float4 o;
    o.x = (v.x - mu) * rstd * g.x + bt.x;
    o.y = (v.y - mu) * rstd * g.y + bt.y;
    o.z = (v.z - mu) * rstd * g.z + bt.z;
    o.w = (v.w - mu) * rstd * g.w + bt.w;
    ((float4*)(out + (size_t)row * DD))[tid] = o;
    if (oh) {
        size_t e0 = (size_t)row * DD + tid * 4;
        float vv[4] = {o.x, o.y, o.z, o.w};
        #pragma unroll
        for (int j = 0; j < 4; j++) split_bf(vv[j], oh[e0+j], ol[e0+j]);
    }
}

// ---------------- launch --------------------------------------------------------
extern "C" void kernel_launch(void* const* d_in, const int* in_sizes, int n_in,
                              void* d_out, int out_size) {
    (void)in_sizes; (void)n_in; (void)out_size;
    const int*   x   = (const int*)  d_in[0];
    const float* emb = (const float*)d_in[1];
    const float* pe  = (const float*)d_in[2];
    const float* Wq  = (const float*)d_in[3];
    const float* bq  = (const float*)d_in[4];
    const float* Wk  = (const float*)d_in[5];
    const float* bk  = (const float*)d_in[6];
    const float* Wv  = (const float*)d_in[7];
    const float* bv  = (const float*)d_in[8];
    const float* Wo  = (const float*)d_in[9];
    const float* bo  = (const float*)d_in[10];
    const float* W1  = (const float*)d_in[11];
    const float* b1  = (const float*)d_in[12];
    const float* W2  = (const float*)d_in[13];
    const float* b2  = (const float*)d_in[14];
    const float* g1  = (const float*)d_in[15];
    const float* be1 = (const float*)d_in[16];
    const float* g2  = (const float*)d_in[17];
    const float* be2 = (const float*)d_in[18];
    const float* gf  = (const float*)d_in[19];
    const float* bf  = (const float*)d_in[20];

    float *h, *q, *kk, *vv;
    cudaGetSymbolAddress((void**)&h, g_h);
    cudaGetSymbolAddress((void**)&q, g_q);
    cudaGetSymbolAddress((void**)&kk, g_k);
    cudaGetSymbolAddress((void**)&vv, g_v);
    __nv_bfloat16 *hb_h, *hb_l, *ab_h, *ab_l, *tb_h, *tb_l;
    cudaGetSymbolAddress((void**)&hb_h, g_hb_h);
    cudaGetSymbolAddress((void**)&hb_l, g_hb_l);
    cudaGetSymbolAddress((void**)&ab_h, g_ab_h);
    cudaGetSymbolAddress((void**)&ab_l, g_ab_l);
    cudaGetSymbolAddress((void**)&tb_h, g_tb_h);
    cudaGetSymbolAddress((void**)&tb_l, g_tb_l);
    __nv_bfloat16 *wqh, *wql, *wkh, *wkl, *wvh, *wvl, *woh, *wol, *w1h, *w1l, *w2h, *w2l;
    cudaGetSymbolAddress((void**)&wqh, g_wq_h); cudaGetSymbolAddress((void**)&wql, g_wq_l);
    cudaGetSymbolAddress((void**)&wkh, g_wk_h); cudaGetSymbolAddress((void**)&wkl, g_wk_l);
    cudaGetSymbolAddress((void**)&wvh, g_wv_h); cudaGetSymbolAddress((void**)&wvl, g_wv_l);
    cudaGetSymbolAddress((void**)&woh, g_wo_h); cudaGetSymbolAddress((void**)&wol, g_wo_l);
    cudaGetSymbolAddress((void**)&w1h, g_w1_h); cudaGetSymbolAddress((void**)&w1l, g_w1_l);
    cudaGetSymbolAddress((void**)&w2h, g_w2_h); cudaGetSymbolAddress((void**)&w2l, g_w2_l);

    cudaFuncSetAttribute(att_out_kernel,
                         cudaFuncAttributeMaxDynamicSharedMemorySize, SM3_BYTES);
    cudaFuncSetAttribute(gemm_mma<0,0>,
                         cudaFuncAttributeMaxDynamicSharedMemorySize, GM_SMEM_BYTES);
    cudaFuncSetAttribute(gemm_mma<1,1>,
                         cudaFuncAttributeMaxDynamicSharedMemorySize, GM_SMEM_BYTES);

    len_kernel<<<BB, 256>>>(x);
    embed_kernel<<<(MM * (DD/4) + 255) / 256, 256>>>(x, emb, pe);

    // batched weight transpose+split: 24 matrices, one launch
    {
        WtcArgs wa = {};
        int idx = 0;
        for (int l = 0; l < NLL; l++) {
            size_t wo = (size_t)l * DD * DD;
            size_t wf = (size_t)l * DD * FF;
            wa.src[idx] = Wq + wo; wa.oh[idx] = wqh + wo; wa.ol[idx] = wql + wo; wa.K[idx] = DD; wa.N[idx] = DD; idx++;
            wa.src[idx] = Wk + wo; wa.oh[idx] = wkh + wo; wa.ol[idx] = wkl + wo; wa.K[idx] = DD; wa.N[idx] = DD; idx++;
            wa.src[idx] = Wv + wo; wa.oh[idx] = wvh + wo; wa.ol[idx] = wvl + wo; wa.K[idx] = DD; wa.N[idx] = DD; idx++;
            wa.src[idx] = Wo + wo; wa.oh[idx] = woh + wo; wa.ol[idx] = wol + wo; wa.K[idx] = DD; wa.N[idx] = DD; idx++;
            wa.src[idx] = W1 + wf; wa.oh[idx] = w1h + wf; wa.ol[idx] = w1l + wf; wa.K[idx] = DD; wa.N[idx] = FF; idx++;
            wa.src[idx] = W2 + wf; wa.oh[idx] = w2h + wf; wa.ol[idx] = w2l + wf; wa.K[idx] = FF; wa.N[idx] = DD; idx++;
        }
        wtc_all_kernel<<<dim3(FF/32, FF/32, 24), dim3(32, 8)>>>(wa);
    }

    for (int l = 0; l < NLL; l++) {
        size_t wo   = (size_t)l * DD * DD;
        size_t wf   = (size_t)l * DD * FF;
        size_t boff = (size_t)l * DD;

        // QKV fused
        GTArgs ga = {};
        ga.Ah = hb_h; ga.Al = hb_l; ga.N = DD; ga.K = DD;
        ga.Bh[0] = wqh + wo; ga.Bl[0] = wql + wo;
        ga.Bh[1] = wkh + wo; ga.Bl[1] = wkl + wo;
        ga.Bh[2] = wvh + wo; ga.Bl[2] = wvl + wo;
        ga.bias[0] = bq + boff; ga.bias[1] = bk + boff; ga.bias[2] = bv + boff;
        ga.outf[0] = q; ga.outf[1] = kk; ga.outf[2] = vv;
        gemm_mma<0,0><<<dim3(DD/128, MM/128, 3), 256, GM_SMEM_BYTES>>>(ga);

        att_sums_kernel<<<dim3(NCC, BHH), 256>>>();
        att_scan_kernel<<<BHH, 256>>>();
        att_out_kernel<<<dim3(NCC, BHH), 256, SM3_BYTES>>>();

        // O proj
        GTArgs go = {};
        go.Ah = ab_h; go.Al = ab_l; go.N = DD; go.K = DD;
        go.Bh[0] = woh + wo; go.Bl[0] = wol + wo;
        go.bias[0] = bo + boff; go.outf[0] = q;
        gemm_mma<0,0><<<dim3(DD/128, MM/128, 1), 256, GM_SMEM_BYTES>>>(go);

        ln_kernel<<<MM, 128>>>(h, q, g1 + boff, be1 + boff, h, hb_h, hb_l);

        // FFN1 (relu, bf16-split output)
        GTArgs g1a = {};
        g1a.Ah = hb_h; g1a.Al = hb_l; g1a.N = FF; g1a.K = DD;
        g1a.Bh[0] = w1h + wf; g1a.Bl[0] = w1l + wf;
        g1a.bias[0] = b1 + (size_t)l * FF;
        g1a.outh[0] = tb_h; g1a.outl[0] = tb_l;
        gemm_mma<1,1><<<dim3(FF/128, MM/128, 1), 256, GM_SMEM_BYTES>>>(g1a);

        // FFN2
        GTArgs g2a = {};
        g2a.Ah = tb_h; g2a.Al = tb_l; g2a.N = DD; g2a.K = FF;
        g2a.Bh[0] = w2h + wf; g2a.Bl[0] = w2l + wf;
        g2a.bias[0] = b2 + boff; g2a.outf[0] = q;
        gemm_mma<0,0><<<dim3(DD/128, MM/128, 1), 256, GM_SMEM_BYTES>>>(g2a);

        ln_kernel<<<MM, 128>>>(h, q, g2 + boff, be2 + boff, h, hb_h, hb_l);
    }

    ln_kernel<<<MM, 128>>>(h, nullptr, gf, bf, (float*)d_out, nullptr, nullptr);
}

// round 6
// speedup vs baseline: 2.1487x; 1.1026x over previous
#include <cuda_runtime.h>
#include <cuda_bf16.h>
#include <cstdint>

// ---------------- problem constants ----------------
#define BB  4
#define SS  2048
#define DD  512
#define HH  8
#define DHH 64
#define FF  2048
#define NLL 4
#define MM  (BB*SS)      // 8192 rows
#define CC  64           // attention chunk length
#define NCC (SS/CC)      // 32 chunks
#define BHH (BB*HH)      // 32 (b,h) pairs

__device__ __forceinline__ uint32_t smem_u32(const void* p) {
    uint32_t a;
    asm("{ .reg .u64 t; cvta.to.shared.u64 t, %1; cvt.u32.u64 %0, t; }" : "=r"(a) : "l"(p));
    return a;
}

// ---------------- scratch (device globals; no allocs allowed) ----------------
__device__ float g_h[MM*DD];
__device__ float g_q[MM*DD];
__device__ float g_k[MM*DD];
__device__ float g_v[MM*DD];
__device__ float g_S[(size_t)BHH*NCC*DHH*DHH];
__device__ float g_ks[BHH*NCC*DHH];
__device__ int   g_len[BB];

__device__ __align__(16) __nv_bfloat16 g_hb_h[MM*DD], g_hb_l[MM*DD];
__device__ __align__(16) __nv_bfloat16 g_ab_h[MM*DD], g_ab_l[MM*DD];
__device__ __align__(16) __nv_bfloat16 g_tb_h[(size_t)MM*FF], g_tb_l[(size_t)MM*FF];

__device__ __align__(16) __nv_bfloat16 g_wq_h[NLL*DD*DD], g_wq_l[NLL*DD*DD];
__device__ __align__(16) __nv_bfloat16 g_wk_h[NLL*DD*DD], g_wk_l[NLL*DD*DD];
__device__ __align__(16) __nv_bfloat16 g_wv_h[NLL*DD*DD], g_wv_l[NLL*DD*DD];
__device__ __align__(16) __nv_bfloat16 g_wo_h[NLL*DD*DD], g_wo_l[NLL*DD*DD];
__device__ __align__(16) __nv_bfloat16 g_w1_h[NLL*FF*DD], g_w1_l[NLL*FF*DD];
__device__ __align__(16) __nv_bfloat16 g_w2_h[NLL*DD*FF], g_w2_l[NLL*DD*FF];

__device__ __forceinline__ float phi_f(float u) { return u > 0.f ? u + 1.f : __expf(u); }

__device__ __forceinline__ void split_bf(float x, __nv_bfloat16& h, __nv_bfloat16& l) {
    h = __float2bfloat16(x);
    l = __float2bfloat16(x - __bfloat162float(h));
}

// ---------------- lengths ----------------
__global__ void len_kernel(const int* __restrict__ x) {
    __shared__ int red[256];
    int b = blockIdx.x, tid = threadIdx.x;
    int cnt = 0;
    for (int s = tid; s < SS; s += 256) cnt += (x[b*SS + s] != 0);
    red[tid] = cnt; __syncthreads();
    for (int off = 128; off; off >>= 1) {
        if (tid < off) red[tid] += red[tid + off];
        __syncthreads();
    }
    if (tid == 0) g_len[b] = red[0];
}

// ---------------- embedding + positional (+ bf16 split) ----------------
__global__ void embed_kernel(const int* __restrict__ x,
                             const float* __restrict__ emb,
                             const float* __restrict__ pe) {
    int idx = blockIdx.x * 256 + threadIdx.x;
    if (idx >= MM * (DD/4)) return;
    int i  = idx >> 7;
    int d4 = idx & 127;
    int s  = i & (SS - 1);
    int tok = x[i];
    float4 e = ((const float4*)emb)[(size_t)tok * (DD/4) + d4];
    float4 p = ((const float4*)pe)[(size_t)s * (DD/4) + d4];
    float4 o;
    o.x = e.x + p.x; o.y = e.y + p.y; o.z = e.z + p.z; o.w = e.w + p.w;
    ((float4*)g_h)[idx] = o;
    size_t e0 = (size_t)idx * 4;
    float vv[4] = {o.x, o.y, o.z, o.w};
    #pragma unroll
    for (int j = 0; j < 4; j++) split_bf(vv[j], g_hb_h[e0+j], g_hb_l[e0+j]);
}

// ---------------- batched weight transpose + split (24 matrices, one launch) ----
struct WtcArgs {
    const float* src[24];
    __nv_bfloat16* oh[24];
    __nv_bfloat16* ol[24];
    int K[24], N[24];
};
__global__ void wtc_all_kernel(WtcArgs p) {
    __shared__ float t[32][33];
    int m = blockIdx.z;
    int K = p.K[m], N = p.N[m];
    int n0 = blockIdx.x * 32, k0 = blockIdx.y * 32;
    if (n0 >= N || k0 >= K) return;
    const float* W = p.src[m];
    __nv_bfloat16 *oh = p.oh[m], *ol = p.ol[m];
    int tx = threadIdx.x, ty = threadIdx.y;   // 32x8
    #pragma unroll
    for (int i = 0; i < 32; i += 8)
        t[ty + i][tx] = W[(size_t)(k0 + ty + i) * N + n0 + tx];
    __syncthreads();
    #pragma unroll
    for (int i = 0; i < 32; i += 8) {
        float v = t[tx][ty + i];
        size_t o = (size_t)(n0 + ty + i) * K + k0 + tx;
        split_bf(v, oh[o], ol[o]);
    }
}

// ---------------- split-bf16 GEMM via warp mma.sync ----------------
// C[M,N] = A[M,K] * B[N,K]^T + bias ; A,B as bf16 (hi,lo) pairs, K-major rows.
// Block 128x128, BK=32, 256 thr, warp tile 64x32.
// 3-stage cp.async pipeline, swizzled 64B-pitch smem (no padding),
// single __syncthreads per iteration, 2 CTAs/SM.
struct GTArgs {
    const __nv_bfloat16 *Ah, *Al;
    const __nv_bfloat16 *Bh[3], *Bl[3];
    const float* bias[3];
    float* outf[3];
    __nv_bfloat16 *outh[3], *outl[3];
    int N, K;
};

#define STAGES 3
#define TILE_BYTES 8192                    // 128 rows x 64B (swizzled)
#define STAGE_BYTES (4*TILE_BYTES)         // Ah,Al,Bh,Bl = 32768
#define GM_SMEM_BYTES (STAGES*STAGE_BYTES) // 98304

// swizzled in-tile byte offset for (row, 16B-chunk c): row*64 + (c ^ ((row>>1)&3))*16
__device__ __forceinline__ uint32_t swz(int row, int c) {
    return (uint32_t)(row * 64 + ((c ^ ((row >> 1) & 3)) << 4));
}

#define MMA_BF16(d, a, b) \
    asm volatile("mma.sync.aligned.m16n8k16.row.col.f32.bf16.bf16.f32 " \
        "{%0,%1,%2,%3}, {%4,%5,%6,%7}, {%8,%9}, {%0,%1,%2,%3};" \
        : "+f"((d)[0]), "+f"((d)[1]), "+f"((d)[2]), "+f"((d)[3]) \
        : "r"((a)[0]), "r"((a)[1]), "r"((a)[2]), "r"((a)[3]), "r"((b)[0]), "r"((b)[1]))

#define LDMX4(r, addr) \
    asm volatile("ldmatrix.sync.aligned.m8n8.x4.shared.b16 {%0,%1,%2,%3}, [%4];" \
        : "=r"((r)[0]), "=r"((r)[1]), "=r"((r)[2]), "=r"((r)[3]) : "r"(addr))

template<int RELU, int OUTBF>
__global__ void __launch_bounds__(256, 2) gemm_mma(GTArgs p) {
    extern __shared__ __nv_bfloat16 sm[];
    const uint32_t sbase = smem_u32(sm);
    const int z = blockIdx.z;
    const int N = p.N, K = p.K;
    const int tid = threadIdx.x;
    const int m0 = blockIdx.y * 128, n0 = blockIdx.x * 128;

    // ---- loader: each thread owns (row rA, chunk chk) in every tile; 8 x 16B per stage
    const int rA  = tid >> 2;          // 0..63
    const int chk = tid & 3;           // 16B chunk within 64B row
    const __nv_bfloat16* gp[4];
    gp[0] = p.Ah    + (size_t)(m0 + rA) * K + chk * 8;
    gp[1] = p.Al    + (size_t)(m0 + rA) * K + chk * 8;
    gp[2] = p.Bh[z] + (size_t)(n0 + rA) * K + chk * 8;
    gp[3] = p.Bl[z] + (size_t)(n0 + rA) * K + chk * 8;
    const uint32_t s0 = swz(rA, chk);  // rows rA and rA+64 share swizzle bits
    const size_t K64 = (size_t)K << 6; // 64 rows of stride K

    const int wid = tid >> 5, lane = tid & 31;
    const int wm = (wid & 1) * 64;
    const int wn = (wid >> 1) * 32;

    // ---- fragment base offsets (swizzled); kh step = XOR 0x20 ----
    const int rowa = wm + (lane & 15);
    const uint32_t aSw = swz(rowa, (lane >> 4) & 1);
    const int rowb = wn + (lane & 7) + ((lane >> 4) << 3);
    const uint32_t bSw = (uint32_t)(2 * TILE_BYTES) + swz(rowb, (lane >> 3) & 1);

    float acc[4][4][4];
    #pragma unroll
    for (int a = 0; a < 4; a++)
        #pragma unroll
        for (int b = 0; b < 4; b++)
            #pragma unroll
            for (int c = 0; c < 4; c++) acc[a][b][c] = 0.f;

    const int nt = K >> 5;

    auto load_stage = [&](int slot, int k0) {
        uint32_t sb = sbase + (uint32_t)slot * STAGE_BYTES + s0;
        #pragma unroll
        for (int op = 0; op < 4; op++)
            #pragma unroll
            for (int j = 0; j < 2; j++) {
                asm volatile("cp.async.cg.shared.global [%0], [%1], 16;"
                    :: "r"(sb + (uint32_t)(op * TILE_BYTES + j * 4096)),
                       "l"(gp[op] + (j ? K64 : 0) + k0));
            }
        asm volatile("cp.async.commit_group;" ::: "memory");
    };

    // prologue: 2 stages in flight
    load_stage(0, 0);
    load_stage(1, 32);

    int cslot = 0, lslot = 2;
    for (int t = 0; t < nt; t++) {
        asm volatile("cp.async.wait_group 1;" ::: "memory");
        __syncthreads();
        if (t + 2 < nt) load_stage(lslot, (t + 2) * 32);
        else asm volatile("cp.async.commit_group;" ::: "memory");
        if (++lslot == STAGES) lslot = 0;

        const uint32_t stg = sbase + (uint32_t)cslot * STAGE_BYTES;
        if (++cslot == STAGES) cslot = 0;
        #pragma unroll
        for (int kh = 0; kh < 2; kh++) {
            const uint32_t kx = (uint32_t)(kh * 0x20);   // chunk+2 under swizzle
            uint32_t afr[2][4][4];
            #pragma unroll
            for (int sp = 0; sp < 2; sp++)
                #pragma unroll
                for (int mt = 0; mt < 4; mt++)
                    LDMX4(afr[sp][mt],
                          stg + ((aSw + (uint32_t)(sp * TILE_BYTES + mt * 1024)) ^ kx));
            uint32_t bfr[2][2][4];
            #pragma unroll
            for (int sp = 0; sp < 2; sp++)
                #pragma unroll
                for (int ng = 0; ng < 2; ng++)
                    LDMX4(bfr[sp][ng],
                          stg + ((bSw + (uint32_t)(sp * TILE_BYTES + ng * 1024)) ^ kx));
            #pragma unroll
            for (int mt = 0; mt < 4; mt++)
                #pragma unroll
                for (int nn = 0; nn < 4; nn++) {
                    int ng = nn >> 1, hb = (nn & 1) * 2;
                    uint32_t b0h[2] = { bfr[0][ng][hb], bfr[0][ng][hb+1] };
                    uint32_t b0l[2] = { bfr[1][ng][hb], bfr[1][ng][hb+1] };
                    MMA_BF16(acc[mt][nn], afr[0][mt], b0h);  // Ah*Bh
                    MMA_BF16(acc[mt][nn], afr[0][mt], b0l);  // Ah*Bl
                    MMA_BF16(acc[mt][nn], afr[1][mt], b0h);  // Al*Bh
                }
        }
    }

    // ---- epilogue ----
    const float* bias = p.bias[z];
    #pragma unroll
    for (int nn = 0; nn < 4; nn++) {
        int cn = n0 + wn + nn * 8 + (lane & 3) * 2;
        float b0v = bias[cn], b1v = bias[cn + 1];
        #pragma unroll
        for (int mt = 0; mt < 4; mt++) {
            int r0 = m0 + wm + mt * 16 + (lane >> 2);
            #pragma unroll
            for (int half = 0; half < 2; half++) {
                int r = r0 + half * 8;
                float v0 = acc[mt][nn][half*2 + 0] + b0v;
                float v1 = acc[mt][nn][half*2 + 1] + b1v;
                if (RELU) { v0 = fmaxf(v0, 0.f); v1 = fmaxf(v1, 0.f); }
                if (OUTBF) {
                    __nv_bfloat16 h0, l0, h1, l1;
                    split_bf(v0, h0, l0);
                    split_bf(v1, h1, l1);
                    __nv_bfloat162 hp; hp.x = h0; hp.y = h1;
                    __nv_bfloat162 lp; lp.x = l0; lp.y = l1;
                    *(__nv_bfloat162*)(p.outh[z] + (size_t)r * N + cn) = hp;
                    *(__nv_bfloat162*)(p.outl[z] + (size_t)r * N + cn) = lp;
                } else {
                    float2 o; o.x = v0; o.y = v1;
                    *(float2*)(p.outf[z] + (size_t)r * N + cn) = o;
                }
            }
        }
    }
}

// ---------------- attention pass 1: per-chunk  S_c = phiK^T V,  ks_c = sum phiK
__global__ void __launch_bounds__(256) att_sums_kernel() {
    __shared__ float sK[CC][68];
    __shared__ float sV[CC][68];
    int c = blockIdx.x, bh = blockIdx.y;
    int b = bh >> 3, h = bh & 7;
    int tid = threadIdx.x;
    int len = g_len[b];
    for (int idx = tid; idx < CC * DHH; idx += 256) {
        int j = idx >> 6, d = idx & 63;
        int srow = c * CC + j;
        size_t g = ((size_t)(b * SS + srow)) * DD + h * DHH + d;
        float kv = g_k[g];
        sK[j][d] = (srow < len) ? phi_f(kv) : 0.f;
        sV[j][d] = g_v[g];
    }
    __syncthreads();
    int ti = tid & 15, tj = tid >> 4;
    float acc[4][4];
    #pragma unroll
    for (int r = 0; r < 4; r++)
        #pragma unroll
        for (int e = 0; e < 4; e++) acc[r][e] = 0.f;
    #pragma unroll 8
    for (int j = 0; j < CC; j++) {
        float4 kf = *(const float4*)&sK[j][ti*4];
        float4 vf = *(const float4*)&sV[j][tj*4];
        float ka[4] = {kf.x,kf.y,kf.z,kf.w};
        float va[4] = {vf.x,vf.y,vf.z,vf.w};
        #pragma unroll
        for (int r = 0; r < 4; r++)
            #pragma unroll
            for (int e = 0; e < 4; e++)
                acc[r][e] = fmaf(ka[r], va[e], acc[r][e]);
    }
    float* So = &g_S[((size_t)(bh * NCC + c)) * (DHH * DHH)];
    #pragma unroll
    for (int r = 0; r < 4; r++) {
        int d = ti * 4 + r;
        float4 o; o.x = acc[r][0]; o.y = acc[r][1]; o.z = acc[r][2]; o.w = acc[r][3];
        *(float4*)&So[d * DHH + tj * 4] = o;
    }
    if (tid < DHH) {
        float s = 0.f;
        #pragma unroll 8
        for (int j = 0; j < CC; j++) s += sK[j][tid];
        g_ks[(bh * NCC + c) * DHH + tid] = s;
    }
}

// ---------------- attention pass 2: exclusive prefix over chunks ----------------
__global__ void __launch_bounds__(256) att_scan_kernel() {
    int bh = blockIdx.x, tid = threadIdx.x;
    float run[16];
    #pragma unroll
    for (int r = 0; r < 16; r++) run[r] = 0.f;
    for (int c = 0; c < NCC; c++) {
        float* p = &g_S[((size_t)(bh * NCC + c)) * (DHH*DHH) + tid * 16];
        #pragma unroll
        for (int r4 = 0; r4 < 4; r4++) {
            float4 tv = ((const float4*)p)[r4];
            float4 rv;
            rv.x = run[r4*4+0]; rv.y = run[r4*4+1];
            rv.z = run[r4*4+2]; rv.w = run[r4*4+3];
            ((float4*)p)[r4] = rv;
            run[r4*4+0] += tv.x; run[r4*4+1] += tv.y;
            run[r4*4+2] += tv.z; run[r4*4+3] += tv.w;
        }
    }
    if (tid < DHH) {
        float rk = 0.f;
        for (int c = 0; c < NCC; c++) {
            float* kp = &g_ks[(bh * NCC + c) * DHH + tid];
            float t = *kp; *kp = rk; rk += t;
        }
    }
}

// ---------------- attention pass 3 ----------------
#define SM3_FLOATS (3*CC*68 + DHH)
#define SM3_BYTES  (SM3_FLOATS * 4)
__global__ void __launch_bounds__(256) att_out_kernel() {
    extern __shared__ float smf[];
    float* sQ  = smf;
    float* sKV = smf + CC*68;
    float* sSA = smf + 2*CC*68;
    float* skp = smf + 3*CC*68;

    int c = blockIdx.x, bh = blockIdx.y;
    int b = bh >> 3, h = bh & 7;
    int tid = threadIdx.x;
    int len = g_len[b];

    for (int idx = tid; idx < CC * DHH; idx += 256) {
        int r = idx >> 6, d = idx & 63;
        int srow = c * CC + r;
        size_t g = ((size_t)(b * SS + srow)) * DD + h * DHH + d;
        sQ[d*68 + r]  = phi_f(g_q[g]);
        float kv = g_k[g];
        sKV[d*68 + r] = (srow < len) ? phi_f(kv) : 0.f;
        sSA[r*68 + d] = g_S[((size_t)(bh * NCC + c)) * (DHH*DHH) + idx];
    }
    if (tid < DHH) skp[tid] = g_ks[(bh * NCC + c) * DHH + tid];
    __syncthreads();

    int ti = tid & 15, tj = tid >> 4;

    float zi = 0.f;
    if (tid < DHH) {
        #pragma unroll 8
        for (int d = 0; d < DHH; d++) zi += sQ[d*68 + tid] * skp[d];
    }

    float oacc[4][4], aacc[4][4];
    #pragma unroll
    for (int r = 0; r < 4; r++)
        #pragma unroll
        for (int e = 0; e < 4; e++) { oacc[r][e] = 0.f; aacc[r][e] = 0.f; }
    #pragma unroll 4
    for (int d = 0; d < DHH; d++) {
        float4 aq = *(const float4*)&sQ [d*68 + ti*4];
        float4 bs = *(const float4*)&sSA[d*68 + tj*4];
        float4 bk = *(const float4*)&sKV[d*68 + tj*4];
        float qa[4] = {aq.x,aq.y,aq.z,aq.w};
        float sa[4] = {bs.x,bs.y,bs.z,bs.w};
        float ka[4] = {bk.x,bk.y,bk.z,bk.w};
        #pragma unroll
        for (int r = 0; r < 4; r++)
            #pragma unroll
            for (int e = 0; e < 4; e++) {
                oacc[r][e] = fmaf(qa[r], sa[e], oacc[r][e]);
                aacc[r][e] = fmaf(qa[r], ka[e], aacc[r][e]);
            }
    }
    __syncthreads();

    #pragma unroll
    for (int r = 0; r < 4; r++)
        #pragma unroll
        for (int e = 0; e < 4; e++) {
            int i = ti * 4 + r, j = tj * 4 + e;
            sSA[j*68 + i] = (j <= i) ? aacc[r][e] : 0.f;
        }
    for (int idx = tid; idx < CC * DHH; idx += 256) {
        int r = idx >> 6, e = idx & 63;
        sKV[r*68 + e] = g_v[((size_t)(b * SS + c * CC + r)) * DD + h * DHH + e];
    }
    __syncthreads();

    if (tid < DHH) {
        float z = zi;
        #pragma unroll 8
        for (int j = 0; j < CC; j++) z += sSA[j*68 + tid];
        skp[tid] = 1.f / (z + 1e-6f);
    }

    #pragma unroll 4
    for (int j = 0; j < CC; j++) {
        float4 aj = *(const float4*)&sSA[j*68 + ti*4];
        float4 ve = *(const float4*)&sKV[j*68 + tj*4];
        float aa[4] = {aj.x,aj.y,aj.z,aj.w};
        float va[4] = {ve.x,ve.y,ve.z,ve.w};
        #pragma unroll
        for (int r = 0; r < 4; r++)
            #pragma unroll
            for (int e = 0; e < 4; e++)
                oacc[r][e] = fmaf(aa[r], va[e], oacc[r][e]);
    }
    __syncthreads();

    #pragma unroll
    for (int r = 0; r < 4; r++) {
        int i = ti * 4 + r;
        float zr = skp[i];
        size_t base = ((size_t)(b * SS + c * CC + i)) * DD + h * DHH + tj * 4;
        #pragma unroll
        for (int e = 0; e < 4; e++) {
            float o = oacc[r][e] * zr;
            __nv_bfloat16 hh, ll;
            split_bf(o, hh, ll);
            g_ab_h[base + e] = hh;
            g_ab_l[base + e] = ll;
        }
    }
}

// ---------------- LayerNorm (+ residual, + optional bf16 split out) ----------------
__global__ void ln_kernel(const float* __restrict__ x, const float* __restrict__ add,
                          const float* __restrict__ gamma, const float* __restrict__ beta,
                          float* __restrict__ out,
                          __nv_bfloat16* __restrict__ oh, __nv_bfloat16* __restrict__ ol) {
    __shared__ float rs[4], rq[4];
    int row = blockIdx.x, tid = threadIdx.x;
    float4 v = ((const float4*)(x + (size_t)row * DD))[tid];
    if (add) {
        float4 a = ((const float4*)(add + (size_t)row * DD))[tid];
        v.x += a.x; v.y += a.y; v.z += a.z; v.w += a.w;
    }
    float s = v.x + v.y + v.z + v.w;
    float q = v.x*v.x + v.y*v.y + v.z*v.z + v.w*v.w;
    #pragma unroll
    for (int off = 16; off; off >>= 1) {
        s += __shfl_xor_sync(0xffffffffu, s, off);
        q += __shfl_xor_sync(0xffffffffu, q, off);
    }
    if ((tid & 31) == 0) { rs[tid >> 5] = s; rq[tid >> 5] = q; }
    __syncthreads();
    s = rs[0] + rs[1] + rs[2] + rs[3];
    q = rq[0] + rq[1] + rq[2] + rq[3];
    float mu   = s * (1.f / DD);
    float var  = q * (1.f / DD) - mu * mu;
    float rstd = rsqrtf(var + 1e-5f);
    float4 g  = ((const float4*)gamma)[tid];
    float4 bt = ((const float4*)beta)[tid];
    float4 o;
    o.x = (v.x - mu) * rstd * g.x + bt.x;
    o.y = (v.y - mu) * rstd * g.y + bt.y;
    o.z = (v.z - mu) * rstd * g.z + bt.z;
    o.w = (v.w - mu) * rstd * g.w + bt.w;
    ((float4*)(out + (size_t)row * DD))[tid] = o;
    if (oh) {
        size_t e0 = (size_t)row * DD + tid * 4;
        float vv[4] = {o.x, o.y, o.z, o.w};
        #pragma unroll
        for (int j = 0; j < 4; j++) split_bf(vv[j], oh[e0+j], ol[e0+j]);
    }
}

// ---------------- launch --------------------------------------------------------
extern "C" void kernel_launch(void* const* d_in, const int* in_sizes, int n_in,
                              void* d_out, int out_size) {
    (void)in_sizes; (void)n_in; (void)out_size;
    const int*   x   = (const int*)  d_in[0];
    const float* emb = (const float*)d_in[1];
    const float* pe  = (const float*)d_in[2];
    const float* Wq  = (const float*)d_in[3];
    const float* bq  = (const float*)d_in[4];
    const float* Wk  = (const float*)d_in[5];
    const float* bk  = (const float*)d_in[6];
    const float* Wv  = (const float*)d_in[7];
    const float* bv  = (const float*)d_in[8];
    const float* Wo  = (const float*)d_in[9];
    const float* bo  = (const float*)d_in[10];
    const float* W1  = (const float*)d_in[11];
    const float* b1  = (const float*)d_in[12];
    const float* W2  = (const float*)d_in[13];
    const float* b2  = (const float*)d_in[14];
    const float* g1  = (const float*)d_in[15];
    const float* be1 = (const float*)d_in[16];
    const float* g2  = (const float*)d_in[17];
    const float* be2 = (const float*)d_in[18];
    const float* gf  = (const float*)d_in[19];
    const float* bf  = (const float*)d_in[20];

    float *h, *q, *kk, *vv;
    cudaGetSymbolAddress((void**)&h, g_h);
    cudaGetSymbolAddress((void**)&q, g_q);
    cudaGetSymbolAddress((void**)&kk, g_k);
    cudaGetSymbolAddress((void**)&vv, g_v);
    __nv_bfloat16 *hb_h, *hb_l, *ab_h, *ab_l, *tb_h, *tb_l;
    cudaGetSymbolAddress((void**)&hb_h, g_hb_h);
    cudaGetSymbolAddress((void**)&hb_l, g_hb_l);
    cudaGetSymbolAddress((void**)&ab_h, g_ab_h);
    cudaGetSymbolAddress((void**)&ab_l, g_ab_l);
    cudaGetSymbolAddress((void**)&tb_h, g_tb_h);
    cudaGetSymbolAddress((void**)&tb_l, g_tb_l);
    __nv_bfloat16 *wqh, *wql, *wkh, *wkl, *wvh, *wvl, *woh, *wol, *w1h, *w1l, *w2h, *w2l;
    cudaGetSymbolAddress((void**)&wqh, g_wq_h); cudaGetSymbolAddress((void**)&wql, g_wq_l);
    cudaGetSymbolAddress((void**)&wkh, g_wk_h); cudaGetSymbolAddress((void**)&wkl, g_wk_l);
    cudaGetSymbolAddress((void**)&wvh, g_wv_h); cudaGetSymbolAddress((void**)&wvl, g_wv_l);
    cudaGetSymbolAddress((void**)&woh, g_wo_h); cudaGetSymbolAddress((void**)&wol, g_wo_l);
    cudaGetSymbolAddress((void**)&w1h, g_w1_h); cudaGetSymbolAddress((void**)&w1l, g_w1_l);
    cudaGetSymbolAddress((void**)&w2h, g_w2_h); cudaGetSymbolAddress((void**)&w2l, g_w2_l);

    cudaFuncSetAttribute(att_out_kernel,
                         cudaFuncAttributeMaxDynamicSharedMemorySize, SM3_BYTES);
    cudaFuncSetAttribute(gemm_mma<0,0>,
                         cudaFuncAttributeMaxDynamicSharedMemorySize, GM_SMEM_BYTES);
    cudaFuncSetAttribute(gemm_mma<1,1>,
                         cudaFuncAttributeMaxDynamicSharedMemorySize, GM_SMEM_BYTES);

    len_kernel<<<BB, 256>>>(x);
    embed_kernel<<<(MM * (DD/4) + 255) / 256, 256>>>(x, emb, pe);

    // batched weight transpose+split: 24 matrices, one launch
    {
        WtcArgs wa = {};
        int idx = 0;
        for (int l = 0; l < NLL; l++) {
            size_t wo = (size_t)l * DD * DD;
            size_t wf = (size_t)l * DD * FF;
            wa.src[idx] = Wq + wo; wa.oh[idx] = wqh + wo; wa.ol[idx] = wql + wo; wa.K[idx] = DD; wa.N[idx] = DD; idx++;
            wa.src[idx] = Wk + wo; wa.oh[idx] = wkh + wo; wa.ol[idx] = wkl + wo; wa.K[idx] = DD; wa.N[idx] = DD; idx++;
            wa.src[idx] = Wv + wo; wa.oh[idx] = wvh + wo; wa.ol[idx] = wvl + wo; wa.K[idx] = DD; wa.N[idx] = DD; idx++;
            wa.src[idx] = Wo + wo; wa.oh[idx] = woh + wo; wa.ol[idx] = wol + wo; wa.K[idx] = DD; wa.N[idx] = DD; idx++;
            wa.src[idx] = W1 + wf; wa.oh[idx] = w1h + wf; wa.ol[idx] = w1l + wf; wa.K[idx] = DD; wa.N[idx] = FF; idx++;
            wa.src[idx] = W2 + wf; wa.oh[idx] = w2h + wf; wa.ol[idx] = w2l + wf; wa.K[idx] = FF; wa.N[idx] = DD; idx++;
        }
        wtc_all_kernel<<<dim3(FF/32, FF/32, 24), dim3(32, 8)>>>(wa);
    }

    for (int l = 0; l < NLL; l++) {
        size_t wo   = (size_t)l * DD * DD;
        size_t wf   = (size_t)l * DD * FF;
        size_t boff = (size_t)l * DD;

        // QKV fused
        GTArgs ga = {};
        ga.Ah = hb_h; ga.Al = hb_l; ga.N = DD; ga.K = DD;
        ga.Bh[0] = wqh + wo; ga.Bl[0] = wql + wo;
        ga.Bh[1] = wkh + wo; ga.Bl[1] = wkl + wo;
        ga.Bh[2] = wvh + wo; ga.Bl[2] = wvl + wo;
        ga.bias[0] = bq + boff; ga.bias[1] = bk + boff; ga.bias[2] = bv + boff;
        ga.outf[0] = q; ga.outf[1] = kk; ga.outf[2] = vv;
        gemm_mma<0,0><<<dim3(DD/128, MM/128, 3), 256, GM_SMEM_BYTES>>>(ga);

        att_sums_kernel<<<dim3(NCC, BHH), 256>>>();
        att_scan_kernel<<<BHH, 256>>>();
        att_out_kernel<<<dim3(NCC, BHH), 256, SM3_BYTES>>>();

        // O proj
        GTArgs go = {};
        go.Ah = ab_h; go.Al = ab_l; go.N = DD; go.K = DD;
        go.Bh[0] = woh + wo; go.Bl[0] = wol + wo;
        go.bias[0] = bo + boff; go.outf[0] = q;
        gemm_mma<0,0><<<dim3(DD/128, MM/128, 1), 256, GM_SMEM_BYTES>>>(go);

        ln_kernel<<<MM, 128>>>(h, q, g1 + boff, be1 + boff, h, hb_h, hb_l);

        // FFN1 (relu, bf16-split output)
        GTArgs g1a = {};
        g1a.Ah = hb_h; g1a.Al = hb_l; g1a.N = FF; g1a.K = DD;
        g1a.Bh[0] = w1h + wf; g1a.Bl[0] = w1l + wf;
        g1a.bias[0] = b1 + (size_t)l * FF;
        g1a.outh[0] = tb_h; g1a.outl[0] = tb_l;
        gemm_mma<1,1><<<dim3(FF/128, MM/128, 1), 256, GM_SMEM_BYTES>>>(g1a);

        // FFN2
        GTArgs g2a = {};
        g2a.Ah = tb_h; g2a.Al = tb_l; g2a.N = DD; g2a.K = FF;
        g2a.Bh[0] = w2h + wf; g2a.Bl[0] = w2l + wf;
        g2a.bias[0] = b2 + boff; g2a.outf[0] = q;
        gemm_mma<0,0><<<dim3(DD/128, MM/128, 1), 256, GM_SMEM_BYTES>>>(g2a);

        ln_kernel<<<MM, 128>>>(h, q, g2 + boff, be2 + boff, h, hb_h, hb_l);
    }

    ln_kernel<<<MM, 128>>>(h, nullptr, gf, bf, (float*)d_out, nullptr, nullptr);
}

// round 7
// speedup vs baseline: 2.3090x; 1.0746x over previous
#include <cuda_runtime.h>
#include <cuda_bf16.h>
#include <cstdint>

// ---------------- problem constants ----------------
#define BB  4
#define SS  2048
#define DD  512
#define HH  8
#define DHH 64
#define FF  2048
#define NLL 4
#define MM  (BB*SS)      // 8192 rows
#define CC  64           // attention chunk length
#define NCC (SS/CC)      // 32 chunks
#define BHH (BB*HH)      // 32 (b,h) pairs

__device__ __forceinline__ uint32_t smem_u32(const void* p) {
    uint32_t a;
    asm("{ .reg .u64 t; cvta.to.shared.u64 t, %1; cvt.u32.u64 %0, t; }" : "=r"(a) : "l"(p));
    return a;
}

// ---------------- scratch (device globals; no allocs allowed) ----------------
__device__ float g_h[MM*DD];
__device__ float g_q[MM*DD];
__device__ float g_k[MM*DD];
__device__ float g_v[MM*DD];
__device__ float g_S[(size_t)BHH*NCC*DHH*DHH];
__device__ float g_ks[BHH*NCC*DHH];
__device__ int   g_len[BB];

__device__ __align__(16) __nv_bfloat16 g_hb_h[MM*DD], g_hb_l[MM*DD];
__device__ __align__(16) __nv_bfloat16 g_ab_h[MM*DD], g_ab_l[MM*DD];
__device__ __align__(16) __nv_bfloat16 g_tb_h[(size_t)MM*FF], g_tb_l[(size_t)MM*FF];

__device__ __align__(16) __nv_bfloat16 g_wq_h[NLL*DD*DD], g_wq_l[NLL*DD*DD];
__device__ __align__(16) __nv_bfloat16 g_wk_h[NLL*DD*DD], g_wk_l[NLL*DD*DD];
__device__ __align__(16) __nv_bfloat16 g_wv_h[NLL*DD*DD], g_wv_l[NLL*DD*DD];
__device__ __align__(16) __nv_bfloat16 g_wo_h[NLL*DD*DD], g_wo_l[NLL*DD*DD];
__device__ __align__(16) __nv_bfloat16 g_w1_h[NLL*FF*DD], g_w1_l[NLL*FF*DD];
__device__ __align__(16) __nv_bfloat16 g_w2_h[NLL*DD*FF], g_w2_l[NLL*DD*FF];

__device__ __forceinline__ float phi_f(float u) { return u > 0.f ? u + 1.f : __expf(u); }

__device__ __forceinline__ void split_bf(float x, __nv_bfloat16& h, __nv_bfloat16& l) {
    h = __float2bfloat16(x);
    l = __float2bfloat16(x - __bfloat162float(h));
}

// ---------------- lengths ----------------
__global__ void len_kernel(const int* __restrict__ x) {
    __shared__ int red[256];
    int b = blockIdx.x, tid = threadIdx.x;
    int cnt = 0;
    for (int s = tid; s < SS; s += 256) cnt += (x[b*SS + s] != 0);
    red[tid] = cnt; __syncthreads();
    for (int off = 128; off; off >>= 1) {
        if (tid < off) red[tid] += red[tid + off];
        __syncthreads();
    }
    if (tid == 0) g_len[b] = red[0];
}

// ---------------- embedding + positional (+ bf16 split) ----------------
__global__ void embed_kernel(const int* __restrict__ x,
                             const float* __restrict__ emb,
                             const float* __restrict__ pe) {
    int idx = blockIdx.x * 256 + threadIdx.x;
    if (idx >= MM * (DD/4)) return;
    int i  = idx >> 7;
    int d4 = idx & 127;
    int s  = i & (SS - 1);
    int tok = x[i];
    float4 e = ((const float4*)emb)[(size_t)tok * (DD/4) + d4];
    float4 p = ((const float4*)pe)[(size_t)s * (DD/4) + d4];
    float4 o;
    o.x = e.x + p.x; o.y = e.y + p.y; o.z = e.z + p.z; o.w = e.w + p.w;
    ((float4*)g_h)[idx] = o;
    size_t e0 = (size_t)idx * 4;
    float vv[4] = {o.x, o.y, o.z, o.w};
    #pragma unroll
    for (int j = 0; j < 4; j++) split_bf(vv[j], g_hb_h[e0+j], g_hb_l[e0+j]);
}

// ---------------- batched weight transpose + split (24 matrices, one launch) ----
struct WtcArgs {
    const float* src[24];
    __nv_bfloat16* oh[24];
    __nv_bfloat16* ol[24];
    int K[24], N[24];
};
__global__ void wtc_all_kernel(WtcArgs p) {
    __shared__ float t[32][33];
    int m = blockIdx.z;
    int K = p.K[m], N = p.N[m];
    int n0 = blockIdx.x * 32, k0 = blockIdx.y * 32;
    if (n0 >= N || k0 >= K) return;
    const float* W = p.src[m];
    __nv_bfloat16 *oh = p.oh[m], *ol = p.ol[m];
    int tx = threadIdx.x, ty = threadIdx.y;   // 32x8
    #pragma unroll
    for (int i = 0; i < 32; i += 8)
        t[ty + i][tx] = W[(size_t)(k0 + ty + i) * N + n0 + tx];
    __syncthreads();
    #pragma unroll
    for (int i = 0; i < 32; i += 8) {
        float v = t[tx][ty + i];
        size_t o = (size_t)(n0 + ty + i) * K + k0 + tx;
        split_bf(v, oh[o], ol[o]);
    }
}

// ---------------- split-bf16 GEMM via warp mma.sync ----------------
// C[M,N] = A[M,K] * B[N,K]^T + bias ; A,B as bf16 (hi,lo) pairs, K-major rows.
// Block 128x128, BK=32, 256 thr, warp tile 64x32.
// 3-stage cp.async pipeline, swizzled 64B-pitch smem (no padding),
// single __syncthreads per iteration, 2 CTAs/SM.
struct GTArgs {
    const __nv_bfloat16 *Ah, *Al;
    const __nv_bfloat16 *Bh[3], *Bl[3];
    const float* bias[3];
    float* outf[3];
    __nv_bfloat16 *outh[3], *outl[3];
    int N, K;
};

#define STAGES 3
#define TILE_BYTES 8192                    // 128 rows x 64B (swizzled)
#define STAGE_BYTES (4*TILE_BYTES)         // Ah,Al,Bh,Bl = 32768
#define GM_SMEM_BYTES (STAGES*STAGE_BYTES) // 98304

// swizzled in-tile byte offset for (row, 16B-chunk c): row*64 + (c ^ ((row>>1)&3))*16
__device__ __forceinline__ uint32_t swz(int row, int c) {
    return (uint32_t)(row * 64 + ((c ^ ((row >> 1) & 3)) << 4));
}

#define MMA_BF16(d, a, b) \
    asm volatile("mma.sync.aligned.m16n8k16.row.col.f32.bf16.bf16.f32 " \
        "{%0,%1,%2,%3}, {%4,%5,%6,%7}, {%8,%9}, {%0,%1,%2,%3};" \
        : "+f"((d)[0]), "+f"((d)[1]), "+f"((d)[2]), "+f"((d)[3]) \
        : "r"((a)[0]), "r"((a)[1]), "r"((a)[2]), "r"((a)[3]), "r"((b)[0]), "r"((b)[1]))

#define LDMX4(r, addr) \
    asm volatile("ldmatrix.sync.aligned.m8n8.x4.shared.b16 {%0,%1,%2,%3}, [%4];" \
        : "=r"((r)[0]), "=r"((r)[1]), "=r"((r)[2]), "=r"((r)[3]) : "r"(addr))

template<int RELU, int OUTBF>
__global__ void __launch_bounds__(256, 2) gemm_mma(GTArgs p) {
    extern __shared__ __nv_bfloat16 sm[];
    const uint32_t sbase = smem_u32(sm);
    const int z = blockIdx.z;
    const int N = p.N, K = p.K;
    const int tid = threadIdx.x;
    const int m0 = blockIdx.y * 128, n0 = blockIdx.x * 128;

    // ---- loader: each thread owns (row rA, chunk chk) in every tile; 8 x 16B per stage
    const int rA  = tid >> 2;          // 0..63
    const int chk = tid & 3;           // 16B chunk within 64B row
    const __nv_bfloat16* gp[4];
    gp[0] = p.Ah    + (size_t)(m0 + rA) * K + chk * 8;
    gp[1] = p.Al    + (size_t)(m0 + rA) * K + chk * 8;
    gp[2] = p.Bh[z] + (size_t)(n0 + rA) * K + chk * 8;
    gp[3] = p.Bl[z] + (size_t)(n0 + rA) * K + chk * 8;
    const uint32_t s0 = swz(rA, chk);  // rows rA and rA+64 share swizzle bits
    const size_t K64 = (size_t)K << 6; // 64 rows of stride K

    const int wid = tid >> 5, lane = tid & 31;
    const int wm = (wid & 1) * 64;
    const int wn = (wid >> 1) * 32;

    // ---- fragment base offsets (swizzled); kh step = XOR 0x20 ----
    const int rowa = wm + (lane & 15);
    const uint32_t aSw = swz(rowa, (lane >> 4) & 1);
    const int rowb = wn + (lane & 7) + ((lane >> 4) << 3);
    const uint32_t bSw = (uint32_t)(2 * TILE_BYTES) + swz(rowb, (lane >> 3) & 1);

    float acc[4][4][4];
    #pragma unroll
    for (int a = 0; a < 4; a++)
        #pragma unroll
        for (int b = 0; b < 4; b++)
            #pragma unroll
            for (int c = 0; c < 4; c++) acc[a][b][c] = 0.f;

    const int nt = K >> 5;

    auto load_stage = [&](int slot, int k0) {
        uint32_t sb = sbase + (uint32_t)slot * STAGE_BYTES + s0;
        #pragma unroll
        for (int op = 0; op < 4; op++)
            #pragma unroll
            for (int j = 0; j < 2; j++) {
                asm volatile("cp.async.cg.shared.global [%0], [%1], 16;"
                    :: "r"(sb + (uint32_t)(op * TILE_BYTES + j * 4096)),
                       "l"(gp[op] + (j ? K64 : 0) + k0));
            }
        asm volatile("cp.async.commit_group;" ::: "memory");
    };

    // prologue: 2 stages in flight
    load_stage(0, 0);
    load_stage(1, 32);

    int cslot = 0, lslot = 2;
    for (int t = 0; t < nt; t++) {
        asm volatile("cp.async.wait_group 1;" ::: "memory");
        __syncthreads();
        if (t + 2 < nt) load_stage(lslot, (t + 2) * 32);
        else asm volatile("cp.async.commit_group;" ::: "memory");
        if (++lslot == STAGES) lslot = 0;

        const uint32_t stg = sbase + (uint32_t)cslot * STAGE_BYTES;
        if (++cslot == STAGES) cslot = 0;
        #pragma unroll
        for (int kh = 0; kh < 2; kh++) {
            const uint32_t kx = (uint32_t)(kh * 0x20);   // chunk+2 under swizzle
            // B fragments first (4 loads), then A mt-outer/sp-inner:
            // first MMA's operands ready after 6 of 12 ldmatrix.
            uint32_t bfr[2][2][4];
            #pragma unroll
            for (int ng = 0; ng < 2; ng++)
                #pragma unroll
                for (int sp = 0; sp < 2; sp++)
                    LDMX4(bfr[sp][ng],
                          stg + ((bSw + (uint32_t)(sp * TILE_BYTES + ng * 1024)) ^ kx));
            uint32_t afr[2][4][4];
            #pragma unroll
            for (int mt = 0; mt < 4; mt++)
                #pragma unroll
                for (int sp = 0; sp < 2; sp++)
                    LDMX4(afr[sp][mt],
                          stg + ((aSw + (uint32_t)(sp * TILE_BYTES + mt * 1024)) ^ kx));
            #pragma unroll
            for (int mt = 0; mt < 4; mt++)
                #pragma unroll
                for (int nn = 0; nn < 4; nn++) {
                    int ng = nn >> 1, hb = (nn & 1) * 2;
                    uint32_t b0h[2] = { bfr[0][ng][hb], bfr[0][ng][hb+1] };
                    uint32_t b0l[2] = { bfr[1][ng][hb], bfr[1][ng][hb+1] };
                    MMA_BF16(acc[mt][nn], afr[0][mt], b0h);  // Ah*Bh
                    MMA_BF16(acc[mt][nn], afr[0][mt], b0l);  // Ah*Bl
                    MMA_BF16(acc[mt][nn], afr[1][mt], b0h);  // Al*Bh
                }
        }
    }

    // ---- epilogue ----
    const float* bias = p.bias[z];
    #pragma unroll
    for (int nn = 0; nn < 4; nn++) {
        int cn = n0 + wn + nn * 8 + (lane & 3) * 2;
        float b0v = bias[cn], b1v = bias[cn + 1];
        #pragma unroll
        for (int mt = 0; mt < 4; mt++) {
            int r0 = m0 + wm + mt * 16 + (lane >> 2);
            #pragma unroll
            for (int half = 0; half < 2; half++) {
                int r = r0 + half * 8;
                float v0 = acc[mt][nn][half*2 + 0] + b0v;
                float v1 = acc[mt][nn][half*2 + 1] + b1v;
                if (RELU) { v0 = fmaxf(v0, 0.f); v1 = fmaxf(v1, 0.f); }
                if (OUTBF) {
                    __nv_bfloat16 h0, l0, h1, l1;
                    split_bf(v0, h0, l0);
                    split_bf(v1, h1, l1);
                    __nv_bfloat162 hp; hp.x = h0; hp.y = h1;
                    __nv_bfloat162 lp; lp.x = l0; lp.y = l1;
                    *(__nv_bfloat162*)(p.outh[z] + (size_t)r * N + cn) = hp;
                    *(__nv_bfloat162*)(p.outl[z] + (size_t)r * N + cn) = lp;
                } else {
                    float2 o; o.x = v0; o.y = v1;
                    *(float2*)(p.outf[z] + (size_t)r * N + cn) = o;
                }
            }
        }
    }
}

// ---------------- attention pass 1: per-chunk  S_c = phiK^T V,  ks_c = sum phiK
__global__ void __launch_bounds__(256) att_sums_kernel() {
    __shared__ float sK[CC][68];
    __shared__ float sV[CC][68];
    int c = blockIdx.x, bh = blockIdx.y;
    int b = bh >> 3, h = bh & 7;
    int tid = threadIdx.x;
    int len = g_len[b];
    #pragma unroll
    for (int it = 0; it < 4; it++) {
        int idx = it * 256 + tid;            // 0..1023
        int j  = idx >> 4;                   // row 0..63
        int d4 = (idx & 15) << 2;            // 0..60
        int srow = c * CC + j;
        size_t g = ((size_t)(b * SS + srow)) * DD + h * DHH + d4;
        float4 k4 = *(const float4*)&g_k[g];
        float4 v4 = *(const float4*)&g_v[g];
        bool msk = srow < len;
        float4 kk4;
        kk4.x = msk ? phi_f(k4.x) : 0.f;
        kk4.y = msk ? phi_f(k4.y) : 0.f;
        kk4.z = msk ? phi_f(k4.z) : 0.f;
        kk4.w = msk ? phi_f(k4.w) : 0.f;
        *(float4*)&sK[j][d4] = kk4;
        *(float4*)&sV[j][d4] = v4;
    }
    __syncthreads();
    int ti = tid & 15, tj = tid >> 4;
    float acc[4][4];
    #pragma unroll
    for (int r = 0; r < 4; r++)
        #pragma unroll
        for (int e = 0; e < 4; e++) acc[r][e] = 0.f;
    #pragma unroll 8
    for (int j = 0; j < CC; j++) {
        float4 kf = *(const float4*)&sK[j][ti*4];
        float4 vf = *(const float4*)&sV[j][tj*4];
        float ka[4] = {kf.x,kf.y,kf.z,kf.w};
        float va[4] = {vf.x,vf.y,vf.z,vf.w};
        #pragma unroll
        for (int r = 0; r < 4; r++)
            #pragma unroll
            for (int e = 0; e < 4; e++)
                acc[r][e] = fmaf(ka[r], va[e], acc[r][e]);
    }
    float* So = &g_S[((size_t)(bh * NCC + c)) * (DHH * DHH)];
    #pragma unroll
    for (int r = 0; r < 4; r++) {
        int d = ti * 4 + r;
        float4 o; o.x = acc[r][0]; o.y = acc[r][1]; o.z = acc[r][2]; o.w = acc[r][3];
        *(float4*)&So[d * DHH + tj * 4] = o;
    }
    if (tid < DHH) {
        float s = 0.f;
        #pragma unroll 8
        for (int j = 0; j < CC; j++) s += sK[j][tid];
        g_ks[(bh * NCC + c) * DHH + tid] = s;
    }
}

// ---------------- attention pass 2: exclusive prefix over chunks ----------------
__global__ void __launch_bounds__(256) att_scan_kernel() {
    int bh = blockIdx.x, tid = threadIdx.x;
    float run[16];
    #pragma unroll
    for (int r = 0; r < 16; r++) run[r] = 0.f;
    for (int c = 0; c < NCC; c++) {
        float* p = &g_S[((size_t)(bh * NCC + c)) * (DHH*DHH) + tid * 16];
        #pragma unroll
        for (int r4 = 0; r4 < 4; r4++) {
            float4 tv = ((const float4*)p)[r4];
            float4 rv;
            rv.x = run[r4*4+0]; rv.y = run[r4*4+1];
            rv.z = run[r4*4+2]; rv.w = run[r4*4+3];
            ((float4*)p)[r4] = rv;
            run[r4*4+0] += tv.x; run[r4*4+1] += tv.y;
            run[r4*4+2] += tv.z; run[r4*4+3] += tv.w;
        }
    }
    if (tid < DHH) {
        float rk = 0.f;
        for (int c = 0; c < NCC; c++) {
            float* kp = &g_ks[(bh * NCC + c) * DHH + tid];
            float t = *kp; *kp = rk; rk += t;
        }
    }
}

// ---------------- attention pass 3 ----------------
#define SM3_FLOATS (3*CC*68 + DHH)
#define SM3_BYTES  (SM3_FLOATS * 4)
__global__ void __launch_bounds__(256) att_out_kernel() {
    extern __shared__ float smf[];
    float* sQ  = smf;
    float* sKV = smf + CC*68;
    float* sSA = smf + 2*CC*68;
    float* skp = smf + 3*CC*68;

    int c = blockIdx.x, bh = blockIdx.y;
    int b = bh >> 3, h = bh & 7;
    int tid = threadIdx.x;
    int len = g_len[b];

    const float* Sg = &g_S[((size_t)(bh * NCC + c)) * (DHH*DHH)];
    #pragma unroll
    for (int it = 0; it < 4; it++) {
        int idx = it * 256 + tid;            // 0..1023
        int r  = idx >> 4;                   // row 0..63
        int d4 = (idx & 15) << 2;            // 0..60
        int srow = c * CC + r;
        size_t g = ((size_t)(b * SS + srow)) * DD + h * DHH + d4;
        float4 q4 = *(const float4*)&g_q[g];
        float4 k4 = *(const float4*)&g_k[g];
        bool msk = srow < len;
        sQ[(d4+0)*68 + r] = phi_f(q4.x);
        sQ[(d4+1)*68 + r] = phi_f(q4.y);
        sQ[(d4+2)*68 + r] = phi_f(q4.z);
        sQ[(d4+3)*68 + r] = phi_f(q4.w);
        sKV[(d4+0)*68 + r] = msk ? phi_f(k4.x) : 0.f;
        sKV[(d4+1)*68 + r] = msk ? phi_f(k4.y) : 0.f;
        sKV[(d4+2)*68 + r] = msk ? phi_f(k4.z) : 0.f;
        sKV[(d4+3)*68 + r] = msk ? phi_f(k4.w) : 0.f;
        float4 s4 = *(const float4*)&Sg[r * DHH + d4];
        *(float4*)&sSA[r*68 + d4] = s4;      // sSA[d][e] with row index = d
    }
    if (tid < DHH) skp[tid] = g_ks[(bh * NCC + c) * DHH + tid];
    __syncthreads();

    int ti = tid & 15, tj = tid >> 4;

    float zi = 0.f;
    if (tid < DHH) {
        #pragma unroll 8
        for (int d = 0; d < DHH; d++) zi += sQ[d*68 + tid] * skp[d];
    }

    float oacc[4][4], aacc[4][4];
    #pragma unroll
    for (int r = 0; r < 4; r++)
        #pragma unroll
        for (int e = 0; e < 4; e++) { oacc[r][e] = 0.f; aacc[r][e] = 0.f; }
    #pragma unroll 4
    for (int d = 0; d < DHH; d++) {
        float4 aq = *(const float4*)&sQ [d*68 + ti*4];
        float4 bs = *(const float4*)&sSA[d*68 + tj*4];
        float4 bk = *(const float4*)&sKV[d*68 + tj*4];
        float qa[4] = {aq.x,aq.y,aq.z,aq.w};
        float sa[4] = {bs.x,bs.y,bs.z,bs.w};
        float ka[4] = {bk.x,bk.y,bk.z,bk.w};
        #pragma unroll
        for (int r = 0; r < 4; r++)
            #pragma unroll
            for (int e = 0; e < 4; e++) {
                oacc[r][e] = fmaf(qa[r], sa[e], oacc[r][e]);
                aacc[r][e] = fmaf(qa[r], ka[e], aacc[r][e]);
            }
    }
    __syncthreads();

    #pragma unroll
    for (int r = 0; r < 4; r++)
        #pragma unroll
        for (int e = 0; e < 4; e++) {
            int i = ti * 4 + r, j = tj * 4 + e;
            sSA[j*68 + i] = (j <= i) ? aacc[r][e] : 0.f;
        }
    #pragma unroll
    for (int it = 0; it < 4; it++) {
        int idx = it * 256 + tid;
        int r  = idx >> 4;
        int e4 = (idx & 15) << 2;
        float4 v4 = *(const float4*)&g_v[((size_t)(b * SS + c * CC + r)) * DD + h * DHH + e4];
        *(float4*)&sKV[r*68 + e4] = v4;
    }
    __syncthreads();

    if (tid < DHH) {
        float z = zi;
        #pragma unroll 8
        for (int j = 0; j < CC; j++) z += sSA[j*68 + tid];
        skp[tid] = 1.f / (z + 1e-6f);
    }

    #pragma unroll 4
    for (int j = 0; j < CC; j++) {
        float4 aj = *(const float4*)&sSA[j*68 + ti*4];
        float4 ve = *(const float4*)&sKV[j*68 + tj*4];
        float aa[4] = {aj.x,aj.y,aj.z,aj.w};
        float va[4] = {ve.x,ve.y,ve.z,ve.w};
        #pragma unroll
        for (int r = 0; r < 4; r++)
            #pragma unroll
            for (int e = 0; e < 4; e++)
                oacc[r][e] = fmaf(aa[r], va[e], oacc[r][e]);
    }
    __syncthreads();

    #pragma unroll
    for (int r = 0; r < 4; r++) {
        int i = ti * 4 + r;
        float zr = skp[i];
        size_t base = ((size_t)(b * SS + c * CC + i)) * DD + h * DHH + tj * 4;
        #pragma unroll
        for (int e = 0; e < 4; e++) {
            float o = oacc[r][e] * zr;
            __nv_bfloat16 hh, ll;
            split_bf(o, hh, ll);
            g_ab_h[base + e] = hh;
            g_ab_l[base + e] = ll;
        }
    }
}

// ---------------- LayerNorm (+ residual, + optional bf16 split out) ----------------
__global__ void ln_kernel(const float* __restrict__ x, const float* __restrict__ add,
                          const float* __restrict__ gamma, const float* __restrict__ beta,
                          float* __restrict__ out,
                          __nv_bfloat16* __restrict__ oh, __nv_bfloat16* __restrict__ ol) {
    __shared__ float rs[4], rq[4];
    int row = blockIdx.x, tid = threadIdx.x;
    float4 v = ((const float4*)(x + (size_t)row * DD))[tid];
    if (add) {
        float4 a = ((const float4*)(add + (size_t)row * DD))[tid];
        v.x += a.x; v.y += a.y; v.z += a.z; v.w += a.w;
    }
    float s = v.x + v.y + v.z + v.w;
    float q = v.x*v.x + v.y*v.y + v.z*v.z + v.w*v.w;
    #pragma unroll
    for (int off = 16; off; off >>= 1) {
        s += __shfl_xor_sync(0xffffffffu, s, off);
        q += __shfl_xor_sync(0xffffffffu, q, off);
    }
    if ((tid & 31) == 0) { rs[tid >> 5] = s; rq[tid >> 5] = q; }
    __syncthreads();
    s = rs[0] + rs[1] + rs[2] + rs[3];
    q = rq[0] + rq[1] + rq[2] + rq[3];
    float mu   = s * (1.f / DD);
    float var  = q * (1.f / DD) - mu * mu;
    float rstd = rsqrtf(var + 1e-5f);
    float4 g  = ((const float4*)gamma)[tid];
    float4 bt = ((const float4*)beta)[tid];
    float4 o;
    o.x = (v.x - mu) * rstd * g.x + bt.x;
    o.y = (v.y - mu) * rstd * g.y + bt.y;
    o.z = (v.z - mu) * rstd * g.z + bt.z;
    o.w = (v.w - mu) * rstd * g.w + bt.w;
    ((float4*)(out + (size_t)row * DD))[tid] = o;
    if (oh) {
        size_t e0 = (size_t)row * DD + tid * 4;
        float vv[4] = {o.x, o.y, o.z, o.w};
        #pragma unroll
        for (int j = 0; j < 4; j++) split_bf(vv[j], oh[e0+j], ol[e0+j]);
    }
}

// ---------------- launch --------------------------------------------------------
extern "C" void kernel_launch(void* const* d_in, const int* in_sizes, int n_in,
                              void* d_out, int out_size) {
    (void)in_sizes; (void)n_in; (void)out_size;
    const int*   x   = (const int*)  d_in[0];
    const float* emb = (const float*)d_in[1];
    const float* pe  = (const float*)d_in[2];
    const float* Wq  = (const float*)d_in[3];
    const float* bq  = (const float*)d_in[4];
    const float* Wk  = (const float*)d_in[5];
    const float* bk  = (const float*)d_in[6];
    const float* Wv  = (const float*)d_in[7];
    const float* bv  = (const float*)d_in[8];
    const float* Wo  = (const float*)d_in[9];
    const float* bo  = (const float*)d_in[10];
    const float* W1  = (const float*)d_in[11];
    const float* b1  = (const float*)d_in[12];
    const float* W2  = (const float*)d_in[13];
    const float* b2  = (const float*)d_in[14];
    const float* g1  = (const float*)d_in[15];
    const float* be1 = (const float*)d_in[16];
    const float* g2  = (const float*)d_in[17];
    const float* be2 = (const float*)d_in[18];
    const float* gf  = (const float*)d_in[19];
    const float* bf  = (const float*)d_in[20];

    float *h, *q, *kk, *vv;
    cudaGetSymbolAddress((void**)&h, g_h);
    cudaGetSymbolAddress((void**)&q, g_q);
    cudaGetSymbolAddress((void**)&kk, g_k);
    cudaGetSymbolAddress((void**)&vv, g_v);
    __nv_bfloat16 *hb_h, *hb_l, *ab_h, *ab_l, *tb_h, *tb_l;
    cudaGetSymbolAddress((void**)&hb_h, g_hb_h);
    cudaGetSymbolAddress((void**)&hb_l, g_hb_l);
    cudaGetSymbolAddress((void**)&ab_h, g_ab_h);
    cudaGetSymbolAddress((void**)&ab_l, g_ab_l);
    cudaGetSymbolAddress((void**)&tb_h, g_tb_h);
    cudaGetSymbolAddress((void**)&tb_l, g_tb_l);
    __nv_bfloat16 *wqh, *wql, *wkh, *wkl, *wvh, *wvl, *woh, *wol, *w1h, *w1l, *w2h, *w2l;
    cudaGetSymbolAddress((void**)&wqh, g_wq_h); cudaGetSymbolAddress((void**)&wql, g_wq_l);
    cudaGetSymbolAddress((void**)&wkh, g_wk_h); cudaGetSymbolAddress((void**)&wkl, g_wk_l);
    cudaGetSymbolAddress((void**)&wvh, g_wv_h); cudaGetSymbolAddress((void**)&wvl, g_wv_l);
    cudaGetSymbolAddress((void**)&woh, g_wo_h); cudaGetSymbolAddress((void**)&wol, g_wo_l);
    cudaGetSymbolAddress((void**)&w1h, g_w1_h); cudaGetSymbolAddress((void**)&w1l, g_w1_l);
    cudaGetSymbolAddress((void**)&w2h, g_w2_h); cudaGetSymbolAddress((void**)&w2l, g_w2_l);

    cudaFuncSetAttribute(att_out_kernel,
                         cudaFuncAttributeMaxDynamicSharedMemorySize, SM3_BYTES);
    cudaFuncSetAttribute(gemm_mma<0,0>,
                         cudaFuncAttributeMaxDynamicSharedMemorySize, GM_SMEM_BYTES);
    cudaFuncSetAttribute(gemm_mma<1,1>,
                         cudaFuncAttributeMaxDynamicSharedMemorySize, GM_SMEM_BYTES);

    len_kernel<<<BB, 256>>>(x);
    embed_kernel<<<(MM * (DD/4) + 255) / 256, 256>>>(x, emb, pe);

    // batched weight transpose+split: 24 matrices, one launch
    {
        WtcArgs wa = {};
        int idx = 0;
        for (int l = 0; l < NLL; l++) {
            size_t wo = (size_t)l * DD * DD;
            size_t wf = (size_t)l * DD * FF;
            wa.src[idx] = Wq + wo; wa.oh[idx] = wqh + wo; wa.ol[idx] = wql + wo; wa.K[idx] = DD; wa.N[idx] = DD; idx++;
            wa.src[idx] = Wk + wo; wa.oh[idx] = wkh + wo; wa.ol[idx] = wkl + wo; wa.K[idx] = DD; wa.N[idx] = DD; idx++;
            wa.src[idx] = Wv + wo; wa.oh[idx] = wvh + wo; wa.ol[idx] = wvl + wo; wa.K[idx] = DD; wa.N[idx] = DD; idx++;
            wa.src[idx] = Wo + wo; wa.oh[idx] = woh + wo; wa.ol[idx] = wol + wo; wa.K[idx] = DD; wa.N[idx] = DD; idx++;
            wa.src[idx] = W1 + wf; wa.oh[idx] = w1h + wf; wa.ol[idx] = w1l + wf; wa.K[idx] = DD; wa.N[idx] = FF; idx++;
            wa.src[idx] = W2 + wf; wa.oh[idx] = w2h + wf; wa.ol[idx] = w2l + wf; wa.K[idx] = FF; wa.N[idx] = DD; idx++;
        }
        wtc_all_kernel<<<dim3(FF/32, FF/32, 24), dim3(32, 8)>>>(wa);
    }

    for (int l = 0; l < NLL; l++) {
        size_t wo   = (size_t)l * DD * DD;
        size_t wf   = (size_t)l * DD * FF;
        size_t boff = (size_t)l * DD;

        // QKV fused
        GTArgs ga = {};
        ga.Ah = hb_h; ga.Al = hb_l; ga.N = DD; ga.K = DD;
        ga.Bh[0] = wqh + wo; ga.Bl[0] = wql + wo;
        ga.Bh[1] = wkh + wo; ga.Bl[1] = wkl + wo;
        ga.Bh[2] = wvh + wo; ga.Bl[2] = wvl + wo;
        ga.bias[0] = bq + boff; ga.bias[1] = bk + boff; ga.bias[2] = bv + boff;
        ga.outf[0] = q; ga.outf[1] = kk; ga.outf[2] = vv;
        gemm_mma<0,0><<<dim3(DD/128, MM/128, 3), 256, GM_SMEM_BYTES>>>(ga);

        att_sums_kernel<<<dim3(NCC, BHH), 256>>>();
        att_scan_kernel<<<BHH, 256>>>();
        att_out_kernel<<<dim3(NCC, BHH), 256, SM3_BYTES>>>();

        // O proj
        GTArgs go = {};
        go.Ah = ab_h; go.Al = ab_l; go.N = DD; go.K = DD;
        go.Bh[0] = woh + wo; go.Bl[0] = wol + wo;
        go.bias[0] = bo + boff; go.outf[0] = q;
        gemm_mma<0,0><<<dim3(DD/128, MM/128, 1), 256, GM_SMEM_BYTES>>>(go);

        ln_kernel<<<MM, 128>>>(h, q, g1 + boff, be1 + boff, h, hb_h, hb_l);

        // FFN1 (relu, bf16-split output)
        GTArgs g1a = {};
        g1a.Ah = hb_h; g1a.Al = hb_l; g1a.N = FF; g1a.K = DD;
        g1a.Bh[0] = w1h + wf; g1a.Bl[0] = w1l + wf;
        g1a.bias[0] = b1 + (size_t)l * FF;
        g1a.outh[0] = tb_h; g1a.outl[0] = tb_l;
        gemm_mma<1,1><<<dim3(FF/128, MM/128, 1), 256, GM_SMEM_BYTES>>>(g1a);

        // FFN2
        GTArgs g2a = {};
        g2a.Ah = tb_h; g2a.Al = tb_l; g2a.N = DD; g2a.K = FF;
        g2a.Bh[0] = w2h + wf; g2a.Bl[0] = w2l + wf;
        g2a.bias[0] = b2 + boff; g2a.outf[0] = q;
        gemm_mma<0,0><<<dim3(DD/128, MM/128, 1), 256, GM_SMEM_BYTES>>>(g2a);

        ln_kernel<<<MM, 128>>>(h, q, g2 + boff, be2 + boff, h, hb_h, hb_l);
    }

    ln_kernel<<<MM, 128>>>(h, nullptr, gf, bf, (float*)d_out, nullptr, nullptr);
}

// round 9
// speedup vs baseline: 2.3204x; 1.0050x over previous
#include <cuda_runtime.h>
#include <cuda_bf16.h>
#include <cstdint>

// ---------------- problem constants ----------------
#define BB  4
#define SS  2048
#define DD  512
#define HH  8
#define DHH 64
#define FF  2048
#define NLL 4
#define MM  (BB*SS)      // 8192 rows
#define CC  64           // attention chunk length
#define NCC (SS/CC)      // 32 chunks
#define BHH (BB*HH)      // 32 (b,h) pairs

__device__ __forceinline__ uint32_t smem_u32(const void* p) {
    uint32_t a;
    asm("{ .reg .u64 t; cvta.to.shared.u64 t, %1; cvt.u32.u64 %0, t; }" : "=r"(a) : "l"(p));
    return a;
}

// ---------------- scratch (device globals; no allocs allowed) ----------------
__device__ float g_h[MM*DD];
__device__ float g_q[MM*DD];          // holds phi(q) after QKV
__device__ float g_k[MM*DD];          // holds masked phi(k) after QKV
__device__ float g_v[MM*DD];
__device__ float g_S[(size_t)BHH*NCC*DHH*DHH];
__device__ float g_ks[BHH*NCC*DHH];
__device__ int   g_len[BB];

__device__ __align__(16) __nv_bfloat16 g_hb_h[MM*DD], g_hb_l[MM*DD];
__device__ __align__(16) __nv_bfloat16 g_ab_h[MM*DD], g_ab_l[MM*DD];
__device__ __align__(16) __nv_bfloat16 g_tb_h[(size_t)MM*FF], g_tb_l[(size_t)MM*FF];

__device__ __align__(16) __nv_bfloat16 g_wq_h[NLL*DD*DD], g_wq_l[NLL*DD*DD];
__device__ __align__(16) __nv_bfloat16 g_wk_h[NLL*DD*DD], g_wk_l[NLL*DD*DD];
__device__ __align__(16) __nv_bfloat16 g_wv_h[NLL*DD*DD], g_wv_l[NLL*DD*DD];
__device__ __align__(16) __nv_bfloat16 g_wo_h[NLL*DD*DD], g_wo_l[NLL*DD*DD];
__device__ __align__(16) __nv_bfloat16 g_w1_h[NLL*FF*DD], g_w1_l[NLL*FF*DD];
__device__ __align__(16) __nv_bfloat16 g_w2_h[NLL*DD*FF], g_w2_l[NLL*DD*FF];

__device__ __forceinline__ float phi_f(float u) { return u > 0.f ? u + 1.f : __expf(u); }

__device__ __forceinline__ void split_bf(float x, __nv_bfloat16& h, __nv_bfloat16& l) {
    h = __float2bfloat16(x);
    l = __float2bfloat16(x - __bfloat162float(h));
}

// ---------------- lengths ----------------
__global__ void len_kernel(const int* __restrict__ x) {
    __shared__ int red[256];
    int b = blockIdx.x, tid = threadIdx.x;
    int cnt = 0;
    for (int s = tid; s < SS; s += 256) cnt += (x[b*SS + s] != 0);
    red[tid] = cnt; __syncthreads();
    for (int off = 128; off; off >>= 1) {
        if (tid < off) red[tid] += red[tid + off];
        __syncthreads();
    }
    if (tid == 0) g_len[b] = red[0];
}

// ---------------- embedding + positional (+ bf16 split) ----------------
__global__ void embed_kernel(const int* __restrict__ x,
                             const float* __restrict__ emb,
                             const float* __restrict__ pe) {
    int idx = blockIdx.x * 256 + threadIdx.x;
    if (idx >= MM * (DD/4)) return;
    int i  = idx >> 7;
    int d4 = idx & 127;
    int s  = i & (SS - 1);
    int tok = x[i];
    float4 e = ((const float4*)emb)[(size_t)tok * (DD/4) + d4];
    float4 p = ((const float4*)pe)[(size_t)s * (DD/4) + d4];
    float4 o;
    o.x = e.x + p.x; o.y = e.y + p.y; o.z = e.z + p.z; o.w = e.w + p.w;
    ((float4*)g_h)[idx] = o;
    size_t e0 = (size_t)idx * 4;
    float vv[4] = {o.x, o.y, o.z, o.w};
    #pragma unroll
    for (int j = 0; j < 4; j++) split_bf(vv[j], g_hb_h[e0+j], g_hb_l[e0+j]);
}

// ---------------- batched weight transpose + split (24 matrices, one launch) ----
struct WtcArgs {
    const float* src[24];
    __nv_bfloat16* oh[24];
    __nv_bfloat16* ol[24];
    int K[24], N[24];
};
__global__ void wtc_all_kernel(WtcArgs p) {
    __shared__ float t[32][33];
    int m = blockIdx.z;
    int K = p.K[m], N = p.N[m];
    int n0 = blockIdx.x * 32, k0 = blockIdx.y * 32;
    if (n0 >= N || k0 >= K) return;
    const float* W = p.src[m];
    __nv_bfloat16 *oh = p.oh[m], *ol = p.ol[m];
    int tx = threadIdx.x, ty = threadIdx.y;   // 32x8
    #pragma unroll
    for (int i = 0; i < 32; i += 8)
        t[ty + i][tx] = W[(size_t)(k0 + ty + i) * N + n0 + tx];
    __syncthreads();
    #pragma unroll
    for (int i = 0; i < 32; i += 8) {
        float v = t[tx][ty + i];
        size_t o = (size_t)(n0 + ty + i) * K + k0 + tx;
        split_bf(v, oh[o], ol[o]);
    }
}

// ---------------- split-bf16 GEMM via warp mma.sync ----------------
// C[M,N] = A[M,K] * B[N,K]^T + bias ; A,B as bf16 (hi,lo) pairs, K-major rows.
// Block 128x128, BK=32, 256 thr, warp tile 64x32.
// 3-stage cp.async pipeline, swizzled 64B-pitch smem, one sync/iter, 2 CTAs/SM.
// MMA terms issued term-major (16 independent acc chains between RAW reuses).
// pmode (float-out path): 0=none, 1=phi, 2=masked phi.
struct GTArgs {
    const __nv_bfloat16 *Ah, *Al;
    const __nv_bfloat16 *Bh[3], *Bl[3];
    const float* bias[3];
    float* outf[3];
    __nv_bfloat16 *outh[3], *outl[3];
    int pmode[3];
    int N, K;
};

#define STAGES 3
#define TILE_BYTES 8192                    // 128 rows x 64B (swizzled)
#define STAGE_BYTES (4*TILE_BYTES)         // Ah,Al,Bh,Bl = 32768
#define GM_SMEM_BYTES (STAGES*STAGE_BYTES) // 98304

// swizzled in-tile byte offset for (row, 16B-chunk c): row*64 + (c ^ ((row>>1)&3))*16
__device__ __forceinline__ uint32_t swz(int row, int c) {
    return (uint32_t)(row * 64 + ((c ^ ((row >> 1) & 3)) << 4));
}

#define MMA_BF16(d, a, b) \
    asm volatile("mma.sync.aligned.m16n8k16.row.col.f32.bf16.bf16.f32 " \
        "{%0,%1,%2,%3}, {%4,%5,%6,%7}, {%8,%9}, {%0,%1,%2,%3};" \
        : "+f"((d)[0]), "+f"((d)[1]), "+f"((d)[2]), "+f"((d)[3]) \
        : "r"((a)[0]), "r"((a)[1]), "r"((a)[2]), "r"((a)[3]), "r"((b)[0]), "r"((b)[1]))

#define LDMX4(r, addr) \
    asm volatile("ldmatrix.sync.aligned.m8n8.x4.shared.b16 {%0,%1,%2,%3}, [%4];" \
        : "=r"((r)[0]), "=r"((r)[1]), "=r"((r)[2]), "=r"((r)[3]) : "r"(addr))

template<int RELU, int OUTBF>
__global__ void __launch_bounds__(256, 2) gemm_mma(GTArgs p) {
    extern __shared__ __nv_bfloat16 sm[];
    const uint32_t sbase = smem_u32(sm);
    const int z = blockIdx.z;
    const int N = p.N, K = p.K;
    const int tid = threadIdx.x;
    const int m0 = blockIdx.y * 128, n0 = blockIdx.x * 128;

    // ---- loader: each thread owns (row rA, chunk chk) in every tile; 8 x 16B per stage
    const int rA  = tid >> 2;          // 0..63
    const int chk = tid & 3;           // 16B chunk within 64B row
    const __nv_bfloat16* gp[4];
    gp[0] = p.Ah    + (size_t)(m0 + rA) * K + chk * 8;
    gp[1] = p.Al    + (size_t)(m0 + rA) * K + chk * 8;
    gp[2] = p.Bh[z] + (size_t)(n0 + rA) * K + chk * 8;
    gp[3] = p.Bl[z] + (size_t)(n0 + rA) * K + chk * 8;
    const uint32_t s0 = swz(rA, chk);  // rows rA and rA+64 share swizzle bits
    const size_t K64 = (size_t)K << 6; // 64 rows of stride K

    const int wid = tid >> 5, lane = tid & 31;
    const int wm = (wid & 1) * 64;
    const int wn = (wid >> 1) * 32;

    // ---- fragment base offsets (swizzled); kh step = XOR 0x20 ----
    const int rowa = wm + (lane & 15);
    const uint32_t aSw = swz(rowa, (lane >> 4) & 1);
    const int rowb = wn + (lane & 7) + ((lane >> 4) << 3);
    const uint32_t bSw = (uint32_t)(2 * TILE_BYTES) + swz(rowb, (lane >> 3) & 1);

    float acc[4][4][4];
    #pragma unroll
    for (int a = 0; a < 4; a++)
        #pragma unroll
        for (int b = 0; b < 4; b++)
            #pragma unroll
            for (int c = 0; c < 4; c++) acc[a][b][c] = 0.f;

    const int nt = K >> 5;

    auto load_stage = [&](int slot, int k0) {
        uint32_t sb = sbase + (uint32_t)slot * STAGE_BYTES + s0;
        #pragma unroll
        for (int op = 0; op < 4; op++)
            #pragma unroll
            for (int j = 0; j < 2; j++) {
                asm volatile("cp.async.cg.shared.global [%0], [%1], 16;"
                    :: "r"(sb + (uint32_t)(op * TILE_BYTES + j * 4096)),
                       "l"(gp[op] + (j ? K64 : 0) + k0));
            }
        asm volatile("cp.async.commit_group;" ::: "memory");
    };

    // prologue: 2 stages in flight
    load_stage(0, 0);
    load_stage(1, 32);

    int cslot = 0, lslot = 2;
    for (int t = 0; t < nt; t++) {
        asm volatile("cp.async.wait_group 1;" ::: "memory");
        __syncthreads();
        if (t + 2 < nt) load_stage(lslot, (t + 2) * 32);
        else asm volatile("cp.async.commit_group;" ::: "memory");
        if (++lslot == STAGES) lslot = 0;

        const uint32_t stg = sbase + (uint32_t)cslot * STAGE_BYTES;
        if (++cslot == STAGES) cslot = 0;
        #pragma unroll
        for (int kh = 0; kh < 2; kh++) {
            const uint32_t kx = (uint32_t)(kh * 0x20);   // chunk+2 under swizzle
            // B fragments first (4 loads), then A — first MMA ready after 6 of 12.
            uint32_t bfr[2][2][4];
            #pragma unroll
            for (int ng = 0; ng < 2; ng++)
                #pragma unroll
                for (int sp = 0; sp < 2; sp++)
                    LDMX4(bfr[sp][ng],
                          stg + ((bSw + (uint32_t)(sp * TILE_BYTES + ng * 1024)) ^ kx));
            uint32_t afr[2][4][4];
            #pragma unroll
            for (int mt = 0; mt < 4; mt++)
                #pragma unroll
                for (int sp = 0; sp < 2; sp++)
                    LDMX4(afr[sp][mt],
                          stg + ((aSw + (uint32_t)(sp * TILE_BYTES + mt * 1024)) ^ kx));
            // term-major: all Ah*Bh, then all Ah*Bl, then all Al*Bh.
            // Per-acc accumulation order stays (hh, hl, lh) — numerics identical;
            // RAW reuse of each acc is now 16 MMAs apart instead of back-to-back.
            #pragma unroll
            for (int mt = 0; mt < 4; mt++)
                #pragma unroll
                for (int nn = 0; nn < 4; nn++) {
                    int ng = nn >> 1, hb = (nn & 1) * 2;
                    uint32_t b0h[2] = { bfr[0][ng][hb], bfr[0][ng][hb+1] };
                    MMA_BF16(acc[mt][nn], afr[0][mt], b0h);  // Ah*Bh
                }
            #pragma unroll
            for (int mt = 0; mt < 4; mt++)
                #pragma unroll
                for (int nn = 0; nn < 4; nn++) {
                    int ng = nn >> 1, hb = (nn & 1) * 2;
                    uint32_t b0l[2] = { bfr[1][ng][hb], bfr[1][ng][hb+1] };
                    MMA_BF16(acc[mt][nn], afr[0][mt], b0l);  // Ah*Bl
                }
            #pragma unroll
            for (int mt = 0; mt < 4; mt++)
                #pragma unroll
                for (int nn = 0; nn < 4; nn++) {
                    int ng = nn >> 1, hb = (nn & 1) * 2;
                    uint32_t b0h[2] = { bfr[0][ng][hb], bfr[0][ng][hb+1] };
                    MMA_BF16(acc[mt][nn], afr[1][mt], b0h);  // Al*Bh
                }
        }
    }

    // ---- epilogue ----
    const float* bias = p.bias[z];
    const int pm = OUTBF ? 0 : p.pmode[z];
    const int lenb = g_len[m0 >> 11];     // batch fixed per CTA (128 | 2048)
    #pragma unroll
    for (int nn = 0; nn < 4; nn++) {
        int cn = n0 + wn + nn * 8 + (lane & 3) * 2;
        float b0v = bias[cn], b1v = bias[cn + 1];
        #pragma unroll
        for (int mt = 0; mt < 4; mt++) {
            int r0 = m0 + wm + mt * 16 + (lane >> 2);
            #pragma unroll
            for (int half = 0; half < 2; half++) {
                int r = r0 + half * 8;
                float v0 = acc[mt][nn][half*2 + 0] + b0v;
                float v1 = acc[mt][nn][half*2 + 1] + b1v;
                if (RELU) { v0 = fmaxf(v0, 0.f); v1 = fmaxf(v1, 0.f); }
                if (OUTBF) {
                    __nv_bfloat16 h0, l0, h1, l1;
                    split_bf(v0, h0, l0);
                    split_bf(v1, h1, l1);
                    __nv_bfloat162 hp; hp.x = h0; hp.y = h1;
                    __nv_bfloat162 lp; lp.x = l0; lp.y = l1;
                    *(__nv_bfloat162*)(p.outh[z] + (size_t)r * N + cn) = hp;
                    *(__nv_bfloat162*)(p.outl[z] + (size_t)r * N + cn) = lp;
                } else {
                    if (pm == 1) { v0 = phi_f(v0); v1 = phi_f(v1); }
                    else if (pm == 2) {
                        if ((r & (SS - 1)) < lenb) { v0 = phi_f(v0); v1 = phi_f(v1); }
                        else { v0 = 0.f; v1 = 0.f; }
                    }
                    float2 o; o.x = v0; o.y = v1;
                    *(float2*)(p.outf[z] + (size_t)r * N + cn) = o;
                }
            }
        }
    }
}

// ---------------- attention pass 1: per-chunk  S_c = phiK^T V,  ks_c = sum phiK
// g_k already holds masked phi(k); g_v raw.
__global__ void __launch_bounds__(256) att_sums_kernel() {
    __shared__ float sK[CC][68];
    __shared__ float sV[CC][68];
    int c = blockIdx.x, bh = blockIdx.y;
    int b = bh >> 3, h = bh & 7;
    int tid = threadIdx.x;
    #pragma unroll
    for (int it = 0; it < 4; it++) {
        int idx = it * 256 + tid;            // 0..1023
        int j  = idx >> 4;                   // row 0..63
        int d4 = (idx & 15) << 2;            // 0..60
        size_t g = ((size_t)(b * SS + c * CC + j)) * DD + h * DHH + d4;
        *(float4*)&sK[j][d4] = *(const float4*)&g_k[g];
        *(float4*)&sV[j][d4] = *(const float4*)&g_v[g];
    }
    __syncthreads();
    int ti = tid & 15, tj = tid >> 4;
    float acc[4][4];
    #pragma unroll
    for (int r = 0; r < 4; r++)
        #pragma unroll
        for (int e = 0; e < 4; e++) acc[r][e] = 0.f;
    #pragma unroll 8
    for (int j = 0; j < CC; j++) {
        float4 kf = *(const float4*)&sK[j][ti*4];
        float4 vf = *(const float4*)&sV[j][tj*4];
        float ka[4] = {kf.x,kf.y,kf.z,kf.w};
        float va[4] = {vf.x,vf.y,vf.z,vf.w};
        #pragma unroll
        for (int r = 0; r < 4; r++)
            #pragma unroll
            for (int e = 0; e < 4; e++)
                acc[r][e] = fmaf(ka[r], va[e], acc[r][e]);
    }
    float* So = &g_S[((size_t)(bh * NCC + c)) * (DHH * DHH)];
    #pragma unroll
    for (int r = 0; r < 4; r++) {
        int d = ti * 4 + r;
        float4 o; o.x = acc[r][0]; o.y = acc[r][1]; o.z = acc[r][2]; o.w = acc[r][3];
        *(float4*)&So[d * DHH + tj * 4] = o;
    }
    if (tid < DHH) {
        float s = 0.f;
        #pragma unroll 8
        for (int j = 0; j < CC; j++) s += sK[j][tid];
        g_ks[(bh * NCC + c) * DHH + tid] = s;
    }
}

// ---------------- attention pass 2: exclusive prefix over chunks ----------------
__global__ void __launch_bounds__(256) att_scan_kernel() {
    int bh = blockIdx.x, tid = threadIdx.x;
    float run[16];
    #pragma unroll
    for (int r = 0; r < 16; r++) run[r] = 0.f;
    for (int c = 0; c < NCC; c++) {
        float* p = &g_S[((size_t)(bh * NCC + c)) * (DHH*DHH) + tid * 16];
        #pragma unroll
        for (int r4 = 0; r4 < 4; r4++) {
            float4 tv = ((const float4*)p)[r4];
            float4 rv;
            rv.x = run[r4*4+0]; rv.y = run[r4*4+1];
            rv.z = run[r4*4+2]; rv.w = run[r4*4+3];
            ((float4*)p)[r4] = rv;
            run[r4*4+0] += tv.x; run[r4*4+1] += tv.y;
            run[r4*4+2] += tv.z; run[r4*4+3] += tv.w;
        }
    }
    if (tid < DHH) {
        float rk = 0.f;
        for (int c = 0; c < NCC; c++) {
            float* kp = &g_ks[(bh * NCC + c) * DHH + tid];
            float t = *kp; *kp = rk; rk += t;
        }
    }
}

// ---------------- attention pass 3 ----------------
// g_q holds phi(q); g_k holds masked phi(k).
#define SM3_FLOATS (3*CC*68 + DHH)
#define SM3_BYTES  (SM3_FLOATS * 4)
__global__ void __launch_bounds__(256) att_out_kernel() {
    extern __shared__ float smf[];
    float* sQ  = smf;
    float* sKV = smf + CC*68;
    float* sSA = smf + 2*CC*68;
    float* skp = smf + 3*CC*68;

    int c = blockIdx.x, bh = blockIdx.y;
    int b = bh >> 3, h = bh & 7;
    int tid = threadIdx.x;

    const float* Sg = &g_S[((size_t)(bh * NCC + c)) * (DHH*DHH)];
    #pragma unroll
    for (int it = 0; it < 4; it++) {
        int idx = it * 256 + tid;            // 0..1023
        int r  = idx >> 4;                   // row 0..63
        int d4 = (idx & 15) << 2;            // 0..60
        size_t g = ((size_t)(b * SS + c * CC + r)) * DD + h * DHH + d4;
        float4 q4 = *(const float4*)&g_q[g];
        float4 k4 = *(const float4*)&g_k[g];
        sQ[(d4+0)*68 + r] = q4.x;
        sQ[(d4+1)*68 + r] = q4.y;
        sQ[(d4+2)*68 + r] = q4.z;
        sQ[(d4+3)*68 + r] = q4.w;
        sKV[(d4+0)*68 + r] = k4.x;
        sKV[(d4+1)*68 + r] = k4.y;
        sKV[(d4+2)*68 + r] = k4.z;
        sKV[(d4+3)*68 + r] = k4.w;
        float4 s4 = *(const float4*)&Sg[r * DHH + d4];
        *(float4*)&sSA[r*68 + d4] = s4;      // sSA[d][e] with row index = d
    }
    if (tid < DHH) skp[tid] = g_ks[(bh * NCC + c) * DHH + tid];
    __syncthreads();

    int ti = tid & 15, tj = tid >> 4;

    float zi = 0.f;
    if (tid < DHH) {
        #pragma unroll 8
        for (int d = 0; d < DHH; d++) zi += sQ[d*68 + tid] * skp[d];
    }

    float oacc[4][4], aacc[4][4];
    #pragma unroll
    for (int r = 0; r < 4; r++)
        #pragma unroll
        for (int e = 0; e < 4; e++) { oacc[r][e] = 0.f; aacc[r][e] = 0.f; }
    #pragma unroll 4
    for (int d = 0; d < DHH; d++) {
        float4 aq = *(const float4*)&sQ [d*68 + ti*4];
        float4 bs = *(const float4*)&sSA[d*68 + tj*4];
        float4 bk = *(const float4*)&sKV[d*68 + tj*4];
        float qa[4] = {aq.x,aq.y,aq.z,aq.w};
        float sa[4] = {bs.x,bs.y,bs.z,bs.w};
        float ka[4] = {bk.x,bk.y,bk.z,bk.w};
        #pragma unroll
        for (int r = 0; r < 4; r++)
            #pragma unroll
            for (int e = 0; e < 4; e++) {
                oacc[r][e] = fmaf(qa[r], sa[e], oacc[r][e]);
                aacc[r][e] = fmaf(qa[r], ka[e], aacc[r][e]);
            }
    }
    __syncthreads();

    #pragma unroll
    for (int r = 0; r < 4; r++)
        #pragma unroll
        for (int e = 0; e < 4; e++) {
            int i = ti * 4 + r, j = tj * 4 + e;
            sSA[j*68 + i] = (j <= i) ? aacc[r][e] : 0.f;
        }
    #pragma unroll
    for (int it = 0; it < 4; it++) {
        int idx = it * 256 + tid;
        int r  = idx >> 4;
        int e4 = (idx & 15) << 2;
        float4 v4 = *(const float4*)&g_v[((size_t)(b * SS + c * CC + r)) * DD + h * DHH + e4];
        *(float4*)&sKV[r*68 + e4] = v4;
    }
    __syncthreads();

    if (tid < DHH) {
        float z = zi;
        #pragma unroll 8
        for (int j = 0; j < CC; j++) z += sSA[j*68 + tid];
        skp[tid] = 1.f / (z + 1e-6f);
    }

    #pragma unroll 4
    for (int j = 0; j < CC; j++) {
        float4 aj = *(const float4*)&sSA[j*68 + ti*4];
        float4 ve = *(const float4*)&sKV[j*68 + tj*4];
        float aa[4] = {aj.x,aj.y,aj.z,aj.w};
        float va[4] = {ve.x,ve.y,ve.z,ve.w};
        #pragma unroll
        for (int r = 0; r < 4; r++)
            #pragma unroll
            for (int e = 0; e < 4; e++)
                oacc[r][e] = fmaf(aa[r], va[e], oacc[r][e]);
    }
    __syncthreads();

    #pragma unroll
    for (int r = 0; r < 4; r++) {
        int i = ti * 4 + r;
        float zr = skp[i];
        size_t base = ((size_t)(b * SS + c * CC + i)) * DD + h * DHH + tj * 4;
        #pragma unroll
        for (int e = 0; e < 4; e++) {
            float o = oacc[r][e] * zr;
            __nv_bfloat16 hh, ll;
            split_bf(o, hh, ll);
            g_ab_h[base + e] = hh;
            g_ab_l[base + e] = ll;
        }
    }
}

// ---------------- LayerNorm (+ residual, + optional bf16 split out) ----------------
__global__ void ln_kernel(const float* __restrict__ x, const float* __restrict__ add,
                          const float* __restrict__ gamma, const float* __restrict__ beta,
                          float* __restrict__ out,
                          __nv_bfloat16* __restrict__ oh, __nv_bfloat16* __restrict__ ol) {
    __shared__ float rs[4], rq[4];
    int row = blockIdx.x, tid = threadIdx.x;
    float4 v = ((const float4*)(x + (size_t)row * DD))[tid];
    if (add) {
        float4 a = ((const float4*)(add + (size_t)row * DD))[tid];
        v.x += a.x; v.y += a.y; v.z += a.z; v.w += a.w;
    }
    float s = v.x + v.y + v.z + v.w;
    float q = v.x*v.x + v.y*v.y + v.z*v.z + v.w*v.w;
    #pragma unroll
    for (int off = 16; off; off >>= 1) {
        s += __shfl_xor_sync(0xffffffffu, s, off);
        q += __shfl_xor_sync(0xffffffffu, q, off);
    }
    if ((tid & 31) == 0) { rs[tid >> 5] = s; rq[tid >> 5] = q; }
    __syncthreads();
    s = rs[0] + rs[1] + rs[2] + rs[3];
    q = rq[0] + rq[1] + rq[2] + rq[3];
    float mu   = s * (1.f / DD);
    float var  = q * (1.f / DD) - mu * mu;
    float rstd = rsqrtf(var + 1e-5f);
    float4 g  = ((const float4*)gamma)[tid];
    float4 bt = ((const float4*)beta)[tid];
    float4 o;
    o.x = (v.x - mu) * rstd * g.x + bt.x;
    o.y = (v.y - mu) * rstd * g.y + bt.y;
    o.z = (v.z - mu) * rstd * g.z + bt.z;
    o.w = (v.w - mu) * rstd * g.w + bt.w;
    ((float4*)(out + (size_t)row * DD))[tid] = o;
    if (oh) {
        size_t e0 = (size_t)row * DD + tid * 4;
        float vv[4] = {o.x, o.y, o.z, o.w};
        #pragma unroll
        for (int j = 0; j < 4; j++) split_bf(vv[j], oh[e0+j], ol[e0+j]);
    }
}

// ---------------- launch --------------------------------------------------------
extern "C" void kernel_launch(void* const* d_in, const int* in_sizes, int n_in,
                              void* d_out, int out_size) {
    (void)in_sizes; (void)n_in; (void)out_size;
    const int*   x   = (const int*)  d_in[0];
    const float* emb = (const float*)d_in[1];
    const float* pe  = (const float*)d_in[2];
    const float* Wq  = (const float*)d_in[3];
    const float* bq  = (const float*)d_in[4];
    const float* Wk  = (const float*)d_in[5];
    const float* bk  = (const float*)d_in[6];
    const float* Wv  = (const float*)d_in[7];
    const float* bv  = (const float*)d_in[8];
    const float* Wo  = (const float*)d_in[9];
    const float* bo  = (const float*)d_in[10];
    const float* W1  = (const float*)d_in[11];
    const float* b1  = (const float*)d_in[12];
    const float* W2  = (const float*)d_in[13];
    const float* b2  = (const float*)d_in[14];
    const float* g1  = (const float*)d_in[15];
    const float* be1 = (const float*)d_in[16];
    const float* g2  = (const float*)d_in[17];
    const float* be2 = (const float*)d_in[18];
    const float* gf  = (const float*)d_in[19];
    const float* bf  = (const float*)d_in[20];

    float *h, *q, *kk, *vv;
    cudaGetSymbolAddress((void**)&h, g_h);
    cudaGetSymbolAddress((void**)&q, g_q);
    cudaGetSymbolAddress((void**)&kk, g_k);
    cudaGetSymbolAddress((void**)&vv, g_v);
    __nv_bfloat16 *hb_h, *hb_l, *ab_h, *ab_l, *tb_h, *tb_l;
    cudaGetSymbolAddress((void**)&hb_h, g_hb_h);
    cudaGetSymbolAddress((void**)&hb_l, g_hb_l);
    cudaGetSymbolAddress((void**)&ab_h, g_ab_h);
    cudaGetSymbolAddress((void**)&ab_l, g_ab_l);
    cudaGetSymbolAddress((void**)&tb_h, g_tb_h);
    cudaGetSymbolAddress((void**)&tb_l, g_tb_l);
    __nv_bfloat16 *wqh, *wql, *wkh, *wkl, *wvh, *wvl, *woh, *wol, *w1h, *w1l, *w2h, *w2l;
    cudaGetSymbolAddress((void**)&wqh, g_wq_h); cudaGetSymbolAddress((void**)&wql, g_wq_l);
    cudaGetSymbolAddress((void**)&wkh, g_wk_h); cudaGetSymbolAddress((void**)&wkl, g_wk_l);
    cudaGetSymbolAddress((void**)&wvh, g_wv_h); cudaGetSymbolAddress((void**)&wvl, g_wv_l);
    cudaGetSymbolAddress((void**)&woh, g_wo_h); cudaGetSymbolAddress((void**)&wol, g_wo_l);
    cudaGetSymbolAddress((void**)&w1h, g_w1_h); cudaGetSymbolAddress((void**)&w1l, g_w1_l);
    cudaGetSymbolAddress((void**)&w2h, g_w2_h); cudaGetSymbolAddress((void**)&w2l, g_w2_l);

    cudaFuncSetAttribute(att_out_kernel,
                         cudaFuncAttributeMaxDynamicSharedMemorySize, SM3_BYTES);
    cudaFuncSetAttribute(gemm_mma<0,0>,
                         cudaFuncAttributeMaxDynamicSharedMemorySize, GM_SMEM_BYTES);
    cudaFuncSetAttribute(gemm_mma<1,1>,
                         cudaFuncAttributeMaxDynamicSharedMemorySize, GM_SMEM_BYTES);

    len_kernel<<<BB, 256>>>(x);
    embed_kernel<<<(MM * (DD/4) + 255) / 256, 256>>>(x, emb, pe);

    // batched weight transpose+split: 24 matrices, one launch
    {
        WtcArgs wa = {};
        int idx = 0;
        for (int l = 0; l < NLL; l++) {
            size_t wo = (size_t)l * DD * DD;
            size_t wf = (size_t)l * DD * FF;
            wa.src[idx] = Wq + wo; wa.oh[idx] = wqh + wo; wa.ol[idx] = wql + wo; wa.K[idx] = DD; wa.N[idx] = DD; idx++;
            wa.src[idx] = Wk + wo; wa.oh[idx] = wkh + wo; wa.ol[idx] = wkl + wo; wa.K[idx] = DD; wa.N[idx] = DD; idx++;
            wa.src[idx] = Wv + wo; wa.oh[idx] = wvh + wo; wa.ol[idx] = wvl + wo; wa.K[idx] = DD; wa.N[idx] = DD; idx++;
            wa.src[idx] = Wo + wo; wa.oh[idx] = woh + wo; wa.ol[idx] = wol + wo; wa.K[idx] = DD; wa.N[idx] = DD; idx++;
            wa.src[idx] = W1 + wf; wa.oh[idx] = w1h + wf; wa.ol[idx] = w1l + wf; wa.K[idx] = DD; wa.N[idx] = FF; idx++;
            wa.src[idx] = W2 + wf; wa.oh[idx] = w2h + wf; wa.ol[idx] = w2l + wf; wa.K[idx] = FF; wa.N[idx] = DD; idx++;
        }
        wtc_all_kernel<<<dim3(FF/32, FF/32, 24), dim3(32, 8)>>>(wa);
    }

    for (int l = 0; l < NLL; l++) {
        size_t wo   = (size_t)l * DD * DD;
        size_t wf   = (size_t)l * DD * FF;
        size_t boff = (size_t)l * DD;

        // QKV fused; epilogue applies phi (q), masked phi (k)
        GTArgs ga = {};
        ga.Ah = hb_h; ga.Al = hb_l; ga.N = DD; ga.K = DD;
        ga.Bh[0] = wqh + wo; ga.Bl[0] = wql + wo;
        ga.Bh[1] = wkh + wo; ga.Bl[1] = wkl + wo;
        ga.Bh[2] = wvh + wo; ga.Bl[2] = wvl + wo;
        ga.bias[0] = bq + boff; ga.bias[1] = bk + boff; ga.bias[2] = bv + boff;
        ga.outf[0] = q; ga.outf[1] = kk; ga.outf[2] = vv;
        ga.pmode[0] = 1; ga.pmode[1] = 2; ga.pmode[2] = 0;
        gemm_mma<0,0><<<dim3(DD/128, MM/128, 3), 256, GM_SMEM_BYTES>>>(ga);

        att_sums_kernel<<<dim3(NCC, BHH), 256>>>();
        att_scan_kernel<<<BHH, 256>>>();
        att_out_kernel<<<dim3(NCC, BHH), 256, SM3_BYTES>>>();

        // O proj
        GTArgs go = {};
        go.Ah = ab_h; go.Al = ab_l; go.N = DD; go.K = DD;
        go.Bh[0] = woh + wo; go.Bl[0] = wol + wo;
        go.bias[0] = bo + boff; go.outf[0] = q;
        gemm_mma<0,0><<<dim3(DD/128, MM/128, 1), 256, GM_SMEM_BYTES>>>(go);

        ln_kernel<<<MM, 128>>>(h, q, g1 + boff, be1 + boff, h, hb_h, hb_l);

        // FFN1 (relu, bf16-split output)
        GTArgs g1a = {};
        g1a.Ah = hb_h; g1a.Al = hb_l; g1a.N = FF; g1a.K = DD;
        g1a.Bh[0] = w1h + wf; g1a.Bl[0] = w1l + wf;
        g1a.bias[0] = b1 + (size_t)l * FF;
        g1a.outh[0] = tb_h; g1a.outl[0] = tb_l;
        gemm_mma<1,1><<<dim3(FF/128, MM/128, 1), 256, GM_SMEM_BYTES>>>(g1a);

        // FFN2
        GTArgs g2a = {};
        g2a.Ah = tb_h; g2a.Al = tb_l; g2a.N = DD; g2a.K = FF;
        g2a.Bh[0] = w2h + wf; g2a.Bl[0] = w2l + wf;
        g2a.bias[0] = b2 + boff; g2a.outf[0] = q;
        gemm_mma<0,0><<<dim3(DD/128, MM/128, 1), 256, GM_SMEM_BYTES>>>(g2a);

        ln_kernel<<<MM, 128>>>(h, q, g2 + boff, be2 + boff, h, hb_h, hb_l);
    }

    ln_kernel<<<MM, 128>>>(h, nullptr, gf, bf, (float*)d_out, nullptr, nullptr);
}

// round 10
// speedup vs baseline: 3.1049x; 1.3380x over previous
#include <cuda_runtime.h>
#include <cuda_fp16.h>
#include <cstdint>

// ---------------- problem constants ----------------
#define BB  4
#define SS  2048
#define DD  512
#define HH  8
#define DHH 64
#define FF  2048
#define NLL 4
#define MM  (BB*SS)      // 8192 rows
#define CC  64           // attention chunk length
#define NCC (SS/CC)      // 32 chunks
#define BHH (BB*HH)      // 32 (b,h) pairs

__device__ __forceinline__ uint32_t smem_u32(const void* p) {
    uint32_t a;
    asm("{ .reg .u64 t; cvta.to.shared.u64 t, %1; cvt.u32.u64 %0, t; }" : "=r"(a) : "l"(p));
    return a;
}

// ---------------- scratch (device globals; no allocs allowed) ----------------
__device__ float g_h[MM*DD];
__device__ float g_q[MM*DD];          // holds phi(q) after QKV
__device__ float g_k[MM*DD];          // holds masked phi(k) after QKV
__device__ float g_v[MM*DD];
__device__ float g_S[(size_t)BHH*NCC*DHH*DHH];
__device__ float g_ks[BHH*NCC*DHH];
__device__ int   g_len[BB];

// fp16 activations (single-rounded)
__device__ __align__(16) __half g_hf[MM*DD];             // residual stream as GEMM-A
__device__ __align__(16) __half g_af[MM*DD];             // attention output
__device__ __align__(16) __half g_tf[(size_t)MM*FF];     // FFN hidden

// transposed weights as fp16 hi/lo pairs: layout [N][K]
__device__ __align__(16) __half g_wq_h[NLL*DD*DD], g_wq_l[NLL*DD*DD];
__device__ __align__(16) __half g_wk_h[NLL*DD*DD], g_wk_l[NLL*DD*DD];
__device__ __align__(16) __half g_wv_h[NLL*DD*DD], g_wv_l[NLL*DD*DD];
__device__ __align__(16) __half g_wo_h[NLL*DD*DD], g_wo_l[NLL*DD*DD];
__device__ __align__(16) __half g_w1_h[NLL*FF*DD], g_w1_l[NLL*FF*DD];
__device__ __align__(16) __half g_w2_h[NLL*DD*FF], g_w2_l[NLL*DD*FF];

__device__ __forceinline__ float phi_f(float u) { return u > 0.f ? u + 1.f : __expf(u); }

__device__ __forceinline__ void split_h(float x, __half& h, __half& l) {
    h = __float2half_rn(x);
    l = __float2half_rn(x - __half2float(h));
}

// ---------------- lengths ----------------
__global__ void len_kernel(const int* __restrict__ x) {
    __shared__ int red[256];
    int b = blockIdx.x, tid = threadIdx.x;
    int cnt = 0;
    for (int s = tid; s < SS; s += 256) cnt += (x[b*SS + s] != 0);
    red[tid] = cnt; __syncthreads();
    for (int off = 128; off; off >>= 1) {
        if (tid < off) red[tid] += red[tid + off];
        __syncthreads();
    }
    if (tid == 0) g_len[b] = red[0];
}

// ---------------- embedding + positional (+ fp16 round) ----------------
__global__ void embed_kernel(const int* __restrict__ x,
                             const float* __restrict__ emb,
                             const float* __restrict__ pe) {
    int idx = blockIdx.x * 256 + threadIdx.x;
    if (idx >= MM * (DD/4)) return;
    int i  = idx >> 7;
    int d4 = idx & 127;
    int s  = i & (SS - 1);
    int tok = x[i];
    float4 e = ((const float4*)emb)[(size_t)tok * (DD/4) + d4];
    float4 p = ((const float4*)pe)[(size_t)s * (DD/4) + d4];
    float4 o;
    o.x = e.x + p.x; o.y = e.y + p.y; o.z = e.z + p.z; o.w = e.w + p.w;
    ((float4*)g_h)[idx] = o;
    size_t e0 = (size_t)idx * 4;
    g_hf[e0+0] = __float2half_rn(o.x);
    g_hf[e0+1] = __float2half_rn(o.y);
    g_hf[e0+2] = __float2half_rn(o.z);
    g_hf[e0+3] = __float2half_rn(o.w);
}

// ---------------- batched weight transpose + split (24 matrices, one launch) ----
struct WtcArgs {
    const float* src[24];
    __half* oh[24];
    __half* ol[24];
    int K[24], N[24];
};
__global__ void wtc_all_kernel(WtcArgs p) {
    __shared__ float t[32][33];
    int m = blockIdx.z;
    int K = p.K[m], N = p.N[m];
    int n0 = blockIdx.x * 32, k0 = blockIdx.y * 32;
    if (n0 >= N || k0 >= K) return;
    const float* W = p.src[m];
    __half *oh = p.oh[m], *ol = p.ol[m];
    int tx = threadIdx.x, ty = threadIdx.y;   // 32x8
    #pragma unroll
    for (int i = 0; i < 32; i += 8)
        t[ty + i][tx] = W[(size_t)(k0 + ty + i) * N + n0 + tx];
    __syncthreads();
    #pragma unroll
    for (int i = 0; i < 32; i += 8) {
        float v = t[tx][ty + i];
        size_t o = (size_t)(n0 + ty + i) * K + k0 + tx;
        split_h(v, oh[o], ol[o]);
    }
}

// ---------------- 2-term fp16 GEMM via warp mma.sync ----------------
// C[M,N] = A[M,K] * B[N,K]^T + bias ; A single fp16, B as fp16 (hi,lo) pair.
// C = Af*Bh + Af*Bl  (B exact to ~2^-24; A rounded to 2^-12 -> rel err ~1e-4).
// Block 128x128, BK=32, 256 thr, warp tile 64x32.
// 4-stage cp.async pipeline, swizzled 64B-pitch smem, one sync/iter, 2 CTAs/SM.
// pmode (float-out path): 0=none, 1=phi, 2=masked phi.
struct GTArgs {
    const __half *Af;
    const __half *Bh[3], *Bl[3];
    const float* bias[3];
    float* outf[3];
    __half* outh[3];
    int pmode[3];
    int N, K;
};

#define STAGES 4
#define TILE_BYTES 8192                    // 128 rows x 64B (swizzled)
#define STAGE_BYTES (3*TILE_BYTES)         // Af,Bh,Bl = 24576
#define GM_SMEM_BYTES (STAGES*STAGE_BYTES) // 98304

// swizzled in-tile byte offset for (row, 16B-chunk c): row*64 + (c ^ ((row>>1)&3))*16
__device__ __forceinline__ uint32_t swz(int row, int c) {
    return (uint32_t)(row * 64 + ((c ^ ((row >> 1) & 3)) << 4));
}

#define MMA_F16(d, a, b) \
    asm volatile("mma.sync.aligned.m16n8k16.row.col.f32.f16.f16.f32 " \
        "{%0,%1,%2,%3}, {%4,%5,%6,%7}, {%8,%9}, {%0,%1,%2,%3};" \
        : "+f"((d)[0]), "+f"((d)[1]), "+f"((d)[2]), "+f"((d)[3]) \
        : "r"((a)[0]), "r"((a)[1]), "r"((a)[2]), "r"((a)[3]), "r"((b)[0]), "r"((b)[1]))

#define LDMX4(r, addr) \
    asm volatile("ldmatrix.sync.aligned.m8n8.x4.shared.b16 {%0,%1,%2,%3}, [%4];" \
        : "=r"((r)[0]), "=r"((r)[1]), "=r"((r)[2]), "=r"((r)[3]) : "r"(addr))

template<int RELU, int OUTH>
__global__ void __launch_bounds__(256, 2) gemm_mma(GTArgs p) {
    extern __shared__ __half sm[];
    const uint32_t sbase = smem_u32(sm);
    const int z = blockIdx.z;
    const int N = p.N, K = p.K;
    const int tid = threadIdx.x;
    const int m0 = blockIdx.y * 128, n0 = blockIdx.x * 128;

    // ---- loader: each thread owns (row rA, chunk chk); 6 x 16B per stage
    const int rA  = tid >> 2;          // 0..63
    const int chk = tid & 3;           // 16B chunk within 64B row
    const __half* gp[3];
    gp[0] = p.Af    + (size_t)(m0 + rA) * K + chk * 8;
    gp[1] = p.Bh[z] + (size_t)(n0 + rA) * K + chk * 8;
    gp[2] = p.Bl[z] + (size_t)(n0 + rA) * K + chk * 8;
    const uint32_t s0 = swz(rA, chk);  // rows rA and rA+64 share swizzle bits
    const size_t K64 = (size_t)K << 6; // 64 rows of stride K

    const int wid = tid >> 5, lane = tid & 31;
    const int wm = (wid & 1) * 64;
    const int wn = (wid >> 1) * 32;

    // ---- fragment base offsets (swizzled); kh step = XOR 0x20 ----
    const int rowa = wm + (lane & 15);
    const uint32_t aSw = swz(rowa, (lane >> 4) & 1);
    const int rowb = wn + (lane & 7) + ((lane >> 4) << 3);
    const uint32_t bSw = (uint32_t)TILE_BYTES + swz(rowb, (lane >> 3) & 1);

    float acc[4][4][4];
    #pragma unroll
    for (int a = 0; a < 4; a++)
        #pragma unroll
        for (int b = 0; b < 4; b++)
            #pragma unroll
            for (int c = 0; c < 4; c++) acc[a][b][c] = 0.f;

    const int nt = K >> 5;

    auto load_stage = [&](int slot, int k0) {
        uint32_t sb = sbase + (uint32_t)slot * STAGE_BYTES + s0;
        #pragma unroll
        for (int op = 0; op < 3; op++)
            #pragma unroll
            for (int j = 0; j < 2; j++) {
                asm volatile("cp.async.cg.shared.global [%0], [%1], 16;"
                    :: "r"(sb + (uint32_t)(op * TILE_BYTES + j * 4096)),
                       "l"(gp[op] + (j ? K64 : 0) + k0));
            }
        asm volatile("cp.async.commit_group;" ::: "memory");
    };

    // prologue: 3 stages in flight
    load_stage(0, 0);
    load_stage(1, 32);
    load_stage(2, 64);

    int cslot = 0, lslot = 3;
    for (int t = 0; t < nt; t++) {
        asm volatile("cp.async.wait_group 2;" ::: "memory");
        __syncthreads();
        if (t + 3 < nt) load_stage(lslot, (t + 3) * 32);
        else asm volatile("cp.async.commit_group;" ::: "memory");
        if (++lslot == STAGES) lslot = 0;

        const uint32_t stg = sbase + (uint32_t)cslot * STAGE_BYTES;
        if (++cslot == STAGES) cslot = 0;
        #pragma unroll
        for (int kh = 0; kh < 2; kh++) {
            const uint32_t kx = (uint32_t)(kh * 0x20);   // chunk+2 under swizzle
            // B fragments first (4 loads: Bh,Bl x 2 ng), then A (4 loads).
            uint32_t bfr[2][2][4];
            #pragma unroll
            for (int ng = 0; ng < 2; ng++)
                #pragma unroll
                for (int sp = 0; sp < 2; sp++)
                    LDMX4(bfr[sp][ng],
                          stg + ((bSw + (uint32_t)(sp * TILE_BYTES + ng * 1024)) ^ kx));
            uint32_t afr[4][4];
            #pragma unroll
            for (int mt = 0; mt < 4; mt++)
                LDMX4(afr[mt],
                      stg + ((aSw + (uint32_t)(mt * 1024)) ^ kx));
            // term-major: all Af*Bh, then all Af*Bl (per-acc order preserved).
            #pragma unroll
            for (int mt = 0; mt < 4; mt++)
                #pragma unroll
                for (int nn = 0; nn < 4; nn++) {
                    int ng = nn >> 1, hb = (nn & 1) * 2;
                    uint32_t b0h[2] = { bfr[0][ng][hb], bfr[0][ng][hb+1] };
                    MMA_F16(acc[mt][nn], afr[mt], b0h);  // Af*Bh
                }
            #pragma unroll
            for (int mt = 0; mt < 4; mt++)
                #pragma unroll
                for (int nn = 0; nn < 4; nn++) {
                    int ng = nn >> 1, hb = (nn & 1) * 2;
                    uint32_t b0l[2] = { bfr[1][ng][hb], bfr[1][ng][hb+1] };
                    MMA_F16(acc[mt][nn], afr[mt], b0l);  // Af*Bl
                }
        }
    }

    // ---- epilogue ----
    const float* bias = p.bias[z];
    const int pm = OUTH ? 0 : p.pmode[z];
    const int lenb = g_len[m0 >> 11];     // batch fixed per CTA (128 | 2048)
    #pragma unroll
    for (int nn = 0; nn < 4; nn++) {
        int cn = n0 + wn + nn * 8 + (lane & 3) * 2;
        float b0v = bias[cn], b1v = bias[cn + 1];
        #pragma unroll
        for (int mt = 0; mt < 4; mt++) {
            int r0 = m0 + wm + mt * 16 + (lane >> 2);
            #pragma unroll
            for (int half_ = 0; half_ < 2; half_++) {
                int r = r0 + half_ * 8;
                float v0 = acc[mt][nn][half_*2 + 0] + b0v;
                float v1 = acc[mt][nn][half_*2 + 1] + b1v;
                if (RELU) { v0 = fmaxf(v0, 0.f); v1 = fmaxf(v1, 0.f); }
                if (OUTH) {
                    __half2 hp;
                    hp.x = __float2half_rn(v0);
                    hp.y = __float2half_rn(v1);
                    *(__half2*)(p.outh[z] + (size_t)r * N + cn) = hp;
                } else {
                    if (pm == 1) { v0 = phi_f(v0); v1 = phi_f(v1); }
                    else if (pm == 2) {
                        if ((r & (SS - 1)) < lenb) { v0 = phi_f(v0); v1 = phi_f(v1); }
                        else { v0 = 0.f; v1 = 0.f; }
                    }
                    float2 o; o.x = v0; o.y = v1;
                    *(float2*)(p.outf[z] + (size_t)r * N + cn) = o;
                }
            }
        }
    }
}

// ---------------- attention pass 1: per-chunk  S_c = phiK^T V,  ks_c = sum phiK
// g_k already holds masked phi(k); g_v raw.
__global__ void __launch_bounds__(256) att_sums_kernel() {
    __shared__ float sK[CC][68];
    __shared__ float sV[CC][68];
    int c = blockIdx.x, bh = blockIdx.y;
    int b = bh >> 3, h = bh & 7;
    int tid = threadIdx.x;
    #pragma unroll
    for (int it = 0; it < 4; it++) {
        int idx = it * 256 + tid;            // 0..1023
        int j  = idx >> 4;                   // row 0..63
        int d4 = (idx & 15) << 2;            // 0..60
        size_t g = ((size_t)(b * SS + c * CC + j)) * DD + h * DHH + d4;
        *(float4*)&sK[j][d4] = *(const float4*)&g_k[g];
        *(float4*)&sV[j][d4] = *(const float4*)&g_v[g];
    }
    __syncthreads();
    int ti = tid & 15, tj = tid >> 4;
    float acc[4][4];
    #pragma unroll
    for (int r = 0; r < 4; r++)
        #pragma unroll
        for (int e = 0; e < 4; e++) acc[r][e] = 0.f;
    #pragma unroll 8
    for (int j = 0; j < CC; j++) {
        float4 kf = *(const float4*)&sK[j][ti*4];
        float4 vf = *(const float4*)&sV[j][tj*4];
        float ka[4] = {kf.x,kf.y,kf.z,kf.w};
        float va[4] = {vf.x,vf.y,vf.z,vf.w};
        #pragma unroll
        for (int r = 0; r < 4; r++)
            #pragma unroll
            for (int e = 0; e < 4; e++)
                acc[r][e] = fmaf(ka[r], va[e], acc[r][e]);
    }
    float* So = &g_S[((size_t)(bh * NCC + c)) * (DHH * DHH)];
    #pragma unroll
    for (int r = 0; r < 4; r++) {
        int d = ti * 4 + r;
        float4 o; o.x = acc[r][0]; o.y = acc[r][1]; o.z = acc[r][2]; o.w = acc[r][3];
        *(float4*)&So[d * DHH + tj * 4] = o;
    }
    if (tid < DHH) {
        float s = 0.f;
        #pragma unroll 8
        for (int j = 0; j < CC; j++) s += sK[j][tid];
        g_ks[(bh * NCC + c) * DHH + tid] = s;
    }
}

// ---------------- attention pass 2: exclusive prefix over chunks ----------------
__global__ void __launch_bounds__(256) att_scan_kernel() {
    int bh = blockIdx.x, tid = threadIdx.x;
    float run[16];
    #pragma unroll
    for (int r = 0; r < 16; r++) run[r] = 0.f;
    for (int c = 0; c < NCC; c++) {
        float* p = &g_S[((size_t)(bh * NCC + c)) * (DHH*DHH) + tid * 16];
        #pragma unroll
        for (int r4 = 0; r4 < 4; r4++) {
            float4 tv = ((const float4*)p)[r4];
            float4 rv;
            rv.x = run[r4*4+0]; rv.y = run[r4*4+1];
            rv.z = run[r4*4+2]; rv.w = run[r4*4+3];
            ((float4*)p)[r4] = rv;
            run[r4*4+0] += tv.x; run[r4*4+1] += tv.y;
            run[r4*4+2] += tv.z; run[r4*4+3] += tv.w;
        }
    }
    if (tid < DHH) {
        float rk = 0.f;
        for (int c = 0; c < NCC; c++) {
            float* kp = &g_ks[(bh * NCC + c) * DHH + tid];
            float t = *kp; *kp = rk; rk += t;
        }
    }
}

// ---------------- attention pass 3 ----------------
// g_q holds phi(q); g_k holds masked phi(k).
#define SM3_FLOATS (3*CC*68 + DHH)
#define SM3_BYTES  (SM3_FLOATS * 4)
__global__ void __launch_bounds__(256) att_out_kernel() {
    extern __shared__ float smf[];
    float* sQ  = smf;
    float* sKV = smf + CC*68;
    float* sSA = smf + 2*CC*68;
    float* skp = smf + 3*CC*68;

    int c = blockIdx.x, bh = blockIdx.y;
    int b = bh >> 3, h = bh & 7;
    int tid = threadIdx.x;

    const float* Sg = &g_S[((size_t)(bh * NCC + c)) * (DHH*DHH)];
    #pragma unroll
    for (int it = 0; it < 4; it++) {
        int idx = it * 256 + tid;            // 0..1023
        int r  = idx >> 4;                   // row 0..63
        int d4 = (idx & 15) << 2;            // 0..60
        size_t g = ((size_t)(b * SS + c * CC + r)) * DD + h * DHH + d4;
        float4 q4 = *(const float4*)&g_q[g];
        float4 k4 = *(const float4*)&g_k[g];
        sQ[(d4+0)*68 + r] = q4.x;
        sQ[(d4+1)*68 + r] = q4.y;
        sQ[(d4+2)*68 + r] = q4.z;
        sQ[(d4+3)*68 + r] = q4.w;
        sKV[(d4+0)*68 + r] = k4.x;
        sKV[(d4+1)*68 + r] = k4.y;
        sKV[(d4+2)*68 + r] = k4.z;
        sKV[(d4+3)*68 + r] = k4.w;
        float4 s4 = *(const float4*)&Sg[r * DHH + d4];
        *(float4*)&sSA[r*68 + d4] = s4;      // sSA[d][e] with row index = d
    }
    if (tid < DHH) skp[tid] = g_ks[(bh * NCC + c) * DHH + tid];
    __syncthreads();

    int ti = tid & 15, tj = tid >> 4;

    float zi = 0.f;
    if (tid < DHH) {
        #pragma unroll 8
        for (int d = 0; d < DHH; d++) zi += sQ[d*68 + tid] * skp[d];
    }

    float oacc[4][4], aacc[4][4];
    #pragma unroll
    for (int r = 0; r < 4; r++)
        #pragma unroll
        for (int e = 0; e < 4; e++) { oacc[r][e] = 0.f; aacc[r][e] = 0.f; }
    #pragma unroll 4
    for (int d = 0; d < DHH; d++) {
        float4 aq = *(const float4*)&sQ [d*68 + ti*4];
        float4 bs = *(const float4*)&sSA[d*68 + tj*4];
        float4 bk = *(const float4*)&sKV[d*68 + tj*4];
        float qa[4] = {aq.x,aq.y,aq.z,aq.w};
        float sa[4] = {bs.x,bs.y,bs.z,bs.w};
        float ka[4] = {bk.x,bk.y,bk.z,bk.w};
        #pragma unroll
        for (int r = 0; r < 4; r++)
            #pragma unroll
            for (int e = 0; e < 4; e++) {
                oacc[r][e] = fmaf(qa[r], sa[e], oacc[r][e]);
                aacc[r][e] = fmaf(qa[r], ka[e], aacc[r][e]);
            }
    }
    __syncthreads();

    #pragma unroll
    for (int r = 0; r < 4; r++)
        #pragma unroll
        for (int e = 0; e < 4; e++) {
            int i = ti * 4 + r, j = tj * 4 + e;
            sSA[j*68 + i] = (j <= i) ? aacc[r][e] : 0.f;
        }
    #pragma unroll
    for (int it = 0; it < 4; it++) {
        int idx = it * 256 + tid;
        int r  = idx >> 4;
        int e4 = (idx & 15) << 2;
        float4 v4 = *(const float4*)&g_v[((size_t)(b * SS + c * CC + r)) * DD + h * DHH + e4];
        *(float4*)&sKV[r*68 + e4] = v4;
    }
    __syncthreads();

    if (tid < DHH) {
        float z = zi;
        #pragma unroll 8
        for (int j = 0; j < CC; j++) z += sSA[j*68 + tid];
        skp[tid] = 1.f / (z + 1e-6f);
    }

    #pragma unroll 4
    for (int j = 0; j < CC; j++) {
        float4 aj = *(const float4*)&sSA[j*68 + ti*4];
        float4 ve = *(const float4*)&sKV[j*68 + tj*4];
        float aa[4] = {aj.x,aj.y,aj.z,aj.w};
        float va[4] = {ve.x,ve.y,ve.z,ve.w};
        #pragma unroll
        for (int r = 0; r < 4; r++)
            #pragma unroll
            for (int e = 0; e < 4; e++)
                oacc[r][e] = fmaf(aa[r], va[e], oacc[r][e]);
    }
    __syncthreads();

    #pragma unroll
    for (int r = 0; r < 4; r++) {
        int i = ti * 4 + r;
        float zr = skp[i];
        size_t base = ((size_t)(b * SS + c * CC + i)) * DD + h * DHH + tj * 4;
        #pragma unroll
        for (int e = 0; e < 4; e++) {
            float o = oacc[r][e] * zr;
            g_af[base + e] = __float2half_rn(o);
        }
    }
}

// ---------------- LayerNorm (+ residual, + optional fp16 out) ----------------
__global__ void ln_kernel(const float* __restrict__ x, const float* __restrict__ add,
                          const float* __restrict__ gamma, const float* __restrict__ beta,
                          float* __restrict__ out, __half* __restrict__ oh) {
    __shared__ float rs[4], rq[4];
    int row = blockIdx.x, tid = threadIdx.x;
    float4 v = ((const float4*)(x + (size_t)row * DD))[tid];
    if (add) {
        float4 a = ((const float4*)(add + (size_t)row * DD))[tid];
        v.x += a.x; v.y += a.y; v.z += a.z; v.w += a.w;
    }
    float s = v.x + v.y + v.z + v.w;
    float q = v.x*v.x + v.y*v.y + v.z*v.z + v.w*v.w;
    #pragma unroll
    for (int off = 16; off; off >>= 1) {
        s += __shfl_xor_sync(0xffffffffu, s, off);
        q += __shfl_xor_sync(0xffffffffu, q, off);
    }
    if ((tid & 31) == 0) { rs[tid >> 5] = s; rq[tid >> 5] = q; }
    __syncthreads();
    s = rs[0] + rs[1] + rs[2] + rs[3];
    q = rq[0] + rq[1] + rq[2] + rq[3];
    float mu   = s * (1.f / DD);
    float var  = q * (1.f / DD) - mu * mu;
    float rstd = rsqrtf(var + 1e-5f);
    float4 g  = ((const float4*)gamma)[tid];
    float4 bt = ((const float4*)beta)[tid];
    float4 o;
    o.x = (v.x - mu) * rstd * g.x + bt.x;
    o.y = (v.y - mu) * rstd * g.y + bt.y;
    o.z = (v.z - mu) * rstd * g.z + bt.z;
    o.w = (v.w - mu) * rstd * g.w + bt.w;
    ((float4*)(out + (size_t)row * DD))[tid] = o;
    if (oh) {
        size_t e0 = (size_t)row * DD + tid * 4;
        oh[e0+0] = __float2half_rn(o.x);
        oh[e0+1] = __float2half_rn(o.y);
        oh[e0+2] = __float2half_rn(o.z);
        oh[e0+3] = __float2half_rn(o.w);
    }
}

// ---------------- launch --------------------------------------------------------
extern "C" void kernel_launch(void* const* d_in, const int* in_sizes, int n_in,
                              void* d_out, int out_size) {
    (void)in_sizes; (void)n_in; (void)out_size;
    const int*   x   = (const int*)  d_in[0];
    const float* emb = (const float*)d_in[1];
    const float* pe  = (const float*)d_in[2];
    const float* Wq  = (const float*)d_in[3];
    const float* bq  = (const float*)d_in[4];
    const float* Wk  = (const float*)d_in[5];
    const float* bk  = (const float*)d_in[6];
    const float* Wv  = (const float*)d_in[7];
    const float* bv  = (const float*)d_in[8];
    const float* Wo  = (const float*)d_in[9];
    const float* bo  = (const float*)d_in[10];
    const float* W1  = (const float*)d_in[11];
    const float* b1  = (const float*)d_in[12];
    const float* W2  = (const float*)d_in[13];
    const float* b2  = (const float*)d_in[14];
    const float* g1  = (const float*)d_in[15];
    const float* be1 = (const float*)d_in[16];
    const float* g2  = (const float*)d_in[17];
    const float* be2 = (const float*)d_in[18];
    const float* gf  = (const float*)d_in[19];
    const float* bf  = (const float*)d_in[20];

    float *h, *q, *kk, *vv;
    cudaGetSymbolAddress((void**)&h, g_h);
    cudaGetSymbolAddress((void**)&q, g_q);
    cudaGetSymbolAddress((void**)&kk, g_k);
    cudaGetSymbolAddress((void**)&vv, g_v);
    __half *hf, *af, *tf;
    cudaGetSymbolAddress((void**)&hf, g_hf);
    cudaGetSymbolAddress((void**)&af, g_af);
    cudaGetSymbolAddress((void**)&tf, g_tf);
    __half *wqh, *wql, *wkh, *wkl, *wvh, *wvl, *woh, *wol, *w1h, *w1l, *w2h, *w2l;
    cudaGetSymbolAddress((void**)&wqh, g_wq_h); cudaGetSymbolAddress((void**)&wql, g_wq_l);
    cudaGetSymbolAddress((void**)&wkh, g_wk_h); cudaGetSymbolAddress((void**)&wkl, g_wk_l);
    cudaGetSymbolAddress((void**)&wvh, g_wv_h); cudaGetSymbolAddress((void**)&wvl, g_wv_l);
    cudaGetSymbolAddress((void**)&woh, g_wo_h); cudaGetSymbolAddress((void**)&wol, g_wo_l);
    cudaGetSymbolAddress((void**)&w1h, g_w1_h); cudaGetSymbolAddress((void**)&w1l, g_w1_l);
    cudaGetSymbolAddress((void**)&w2h, g_w2_h); cudaGetSymbolAddress((void**)&w2l, g_w2_l);

    cudaFuncSetAttribute(att_out_kernel,
                         cudaFuncAttributeMaxDynamicSharedMemorySize, SM3_BYTES);
    cudaFuncSetAttribute(gemm_mma<0,0>,
                         cudaFuncAttributeMaxDynamicSharedMemorySize, GM_SMEM_BYTES);
    cudaFuncSetAttribute(gemm_mma<1,1>,
                         cudaFuncAttributeMaxDynamicSharedMemorySize, GM_SMEM_BYTES);

    len_kernel<<<BB, 256>>>(x);
    embed_kernel<<<(MM * (DD/4) + 255) / 256, 256>>>(x, emb, pe);

    // batched weight transpose+split: 24 matrices, one launch
    {
        WtcArgs wa = {};
        int idx = 0;
        for (int l = 0; l < NLL; l++) {
            size_t wo = (size_t)l * DD * DD;
            size_t wf = (size_t)l * DD * FF;
            wa.src[idx] = Wq + wo; wa.oh[idx] = wqh + wo; wa.ol[idx] = wql + wo; wa.K[idx] = DD; wa.N[idx] = DD; idx++;
            wa.src[idx] = Wk + wo; wa.oh[idx] = wkh + wo; wa.ol[idx] = wkl + wo; wa.K[idx] = DD; wa.N[idx] = DD; idx++;
            wa.src[idx] = Wv + wo; wa.oh[idx] = wvh + wo; wa.ol[idx] = wvl + wo; wa.K[idx] = DD; wa.N[idx] = DD; idx++;
            wa.src[idx] = Wo + wo; wa.oh[idx] = woh + wo; wa.ol[idx] = wol + wo; wa.K[idx] = DD; wa.N[idx] = DD; idx++;
            wa.src[idx] = W1 + wf; wa.oh[idx] = w1h + wf; wa.ol[idx] = w1l + wf; wa.K[idx] = DD; wa.N[idx] = FF; idx++;
            wa.src[idx] = W2 + wf; wa.oh[idx] = w2h + wf; wa.ol[idx] = w2l + wf; wa.K[idx] = FF; wa.N[idx] = DD; idx++;
        }
        wtc_all_kernel<<<dim3(FF/32, FF/32, 24), dim3(32, 8)>>>(wa);
    }

    for (int l = 0; l < NLL; l++) {
        size_t wo   = (size_t)l * DD * DD;
        size_t wf   = (size_t)l * DD * FF;
        size_t boff = (size_t)l * DD;

        // QKV fused; epilogue applies phi (q), masked phi (k)
        GTArgs ga = {};
        ga.Af = hf; ga.N = DD; ga.K = DD;
        ga.Bh[0] = wqh + wo; ga.Bl[0] = wql + wo;
        ga.Bh[1] = wkh + wo; ga.Bl[1] = wkl + wo;
        ga.Bh[2] = wvh + wo; ga.Bl[2] = wvl + wo;
        ga.bias[0] = bq + boff; ga.bias[1] = bk + boff; ga.bias[2] = bv + boff;
        ga.outf[0] = q; ga.outf[1] = kk; ga.outf[2] = vv;
        ga.pmode[0] = 1; ga.pmode[1] = 2; ga.pmode[2] = 0;
        gemm_mma<0,0><<<dim3(DD/128, MM/128, 3), 256, GM_SMEM_BYTES>>>(ga);

        att_sums_kernel<<<dim3(NCC, BHH), 256>>>();
        att_scan_kernel<<<BHH, 256>>>();
        att_out_kernel<<<dim3(NCC, BHH), 256, SM3_BYTES>>>();

        // O proj
        GTArgs go = {};
        go.Af = af; go.N = DD; go.K = DD;
        go.Bh[0] = woh + wo; go.Bl[0] = wol + wo;
        go.bias[0] = bo + boff; go.outf[0] = q;
        gemm_mma<0,0><<<dim3(DD/128, MM/128, 1), 256, GM_SMEM_BYTES>>>(go);

        ln_kernel<<<MM, 128>>>(h, q, g1 + boff, be1 + boff, h, hf);

        // FFN1 (relu, fp16 output)
        GTArgs g1a = {};
        g1a.Af = hf; g1a.N = FF; g1a.K = DD;
        g1a.Bh[0] = w1h + wf; g1a.Bl[0] = w1l + wf;
        g1a.bias[0] = b1 + (size_t)l * FF;
        g1a.outh[0] = tf;
        gemm_mma<1,1><<<dim3(FF/128, MM/128, 1), 256, GM_SMEM_BYTES>>>(g1a);

        // FFN2
        GTArgs g2a = {};
        g2a.Af = tf; g2a.N = DD; g2a.K = FF;
        g2a.Bh[0] = w2h + wf; g2a.Bl[0] = w2l + wf;
        g2a.bias[0] = b2 + boff; g2a.outf[0] = q;
        gemm_mma<0,0><<<dim3(DD/128, MM/128, 1), 256, GM_SMEM_BYTES>>>(g2a);

        ln_kernel<<<MM, 128>>>(h, q, g2 + boff, be2 + boff, h, hf);
    }

    ln_kernel<<<MM, 128>>>(h, nullptr, gf, bf, (float*)d_out, nullptr);
}